// round 11
// baseline (speedup 1.0000x reference)
#include <cuda_runtime.h>
#include <math.h>

#define Nn 30000
#define Ee 480000
#define Bb 4096
#define EPSF 1e-8f

typedef unsigned long long u64;
__device__ __forceinline__ u64 pk2(float x,float y){u64 r;asm("mov.b64 %0,{%1,%2};":"=l"(r):"f"(x),"f"(y));return r;}
__device__ __forceinline__ float2 up2(u64 v){float2 r;asm("mov.b64 {%0,%1},%2;":"=f"(r.x),"=f"(r.y):"l"(v));return r;}
__device__ __forceinline__ void fma2(u64&d,u64 a,u64 b){asm("fma.rn.f32x2 %0,%1,%2,%0;":"+l"(d):"l"(a),"l"(b));}

#define APAD 132
#define ATILE (32*APAD)            // floats per A buffer
#define WTILE (32*128)             // floats per W buffer
#define SMEM_DB ((2*ATILE+2*WTILE)*4)  // 66560 bytes

// ------------- device scratch -------------
__device__ float g_Wp[256*896];
__device__ float g_X64a[Nn*64], g_X64b[Nn*64];
__device__ float g_XC1[Nn*128], g_XC2[Nn*128], g_XCf[Nn*128];
__device__ float g_XG[Nn*128], g_XG1[Nn*128], g_XG2[Nn*128];
__device__ float g_Ha[Nn*128], g_Hb[Nn*128];
__device__ float g_emba[Nn*64], g_embb[Nn*64];
__device__ float g_S16a[Nn*16], g_S16b[Nn*16];
__device__ float g_C16a[Nn*16], g_C16b[Nn*16];
__device__ float g_dra[Nn], g_dca[Nn], g_drb[Nn], g_dcb[Nn];
__device__ float g_w1[Nn], g_w2[Nn], g_b1[Nn], g_b2[Nn];
__device__ int   g_cnt1[Nn], g_cnt1b[Nn], g_cnt2[Nn], g_cnt2b[Nn];
__device__ int   g_cur1d[Nn], g_cur2d[Nn], g_cur1s[Nn], g_cur2s[Nn];
__device__ int   g_rp1d[Nn+1], g_rp2d[Nn+1], g_rp1s[Nn+1], g_rp2s[Nn+1];
__device__ int   g_col1d[Ee];   __device__ float g_val1d[Ee];
__device__ int   g_col2d[Ee];   __device__ float g_val2d[Ee];
__device__ int   g_col1s[2*Ee]; __device__ float g_val1s[2*Ee];
__device__ int   g_col2s[2*Ee]; __device__ float g_val2s[2*Ee];
__device__ float g_Z[3*Bb*128], g_T[3*Bb*128], g_E[3*Bb*128];
__device__ float g_RS[3*Bb], g_CS[3*Bb], g_DG[3*Bb];

// ------------- pack weights -------------
__global__ void k_pack(const float* __restrict__ wg1, const float* __restrict__ wg2,
                       const float* __restrict__ a, const float* __restrict__ b,
                       const float* __restrict__ c, const float* __restrict__ d,
                       const float* __restrict__ e, const float* __restrict__ f,
                       float* __restrict__ Wp){
    int i=blockIdx.x*blockDim.x+threadIdx.x; if(i>=256*896) return;
    int row=i/896, col=i%896;
    float v;
    if(col<64) v=wg1[row*64+col];
    else if(col<128) v=wg2[row*64+col-64];
    else{
        int blk=(col-128)>>7, lc=(col-128)&127;
        const float* s;
        switch(blk){case 0:s=a;break;case 1:s=b;break;case 2:s=c;break;
                    case 3:s=d;break;case 4:s=e;break;default:s=f;break;}
        v=s[row*128+lc];
    }
    Wp[i]=v;
}

// ------------- small utils -------------
__global__ void k_zero4(int* a,int* b,int* c,int* d,int n){
    int i=blockIdx.x*blockDim.x+threadIdx.x; if(i<n){a[i]=0;b[i]=0;c[i]=0;d[i]=0;} }
__global__ void k_zero_f2(float* a, float* b, int n){
    int i=blockIdx.x*blockDim.x+threadIdx.x; if(i<n){a[i]=0.f;b[i]=0.f;} }

__global__ void k_count2(const int* __restrict__ ind1, const int* __restrict__ ind2,
                         int* cd1, int* cs1, int* cd2, int* cs2){
    int e=blockIdx.x*blockDim.x+threadIdx.x; if(e>=Ee) return;
    int r1=ind1[e], c1=ind1[Ee+e];
    atomicAdd(&cd1[r1],1); atomicAdd(&cs1[r1],1); atomicAdd(&cs1[c1],1);
    int r2=ind2[e], c2=ind2[Ee+e];
    atomicAdd(&cd2[r2],1); atomicAdd(&cs2[r2],1); atomicAdd(&cs2[c2],1);
}

// 4 independent scans; register-staged, fully unrolled (CHUNK=30)
__global__ void k_scan4(const int* c0,int* r0,int* u0,const int* c1,int* r1,int* u1,
                        const int* c2,int* r2,int* u2,const int* c3,int* r3,int* u3){
    const int* cnt; int* rp; int* cu;
    switch(blockIdx.x){
        case 0: cnt=c0; rp=r0; cu=u0; break;
        case 1: cnt=c1; rp=r1; cu=u1; break;
        case 2: cnt=c2; rp=r2; cu=u2; break;
        default:cnt=c3; rp=r3; cu=u3; break;
    }
    const int CH=30;
    int tid=threadIdx.x;
    int s=tid*CH;
    int vloc[CH];
#pragma unroll
    for(int i=0;i<CH;i++){int idx=s+i; vloc[i]=(idx<Nn)?cnt[idx]:0;}
    int sum=0;
#pragma unroll
    for(int i=0;i<CH;i++) sum+=vloc[i];
    __shared__ int wsum[32];
    int lane=tid&31, wid=tid>>5;
    int v=sum;
#pragma unroll
    for(int o=1;o<32;o<<=1){int t=__shfl_up_sync(0xffffffffu,v,o); if(lane>=o) v+=t;}
    if(lane==31) wsum[wid]=v;
    __syncthreads();
    if(wid==0){
        int w=wsum[lane];
#pragma unroll
        for(int o=1;o<32;o<<=1){int t=__shfl_up_sync(0xffffffffu,w,o); if(lane>=o) w+=t;}
        wsum[lane]=w;
    }
    __syncthreads();
    int excl=v-sum+(wid?wsum[wid-1]:0);
    int run=excl;
#pragma unroll
    for(int i=0;i<CH;i++){
        int idx=s+i;
        if(idx<Nn){ rp[idx]=run; cu[idx]=run; run+=vloc[i]; }
    }
    if(tid==1023) rp[Nn]=run;
}

__global__ void k_scatter_dir(const int* __restrict__ ind, const float* __restrict__ vals,
                              int* cur, int* __restrict__ col, float* __restrict__ val){
    int e=blockIdx.x*blockDim.x+threadIdx.x; if(e>=Ee) return;
    int r=ind[e], c=ind[Ee+e];
    int p=atomicAdd(&cur[r],1);
    col[p]=c; val[p]=vals[e];
}

__global__ void k_scatter_sym(const int* __restrict__ rpd, const int* __restrict__ cold,
                              const float* __restrict__ vald, int* cur,
                              int* __restrict__ cols, float* __restrict__ vals){
    int r=blockIdx.x*blockDim.x+threadIdx.x; if(r>=Nn) return;
    for(int i=rpd[r];i<rpd[r+1];i++){
        int c=cold[i]; float v=vald[i];
        int p=atomicAdd(&cur[r],1); cols[p]=c; vals[p]=v;
        int q=atomicAdd(&cur[c],1); cols[q]=r; vals[q]=v;
    }
}

// ------------- inner-product macro (8x8, f32x2) -------------
#define MMA_KK(sak, sWk) do{ \
    float4 aA=*(const float4*)(sak); \
    float4 aB=*(const float4*)((sak)+4); \
    const ulonglong2* bw=(const ulonglong2*)(sWk); \
    ulonglong2 bA=bw[0], bB=bw[1]; \
    u64 s0=pk2(aA.x,aA.x), s1=pk2(aA.y,aA.y); \
    u64 s2=pk2(aA.z,aA.z), s3=pk2(aA.w,aA.w); \
    u64 s4=pk2(aB.x,aB.x), s5=pk2(aB.y,aB.y); \
    u64 s6=pk2(aB.z,aB.z), s7=pk2(aB.w,aB.w); \
    fma2(acc[0][0],s0,bA.x); fma2(acc[0][1],s0,bA.y); fma2(acc[0][2],s0,bB.x); fma2(acc[0][3],s0,bB.y); \
    fma2(acc[1][0],s1,bA.x); fma2(acc[1][1],s1,bA.y); fma2(acc[1][2],s1,bB.x); fma2(acc[1][3],s1,bB.y); \
    fma2(acc[2][0],s2,bA.x); fma2(acc[2][1],s2,bA.y); fma2(acc[2][2],s2,bB.x); fma2(acc[2][3],s2,bB.y); \
    fma2(acc[3][0],s3,bA.x); fma2(acc[3][1],s3,bA.y); fma2(acc[3][2],s3,bB.x); fma2(acc[3][3],s3,bB.y); \
    fma2(acc[4][0],s4,bA.x); fma2(acc[4][1],s4,bA.y); fma2(acc[4][2],s4,bB.x); fma2(acc[4][3],s4,bB.y); \
    fma2(acc[5][0],s5,bA.x); fma2(acc[5][1],s5,bA.y); fma2(acc[5][2],s5,bB.x); fma2(acc[5][3],s5,bB.y); \
    fma2(acc[6][0],s6,bA.x); fma2(acc[6][1],s6,bA.y); fma2(acc[6][2],s6,bB.x); fma2(acc[6][3],s6,bB.y); \
    fma2(acc[7][0],s7,bA.x); fma2(acc[7][1],s7,bA.y); fma2(acc[7][2],s7,bB.x); fma2(acc[7][3],s7,bB.y); \
}while(0)

// compute all 32 kk of one buffered chunk
#define COMPUTE_CHUNK(sA, sW) do{ \
    _Pragma("unroll") \
    for(int kk=0;kk<32;kk++){ MMA_KK((sA)+kk*APAD+ty*8, (sW)+kk*128+tx*8); } \
}while(0)

// ------------- packed GEMM slice (double-buffered): feat @ Wp[:,128*bx..] -------------
__global__ __launch_bounds__(256,2) void k_gemmP(
        const float* __restrict__ A, const float* __restrict__ Wp, int bxoff,
        float* __restrict__ e1, float* __restrict__ e2,
        float* __restrict__ x0, float* __restrict__ x1, float* __restrict__ x2,
        float* __restrict__ x3, float* __restrict__ x4, float* __restrict__ x5){
    extern __shared__ __align__(16) float smem[];
    float* sAb=smem;              // 2 x ATILE
    float* sWb=smem+2*ATILE;      // 2 x WTILE
    int tid=threadIdx.x, tx=tid&15, ty=tid>>4;
    int bx=blockIdx.x+bxoff;
    int br=blockIdx.y*128;
    u64 acc[8][4];
#pragma unroll
    for(int i=0;i<8;i++){acc[i][0]=0;acc[i][1]=0;acc[i][2]=0;acc[i][3]=0;}
    int ra=tid>>3, fa=(tid&7)<<2;
    int cw=(tid&31)<<2, kw=tid>>5;

#define LOADP(k0, sA, sW) do{ \
    _Pragma("unroll") \
    for(int h=0;h<4;h++){ \
        int r=ra+h*32, gr=br+r; \
        float4 v=make_float4(0.f,0.f,0.f,0.f); \
        if(gr<Nn) v=*(const float4*)(A+(long)gr*256+(k0)+fa); \
        (sA)[(fa+0)*APAD+r]=v.x; (sA)[(fa+1)*APAD+r]=v.y; \
        (sA)[(fa+2)*APAD+r]=v.z; (sA)[(fa+3)*APAD+r]=v.w; \
    } \
    _Pragma("unroll") \
    for(int h=0;h<4;h++){ \
        int kk=kw+h*8; \
        float4 v=*(const float4*)(Wp+(long)((k0)+kk)*896+bx*128+cw); \
        *(float4*)&(sW)[kk*128+cw]=v; \
    } \
}while(0)

    LOADP(0, sAb, sWb);
    __syncthreads();
    int buf=0;
#pragma unroll 1
    for(int k0=0;k0<256;k0+=32){
        if(k0+32<256) LOADP(k0+32, sAb+(buf^1)*ATILE, sWb+(buf^1)*WTILE);
        COMPUTE_CHUNK(sAb+buf*ATILE, sWb+buf*WTILE);
        __syncthreads();
        buf^=1;
    }
#undef LOADP
    float* dst; int w; int c0;
    if(bx==0){
        if(tx<8){ dst=e1; w=64; c0=tx*8; } else { dst=e2; w=64; c0=(tx-8)*8; }
    } else {
        switch(bx-1){case 0:dst=x0;break;case 1:dst=x1;break;case 2:dst=x2;break;
                     case 3:dst=x3;break;case 4:dst=x4;break;default:dst=x5;break;}
        w=128; c0=tx*8;
    }
#pragma unroll
    for(int i=0;i<8;i++){
        int gr=br+ty*8+i; if(gr>=Nn) continue;
        float vv[8];
#pragma unroll
        for(int p=0;p<4;p++){float2 t=up2(acc[i][p]); vv[2*p]=t.x; vv[2*p+1]=t.y;}
        float* cp=dst+(long)gr*w+c0;
        *(float4*)cp=make_float4(vv[0],vv[1],vv[2],vv[3]);
        *(float4*)(cp+4)=make_float4(vv[4],vv[5],vv[6],vv[7]);
    }
}

// ------------- generic GEMM (double-buffered): C[n,128]=A[n,K]@W[K,128] -------------
__global__ __launch_bounds__(256,2) void k_gemm128(
        const float* __restrict__ A, const float* __restrict__ W,
        const float* __restrict__ bias, float* __restrict__ C,
        int n, int K, int act){
    extern __shared__ __align__(16) float smem[];
    float* sAb=smem;
    float* sWb=smem+2*ATILE;
    int tid=threadIdx.x, tx=tid&15, ty=tid>>4;
    int br=blockIdx.y*128;
    u64 acc[8][4];
#pragma unroll
    for(int i=0;i<8;i++){acc[i][0]=0;acc[i][1]=0;acc[i][2]=0;acc[i][3]=0;}
    int ra=tid>>3, fa=(tid&7)<<2;
    int cw=(tid&31)<<2, kw=tid>>5;

#define LOADG(k0, sA, sW) do{ \
    _Pragma("unroll") \
    for(int h=0;h<4;h++){ \
        int r=ra+h*32, gr=br+r; \
        float4 v=make_float4(0.f,0.f,0.f,0.f); \
        if(gr<n) v=*(const float4*)(A+(long)gr*K+(k0)+fa); \
        (sA)[(fa+0)*APAD+r]=v.x; (sA)[(fa+1)*APAD+r]=v.y; \
        (sA)[(fa+2)*APAD+r]=v.z; (sA)[(fa+3)*APAD+r]=v.w; \
    } \
    _Pragma("unroll") \
    for(int h=0;h<4;h++){ \
        int kk=kw+h*8; \
        float4 v=*(const float4*)(W+(long)((k0)+kk)*128+cw); \
        *(float4*)&(sW)[kk*128+cw]=v; \
    } \
}while(0)

    LOADG(0, sAb, sWb);
    __syncthreads();
    int buf=0;
#pragma unroll 1
    for(int k0=0;k0<K;k0+=32){
        if(k0+32<K) LOADG(k0+32, sAb+(buf^1)*ATILE, sWb+(buf^1)*WTILE);
        COMPUTE_CHUNK(sAb+buf*ATILE, sWb+buf*WTILE);
        __syncthreads();
        buf^=1;
    }
#undef LOADG
    float bb[8];
#pragma unroll
    for(int q=0;q<8;q++) bb[q]=bias?bias[tx*8+q]:0.f;
#pragma unroll
    for(int i=0;i<8;i++){
        int gr=br+ty*8+i; if(gr>=n) continue;
        float vv[8];
#pragma unroll
        for(int p=0;p<4;p++){float2 t=up2(acc[i][p]); vv[2*p]=t.x; vv[2*p+1]=t.y;}
#pragma unroll
        for(int q=0;q<8;q++){
            float v=vv[q]+bb[q];
            if(act==1) v=(v>0.f)?v:expm1f(v);
            vv[q]=v;
        }
        float* cp=C+(long)gr*128+tx*8;
        *(float4*)cp=make_float4(vv[0],vv[1],vv[2],vv[3]);
        *(float4*)(cp+4)=make_float4(vv[4],vv[5],vv[6],vv[7]);
    }
}

// ------------- GEMM M=16 (W2 in smem) -------------
__global__ void k_gemm16(const float* __restrict__ H, const float* __restrict__ W2,
                         float* __restrict__ C, int n){
    __shared__ float sW[128*16];
    int tid=threadIdx.y*16+threadIdx.x;
#pragma unroll
    for(int q=0;q<2;q++) ((float4*)sW)[tid*2+q]=((const float4*)W2)[tid*2+q];
    __syncthreads();
    int r=blockIdx.x*16+threadIdx.y, j=threadIdx.x;
    if(r>=n) return;
    const float4* H4=(const float4*)(H+(long)r*128);
    float acc=0.f;
#pragma unroll
    for(int k4=0;k4<32;k4++){
        float4 h=H4[k4];
        acc+=h.x*sW[(k4*4+0)*16+j];
        acc+=h.y*sW[(k4*4+1)*16+j];
        acc+=h.z*sW[(k4*4+2)*16+j];
        acc+=h.w*sW[(k4*4+3)*16+j];
    }
    C[(long)r*16+j]=acc;
}

// ------------- SpMM (warp per row, 2-way unrolled) -------------
__device__ __forceinline__ float4 spmm_row128(const int* __restrict__ rp,
        const int* __restrict__ col, const float* __restrict__ val,
        const float4* __restrict__ X4, int w, int lane){
    int s=rp[w], e=rp[w+1];
    float4 A=make_float4(0.f,0.f,0.f,0.f), B=A;
    int i=s;
    for(; i+1<e; i+=2){
        int c0=col[i], c1=col[i+1];
        float v0=val[i], v1=val[i+1];
        float4 x0=X4[(long)c0*32+lane];
        float4 x1=X4[(long)c1*32+lane];
        A.x+=v0*x0.x; A.y+=v0*x0.y; A.z+=v0*x0.z; A.w+=v0*x0.w;
        B.x+=v1*x1.x; B.y+=v1*x1.y; B.z+=v1*x1.z; B.w+=v1*x1.w;
    }
    if(i<e){
        int c=col[i]; float v=val[i];
        float4 x=X4[(long)c*32+lane];
        A.x+=v*x.x; A.y+=v*x.y; A.z+=v*x.z; A.w+=v*x.w;
    }
    A.x+=B.x; A.y+=B.y; A.z+=B.z; A.w+=B.w;
    return A;
}

__global__ void k_spmm128(const int* __restrict__ rp, const int* __restrict__ col,
                          const float* __restrict__ val, const float* __restrict__ X,
                          float* __restrict__ Y){
    int w=(blockIdx.x*blockDim.x+threadIdx.x)>>5; if(w>=Nn) return;
    int lane=threadIdx.x&31;
    float4 a=spmm_row128(rp,col,val,(const float4*)X,w,lane);
    a.x=fmaxf(a.x,0.f); a.y=fmaxf(a.y,0.f); a.z=fmaxf(a.z,0.f); a.w=fmaxf(a.w,0.f);
    ((float4*)Y)[(long)w*32+lane]=a;
}

__global__ void k_spmm128f(const int* __restrict__ rp1, const int* __restrict__ col1,
                           const float* __restrict__ val1,
                           const int* __restrict__ rp2, const int* __restrict__ col2,
                           const float* __restrict__ val2,
                           const float* __restrict__ b1, const float* __restrict__ b2,
                           const float* __restrict__ X, float* __restrict__ Y){
    int w=(blockIdx.x*blockDim.x+threadIdx.x)>>5; if(w>=Nn) return;
    int lane=threadIdx.x&31;
    float4 a1=spmm_row128(rp1,col1,val1,(const float4*)X,w,lane);
    float4 a2=spmm_row128(rp2,col2,val2,(const float4*)X,w,lane);
    float f1=b1[w], f2=b2[w];
    float4 r;
    r.x=fmaxf(f1*a1.x+f2*a2.x,0.f); r.y=fmaxf(f1*a1.y+f2*a2.y,0.f);
    r.z=fmaxf(f1*a1.z+f2*a2.z,0.f); r.w=fmaxf(f1*a1.w+f2*a2.w,0.f);
    ((float4*)Y)[(long)w*32+lane]=r;
}

__global__ void k_spmm128g(const int* __restrict__ bidx,
                           const int* __restrict__ rp, const int* __restrict__ col,
                           const float* __restrict__ val, const float* __restrict__ X,
                           float* __restrict__ Z){
    int w=(blockIdx.x*blockDim.x+threadIdx.x)>>5; if(w>=Bb) return;
    int lane=threadIdx.x&31;
    int row=bidx[w];
    float4 a=spmm_row128(rp,col,val,(const float4*)X,row,lane);
    a.x=fmaxf(a.x,0.f); a.y=fmaxf(a.y,0.f); a.z=fmaxf(a.z,0.f); a.w=fmaxf(a.w,0.f);
    ((float4*)Z)[(long)w*32+lane]=a;
}

__global__ void k_spmm128fg(const int* __restrict__ bidx,
                            const int* __restrict__ rp1, const int* __restrict__ col1,
                            const float* __restrict__ val1,
                            const int* __restrict__ rp2, const int* __restrict__ col2,
                            const float* __restrict__ val2,
                            const float* __restrict__ b1, const float* __restrict__ b2,
                            const float* __restrict__ X, float* __restrict__ Z){
    int w=(blockIdx.x*blockDim.x+threadIdx.x)>>5; if(w>=Bb) return;
    int lane=threadIdx.x&31;
    int row=bidx[w];
    float4 a1=spmm_row128(rp1,col1,val1,(const float4*)X,row,lane);
    float4 a2=spmm_row128(rp2,col2,val2,(const float4*)X,row,lane);
    float f1=b1[row], f2=b2[row];
    float4 r;
    r.x=fmaxf(f1*a1.x+f2*a2.x,0.f); r.y=fmaxf(f1*a1.y+f2*a2.y,0.f);
    r.z=fmaxf(f1*a1.z+f2*a2.z,0.f); r.w=fmaxf(f1*a1.w+f2*a2.w,0.f);
    ((float4*)Z)[(long)w*32+lane]=r;
}

__global__ void k_spmm64(const int* __restrict__ rp, const int* __restrict__ col,
                         const float* __restrict__ val, const float* __restrict__ X,
                         float* __restrict__ Y){
    int w=(blockIdx.x*blockDim.x+threadIdx.x)>>5; if(w>=Nn) return;
    int lane=threadIdx.x&31;
    const float2* X2=(const float2*)X;
    int s=rp[w], e=rp[w+1];
    float2 A=make_float2(0.f,0.f), B=A;
    int i=s;
    for(; i+1<e; i+=2){
        int c0=col[i], c1=col[i+1];
        float v0=val[i], v1=val[i+1];
        float2 x0=X2[(long)c0*32+lane];
        float2 x1=X2[(long)c1*32+lane];
        A.x+=v0*x0.x; A.y+=v0*x0.y;
        B.x+=v1*x1.x; B.y+=v1*x1.y;
    }
    if(i<e){
        int c=col[i]; float v=val[i];
        float2 x=X2[(long)c*32+lane];
        A.x+=v*x.x; A.y+=v*x.y;
    }
    A.x=fmaxf(A.x+B.x,0.f); A.y=fmaxf(A.y+B.y,0.f);
    ((float2*)Y)[(long)w*32+lane]=A;
}

__global__ void k_spmm16(const int* __restrict__ rp, const int* __restrict__ col,
                         const float* __restrict__ val, const float* __restrict__ X,
                         float* __restrict__ Y){
    int row=blockIdx.x*16+threadIdx.y; int j=threadIdx.x;
    if(row>=Nn) return;
    float acc=0.f;
    for(int i=rp[row];i<rp[row+1];i++) acc+=val[i]*X[(long)col[i]*16+j];
    Y[(long)row*16+j]=acc;
}

__global__ void k_spmm16f(const int* __restrict__ rp1, const int* __restrict__ col1,
                          const float* __restrict__ val1,
                          const int* __restrict__ rp2, const int* __restrict__ col2,
                          const float* __restrict__ val2,
                          const float* __restrict__ b1, const float* __restrict__ b2,
                          const float* __restrict__ X, float* __restrict__ Y){
    int row=blockIdx.x*16+threadIdx.y; int j=threadIdx.x;
    if(row>=Nn) return;
    float a1=0.f, a2=0.f;
    for(int i=rp1[row];i<rp1[row+1];i++) a1+=val1[i]*X[(long)col1[i]*16+j];
    for(int i=rp2[row];i<rp2[row+1];i++) a2+=val2[i]*X[(long)col2[i]*16+j];
    Y[(long)row*16+j]=b1[row]*a1+b2[row]*a2;
}

// ------------- gen_view helpers -------------
__global__ void k_nodedot(const float* __restrict__ emb, const float* __restrict__ Wm,
                          float* __restrict__ dr, float* __restrict__ dc){
    int node=(blockIdx.x*blockDim.x+threadIdx.x)>>5; if(node>=Nn) return;
    int lane=threadIdx.x&31;
    float2 e=((const float2*)(emb+(long)node*64))[lane];
    float2 wr=((const float2*)Wm)[lane];
    float2 wc=((const float2*)Wm)[lane+32];
    float a=e.x*wr.x+e.y*wr.y;
    float b=e.x*wc.x+e.y*wc.y;
#pragma unroll
    for(int o=16;o;o>>=1){
        a+=__shfl_xor_sync(0xffffffffu,a,o);
        b+=__shfl_xor_sync(0xffffffffu,b,o);
    }
    if(lane==0){dr[node]=a; dc[node]=b;}
}

__global__ void k_gensoftmax(const int* __restrict__ rp, const int* __restrict__ col,
                             float* __restrict__ val, const float* __restrict__ dr,
                             const float* __restrict__ dc, const float* __restrict__ bm,
                             float com){
    int row=(blockIdx.x*blockDim.x+threadIdx.x)>>5; if(row>=Nn) return;
    int lane=threadIdx.x&31;
    int s=rp[row], e=rp[row+1];
    if(s==e) return;
    float base=dr[row]+bm[0];
    float m=-3.4e38f;
    for(int i=s+lane;i<e;i+=32) m=fmaxf(m, base+dc[col[i]]);
#pragma unroll
    for(int o=16;o;o>>=1) m=fmaxf(m,__shfl_xor_sync(0xffffffffu,m,o));
    float ss=0.f;
    for(int i=s+lane;i<e;i+=32) ss+=__expf(base+dc[col[i]]-m);
#pragma unroll
    for(int o=16;o;o>>=1) ss+=__shfl_xor_sync(0xffffffffu,ss,o);
    float inv=com/ss;
    for(int i=s+lane;i<e;i+=32) val[i]+=__expf(base+dc[col[i]]-m)*inv;
}

// ------------- 16-class softmax + logits + top2 weight -------------
__global__ void k_softmax_w(const float* __restrict__ C, float* __restrict__ lg,
                            float* __restrict__ w){
    int node=blockIdx.x*blockDim.x+threadIdx.x; if(node>=Nn) return;
    float x[16];
    const float4* p=(const float4*)(C+(long)node*16);
#pragma unroll
    for(int q=0;q<4;q++){float4 t=p[q]; x[4*q]=t.x; x[4*q+1]=t.y; x[4*q+2]=t.z; x[4*q+3]=t.w;}
    float m=x[0];
#pragma unroll
    for(int j=1;j<16;j++) m=fmaxf(m,x[j]);
    float s=0.f;
#pragma unroll
    for(int j=0;j<16;j++){x[j]=__expf(x[j]-m); s+=x[j];}
    float inv=1.f/s;
    float fir=0.f, sec=0.f;
#pragma unroll
    for(int j=0;j<16;j++){
        float pr=x[j]*inv;
        lg[(long)node*16+j]=logf(pr+EPSF);
        if(pr>fir){sec=fir; fir=pr;} else if(pr>sec) sec=pr;
    }
    if(w) w[node]=sqrtf((fir+EPSF)*(fir-sec+EPSF));
}

__global__ void k_bal(const float* __restrict__ w1, const float* __restrict__ w2,
                      float* __restrict__ b1, float* __restrict__ b2){
    int i=blockIdx.x*blockDim.x+threadIdx.x; if(i>=Nn) return;
    float a=w1[i], b=w2[i], inv=1.f/(a+b);
    b1[i]=a*inv; b2[i]=b*inv;
}

__global__ void k_normrows(float* __restrict__ E, int nrows){
    int row=(blockIdx.x*blockDim.x+threadIdx.x)>>5; if(row>=nrows) return;
    int lane=threadIdx.x&31;
    float4* p=(float4*)(E+(long)row*128);
    float4 v=p[lane];
    float s=v.x*v.x+v.y*v.y+v.z*v.z+v.w*v.w;
#pragma unroll
    for(int o=16;o;o>>=1) s+=__shfl_xor_sync(0xffffffffu,s,o);
    float inv=rsqrtf(s);
    v.x*=inv; v.y*=inv; v.z*=inv; v.w*=inv;
    p[lane]=v;
}

// ------------- contrast pair (double-buffered): exp(2*z1.z2) sums + diag -------------
__global__ __launch_bounds__(256,2) void k_contrast(
        const float* __restrict__ z1, const float* __restrict__ z2,
        float* __restrict__ rs, float* __restrict__ cs, float* __restrict__ dg){
    extern __shared__ __align__(16) float smem[];
    float* sAb=smem;
    float* sWb=smem+2*ATILE;
    __shared__ float sRS[128], sCS[128];
    int tid=threadIdx.x, tx=tid&15, ty=tid>>4;
    int br=blockIdx.y*128, bc=blockIdx.x*128;
    u64 acc[8][4];
#pragma unroll
    for(int i=0;i<8;i++){acc[i][0]=0;acc[i][1]=0;acc[i][2]=0;acc[i][3]=0;}
    int ra=tid>>3, fa=(tid&7)<<2;

#define LOADC(k0, sA, sW) do{ \
    _Pragma("unroll") \
    for(int h=0;h<4;h++){ \
        int r=ra+h*32; \
        float4 v=*(const float4*)(z1+(long)(br+r)*128+(k0)+fa); \
        (sA)[(fa+0)*APAD+r]=v.x; (sA)[(fa+1)*APAD+r]=v.y; \
        (sA)[(fa+2)*APAD+r]=v.z; (sA)[(fa+3)*APAD+r]=v.w; \
    } \
    _Pragma("unroll") \
    for(int h=0;h<4;h++){ \
        int c=ra+h*32; \
        float4 v=*(const float4*)(z2+(long)(bc+c)*128+(k0)+fa); \
        (sW)[(fa+0)*128+c]=v.x; (sW)[(fa+1)*128+c]=v.y; \
        (sW)[(fa+2)*128+c]=v.z; (sW)[(fa+3)*128+c]=v.w; \
    } \
}while(0)

    LOADC(0, sAb, sWb);
    __syncthreads();
    int buf=0;
#pragma unroll 1
    for(int k0=0;k0<128;k0+=32){
        if(k0+32<128) LOADC(k0+32, sAb+(buf^1)*ATILE, sWb+(buf^1)*WTILE);
        COMPUTE_CHUNK(sAb+buf*ATILE, sWb+buf*WTILE);
        __syncthreads();
        buf^=1;
    }
#undef LOADC
    if(tid<128){sRS[tid]=0.f; sCS[tid]=0.f;}
    __syncthreads();
    float rsum[8]={0,0,0,0,0,0,0,0}, csum[8]={0,0,0,0,0,0,0,0};
#pragma unroll
    for(int i=0;i<8;i++){
        float vv[8];
#pragma unroll
        for(int p=0;p<4;p++){float2 t=up2(acc[i][p]); vv[2*p]=t.x; vv[2*p+1]=t.y;}
        int gr=br+ty*8+i;
#pragma unroll
        for(int j=0;j<8;j++){
            float e=__expf(2.0f*vv[j]);
            rsum[i]+=e; csum[j]+=e;
            if(gr==bc+tx*8+j) dg[gr]=e;
        }
    }
#pragma unroll
    for(int i=0;i<8;i++) atomicAdd(&sRS[ty*8+i], rsum[i]);
#pragma unroll
    for(int j=0;j<8;j++) atomicAdd(&sCS[tx*8+j], csum[j]);
    __syncthreads();
    if(tid<128){atomicAdd(&rs[br+tid], sRS[tid]); atomicAdd(&cs[bc+tid], sCS[tid]);}
}

__global__ void k_creduce3(const float* __restrict__ RS, const float* __restrict__ CS,
                           const float* __restrict__ DG, float* out){
    __shared__ float sh[1024];
    int pair=blockIdx.x;
    const float* rs=RS+(long)pair*Bb;
    const float* cs=CS+(long)pair*Bb;
    const float* dg=DG+(long)pair*Bb;
    int tid=threadIdx.x;
    float a=0.f;
    for(int i=tid;i<Bb;i+=1024){
        a+=-logf(dg[i]/(rs[i]+EPSF)+EPSF);
        a+=-logf(dg[i]/(cs[i]+EPSF)+EPSF);
    }
    sh[tid]=a; __syncthreads();
    for(int d=512;d;d>>=1){ if(tid<d) sh[tid]+=sh[tid+d]; __syncthreads(); }
    if(tid==0) out[pair]=0.5f*sh[0]/(float)Bb;
}

// ------------- host -------------
#define GSA(var) ([]{ void* _p; cudaGetSymbolAddress(&_p, var); return _p; }())

extern "C" void kernel_launch(void* const* d_in, const int* in_sizes, int n_in,
                              void* d_out, int out_size){
    const float* feat  =(const float*)d_in[0];
    const int*   i1    =(const int*)  d_in[1];
    const float* v1    =(const float*)d_in[2];
    const int*   i2    =(const int*)  d_in[3];
    const float* v2    =(const float*)d_in[4];
    const int*   bidx  =(const int*)  d_in[5];
    const float* Wgen1 =(const float*)d_in[6];
    const float* Wm1   =(const float*)d_in[7];
    const float* bm1   =(const float*)d_in[8];
    const float* Wgen2 =(const float*)d_in[9];
    const float* Wm2   =(const float*)d_in[10];
    const float* bm2   =(const float*)d_in[11];
    const float* W1v1  =(const float*)d_in[12];
    const float* W2v1  =(const float*)d_in[13];
    const float* W1v2  =(const float*)d_in[14];
    const float* W2v2  =(const float*)d_in[15];
    const float* W1v   =(const float*)d_in[16];
    const float* W2v   =(const float*)d_in[17];
    const float* Wg    =(const float*)d_in[18];
    const float* Wg1   =(const float*)d_in[19];
    const float* Wg2   =(const float*)d_in[20];
    const float* Wp1   =(const float*)d_in[21];
    const float* bp1   =(const float*)d_in[22];
    const float* Wp2   =(const float*)d_in[23];
    const float* bp2   =(const float*)d_in[24];
    float* out=(float*)d_out;

    float* Wp=(float*)GSA(g_Wp);
    float* X64a=(float*)GSA(g_X64a); float* X64b=(float*)GSA(g_X64b);
    float* XC1=(float*)GSA(g_XC1); float* XC2=(float*)GSA(g_XC2); float* XCf=(float*)GSA(g_XCf);
    float* XG=(float*)GSA(g_XG); float* XG1=(float*)GSA(g_XG1); float* XG2=(float*)GSA(g_XG2);
    float* Ha=(float*)GSA(g_Ha); float* Hb=(float*)GSA(g_Hb);
    float* emba=(float*)GSA(g_emba); float* embb=(float*)GSA(g_embb);
    float* S16a=(float*)GSA(g_S16a); float* S16b=(float*)GSA(g_S16b);
    float* C16a=(float*)GSA(g_C16a); float* C16b=(float*)GSA(g_C16b);
    float* dra=(float*)GSA(g_dra), *dca=(float*)GSA(g_dca);
    float* drb=(float*)GSA(g_drb), *dcb=(float*)GSA(g_dcb);
    float* w1=(float*)GSA(g_w1), *w2=(float*)GSA(g_w2);
    float* b1=(float*)GSA(g_b1), *b2=(float*)GSA(g_b2);
    int* cnt1=(int*)GSA(g_cnt1), *cnt1b=(int*)GSA(g_cnt1b);
    int* cnt2=(int*)GSA(g_cnt2), *cnt2b=(int*)GSA(g_cnt2b);
    int* cur1d=(int*)GSA(g_cur1d), *cur2d=(int*)GSA(g_cur2d);
    int* cur1s=(int*)GSA(g_cur1s), *cur2s=(int*)GSA(g_cur2s);
    int* rp1d=(int*)GSA(g_rp1d), *rp2d=(int*)GSA(g_rp2d);
    int* rp1s=(int*)GSA(g_rp1s), *rp2s=(int*)GSA(g_rp2s);
    int* col1d=(int*)GSA(g_col1d);   float* val1d=(float*)GSA(g_val1d);
    int* col2d=(int*)GSA(g_col2d);   float* val2d=(float*)GSA(g_val2d);
    int* col1s=(int*)GSA(g_col1s);   float* val1s=(float*)GSA(g_val1s);
    int* col2s=(int*)GSA(g_col2s);   float* val2s=(float*)GSA(g_val2s);
    float* Z=(float*)GSA(g_Z), *T=(float*)GSA(g_T), *E=(float*)GSA(g_E);
    float* RS=(float*)GSA(g_RS), *CS=(float*)GSA(g_CS), *DG=(float*)GSA(g_DG);

    float* E0=E;
    float* E1=E+(long)Bb*128;
    float* E2=E+(long)2*Bb*128;

    const int TB=256;
    int gN  =(Nn+TB-1)/TB;
    int gE  =(Ee+TB-1)/TB;
    int gW  =(Nn*32+TB-1)/TB;
    int gWB =(Bb*32+TB-1)/TB;
    dim3 b16(16,16); int g16=(Nn+15)/16;
    dim3 cg(32,32);

    static cudaStream_t s1=0, s2=0, s3=0;
    static cudaEvent_t eRoot=0,eScan=0,eA=0,eB=0,eC=0,eW1=0,eW2=0,eZ1=0,eZ2=0,
                       eFg=0,eEV=0,eE12=0,eCa=0,eCb=0;
    if(!s1){
        cudaStreamCreateWithFlags(&s1, cudaStreamNonBlocking);
        cudaStreamCreateWithFlags(&s2, cudaStreamNonBlocking);
        cudaStreamCreateWithFlags(&s3, cudaStreamNonBlocking);
        cudaEventCreateWithFlags(&eRoot,cudaEventDisableTiming);
        cudaEventCreateWithFlags(&eScan,cudaEventDisableTiming);
        cudaEventCreateWithFlags(&eA, cudaEventDisableTiming);
        cudaEventCreateWithFlags(&eB, cudaEventDisableTiming);
        cudaEventCreateWithFlags(&eC, cudaEventDisableTiming);
        cudaEventCreateWithFlags(&eW1,cudaEventDisableTiming);
        cudaEventCreateWithFlags(&eW2,cudaEventDisableTiming);
        cudaEventCreateWithFlags(&eZ1,cudaEventDisableTiming);
        cudaEventCreateWithFlags(&eZ2,cudaEventDisableTiming);
        cudaEventCreateWithFlags(&eFg,cudaEventDisableTiming);
        cudaEventCreateWithFlags(&eEV,cudaEventDisableTiming);
        cudaEventCreateWithFlags(&eE12,cudaEventDisableTiming);
        cudaEventCreateWithFlags(&eCa,cudaEventDisableTiming);
        cudaEventCreateWithFlags(&eCb,cudaEventDisableTiming);
        cudaFuncSetAttribute(k_gemmP,    cudaFuncAttributeMaxDynamicSharedMemorySize, SMEM_DB);
        cudaFuncSetAttribute(k_gemm128,  cudaFuncAttributeMaxDynamicSharedMemorySize, SMEM_DB);
        cudaFuncSetAttribute(k_contrast, cudaFuncAttributeMaxDynamicSharedMemorySize, SMEM_DB);
    }

    cudaEventRecord(eRoot, 0);
    cudaStreamWaitEvent(s1, eRoot, 0);
    cudaStreamWaitEvent(s2, eRoot, 0);
    cudaStreamWaitEvent(s3, eRoot, 0);

    int gyP=(Nn+127)/128;
    // ---- stream 0: pack + sliced big GEMM (ordered by consumer need) ----
    k_pack<<<(256*896+TB-1)/TB,TB>>>(Wgen1,Wgen2,W1v1,W1v2,W1v,Wg,Wg1,Wg2,Wp);
    k_zero_f2<<<(3*Bb+TB-1)/TB,TB>>>(RS,CS,3*Bb);
    k_gemmP<<<dim3(1,gyP),256,SMEM_DB>>>(feat,Wp,0,X64a,X64b,XC1,XC2,XCf,XG,XG1,XG2);
    cudaEventRecord(eA, 0);   // X64a, X64b ready
    k_gemmP<<<dim3(2,gyP),256,SMEM_DB>>>(feat,Wp,1,X64a,X64b,XC1,XC2,XCf,XG,XG1,XG2);
    cudaEventRecord(eB, 0);   // XC1, XC2 ready
    k_gemmP<<<dim3(2,gyP),256,SMEM_DB>>>(feat,Wp,5,X64a,X64b,XC1,XC2,XCf,XG,XG1,XG2);
    cudaEventRecord(eC, 0);   // XG1, XG2 ready
    k_gemmP<<<dim3(2,gyP),256,SMEM_DB>>>(feat,Wp,3,X64a,X64b,XC1,XC2,XCf,XG,XG1,XG2);
    // XCf, XG ready (stream 0 in-order for stream-0 consumers)

    // ---- s1: CSR build + view1 pipeline ----
    k_zero4<<<gN,TB,0,s1>>>(cnt1,cnt1b,cnt2,cnt2b,Nn);
    k_count2<<<gE,TB,0,s1>>>(i1,i2,cnt1,cnt1b,cnt2,cnt2b);
    k_scan4<<<4,1024,0,s1>>>(cnt1,rp1d,cur1d,cnt1b,rp1s,cur1s,cnt2,rp2d,cur2d,cnt2b,rp2s,cur2s);
    cudaEventRecord(eScan, s1);
    k_scatter_dir<<<gE,TB,0,s1>>>(i1,v1,cur1d,col1d,val1d);
    cudaStreamWaitEvent(s1, eA, 0);
    k_spmm64<<<gW,TB,0,s1>>>(rp1d,col1d,val1d,X64a,emba);
    k_nodedot<<<gW,TB,0,s1>>>(emba,Wm1,dra,dca);
    k_gensoftmax<<<gW,TB,0,s1>>>(rp1d,col1d,val1d,dra,dca,bm1,0.5f);
    k_scatter_sym<<<gN,TB,0,s1>>>(rp1d,col1d,val1d,cur1s,col1s,val1s);
    cudaStreamWaitEvent(s1, eB, 0);
    k_spmm128<<<gW,TB,0,s1>>>(rp1s,col1s,val1s,XC1,Ha);
    k_gemm16<<<g16,b16,0,s1>>>(Ha,W2v1,S16a,Nn);
    k_spmm16<<<g16,b16,0,s1>>>(rp1s,col1s,val1s,S16a,C16a);
    k_softmax_w<<<gN,TB,0,s1>>>(C16a,out+(long)16*Nn,w1);
    cudaEventRecord(eW1, s1);
    cudaStreamWaitEvent(s1, eC, 0);
    k_spmm128g<<<gWB,TB,0,s1>>>(bidx,rp1s,col1s,val1s,XG1,E1);
    cudaEventRecord(eZ1, s1);

    // ---- s2: view2 pipeline ----
    cudaStreamWaitEvent(s2, eScan, 0);
    k_scatter_dir<<<gE,TB,0,s2>>>(i2,v2,cur2d,col2d,val2d);
    cudaStreamWaitEvent(s2, eA, 0);
    k_spmm64<<<gW,TB,0,s2>>>(rp2d,col2d,val2d,X64b,embb);
    k_nodedot<<<gW,TB,0,s2>>>(embb,Wm2,drb,dcb);
    k_gensoftmax<<<gW,TB,0,s2>>>(rp2d,col2d,val2d,drb,dcb,bm2,0.5f);
    k_scatter_sym<<<gN,TB,0,s2>>>(rp2d,col2d,val2d,cur2s,col2s,val2s);
    cudaStreamWaitEvent(s2, eB, 0);
    k_spmm128<<<gW,TB,0,s2>>>(rp2s,col2s,val2s,XC2,Hb);
    k_gemm16<<<g16,b16,0,s2>>>(Hb,W2v2,S16b,Nn);
    k_spmm16<<<g16,b16,0,s2>>>(rp2s,col2s,val2s,S16b,C16b);
    k_softmax_w<<<gN,TB,0,s2>>>(C16b,out+(long)32*Nn,w2);
    cudaEventRecord(eW2, s2);
    cudaStreamWaitEvent(s2, eC, 0);
    k_spmm128g<<<gWB,TB,0,s2>>>(bidx,rp2s,col2s,val2s,XG2,E2);
    cudaEventRecord(eZ2, s2);

    // ---- s3: E1/E2 projection (gather buf -> T -> back into E1/E2) + contrast(E1,E2) ----
    cudaStreamWaitEvent(s3, eZ1, 0);
    cudaStreamWaitEvent(s3, eZ2, 0);
    k_gemm128<<<dim3(1,(2*Bb+127)/128),256,SMEM_DB,s3>>>(E1,Wp1,bp1,T+(long)Bb*128,2*Bb,128,1);
    k_gemm128<<<dim3(1,(2*Bb+127)/128),256,SMEM_DB,s3>>>(T+(long)Bb*128,Wp2,bp2,E1,2*Bb,128,0);
    k_normrows<<<(2*Bb*32+TB-1)/TB,TB,0,s3>>>(E1,2*Bb);
    cudaEventRecord(eE12, s3);
    k_contrast<<<cg,256,SMEM_DB,s3>>>(E1,E2,RS+2*Bb,CS+2*Bb,DG+2*Bb);   // pair v1v2

    // ---- stream 0: bal + EV gather, fused classifier chain ----
    cudaStreamWaitEvent(0, eW1, 0);
    cudaStreamWaitEvent(0, eW2, 0);
    k_bal<<<gN,TB>>>(w1,w2,b1,b2);
    k_spmm128fg<<<gWB,TB>>>(bidx,rp1s,col1s,val1s,rp2s,col2s,val2s,b1,b2,XG,Z);
    cudaEventRecord(eFg, 0);
    k_spmm128f<<<gW,TB>>>(rp1s,col1s,val1s,rp2s,col2s,val2s,b1,b2,XCf,Ha);
    k_gemm16<<<g16,b16>>>(Ha,W2v,S16a,Nn);
    k_spmm16f<<<g16,b16>>>(rp1s,col1s,val1s,rp2s,col2s,val2s,b1,b2,S16a,C16a);
    k_softmax_w<<<gN,TB>>>(C16a,out,nullptr);

    // ---- s1: EV projection + contrast(EV,E1) ----
    cudaStreamWaitEvent(s1, eFg, 0);
    k_gemm128<<<dim3(1,(Bb+127)/128),256,SMEM_DB,s1>>>(Z,Wp1,bp1,T,Bb,128,1);
    k_gemm128<<<dim3(1,(Bb+127)/128),256,SMEM_DB,s1>>>(T,Wp2,bp2,E0,Bb,128,0);
    k_normrows<<<(Bb*32+TB-1)/TB,TB,0,s1>>>(E0,Bb);
    cudaEventRecord(eEV, s1);
    cudaStreamWaitEvent(s1, eE12, 0);
    k_contrast<<<cg,256,SMEM_DB,s1>>>(E0,E1,RS,CS,DG);                   // pair vv1
    cudaEventRecord(eCa, s1);

    // ---- s3: contrast(EV,E2) ----
    cudaStreamWaitEvent(s3, eEV, 0);
    k_contrast<<<cg,256,SMEM_DB,s3>>>(E0,E2,RS+Bb,CS+Bb,DG+Bb);          // pair vv2
    cudaEventRecord(eCb, s3);

    // ---- stream 0: final reduce ----
    cudaStreamWaitEvent(0, eCa, 0);
    cudaStreamWaitEvent(0, eCb, 0);
    k_creduce3<<<3,1024>>>(RS,CS,DG,out+(long)48*Nn);
}

// round 12
// speedup vs baseline: 1.0104x; 1.0104x over previous
#include <cuda_runtime.h>
#include <math.h>

#define Nn 30000
#define Ee 480000
#define Bb 4096
#define EPSF 1e-8f

typedef unsigned long long u64;
__device__ __forceinline__ u64 pk2(float x,float y){u64 r;asm("mov.b64 %0,{%1,%2};":"=l"(r):"f"(x),"f"(y));return r;}
__device__ __forceinline__ float2 up2(u64 v){float2 r;asm("mov.b64 {%0,%1},%2;":"=f"(r.x),"=f"(r.y):"l"(v));return r;}
__device__ __forceinline__ void fma2(u64&d,u64 a,u64 b){asm("fma.rn.f32x2 %0,%1,%2,%0;":"+l"(d):"l"(a),"l"(b));}

#define APAD 132

// ------------- device scratch -------------
__device__ float g_Wp[256*896];
__device__ float g_X64a[Nn*64], g_X64b[Nn*64];
__device__ float g_XC1[Nn*128], g_XC2[Nn*128], g_XCf[Nn*128];
__device__ float g_XG[Nn*128], g_XG1[Nn*128], g_XG2[Nn*128];
__device__ float g_Ha[Nn*128], g_Hb[Nn*128];
__device__ float g_emba[Nn*64], g_embb[Nn*64];
__device__ float g_S16a[Nn*16], g_S16b[Nn*16];
__device__ float g_C16a[Nn*16], g_C16b[Nn*16];
__device__ float g_dra[Nn], g_dca[Nn], g_drb[Nn], g_dcb[Nn];
__device__ float g_w1[Nn], g_w2[Nn], g_b1[Nn], g_b2[Nn];
__device__ int   g_cnt1[Nn], g_cnt1b[Nn], g_cnt2[Nn], g_cnt2b[Nn];
__device__ int   g_cur1d[Nn], g_cur2d[Nn], g_cur1s[Nn], g_cur2s[Nn];
__device__ int   g_rp1d[Nn+1], g_rp2d[Nn+1], g_rp1s[Nn+1], g_rp2s[Nn+1];
__device__ int   g_col1d[Ee];   __device__ float g_val1d[Ee];
__device__ int   g_col2d[Ee];   __device__ float g_val2d[Ee];
__device__ int   g_col1s[2*Ee]; __device__ float g_val1s[2*Ee];
__device__ int   g_col2s[2*Ee]; __device__ float g_val2s[2*Ee];
__device__ float g_Z[3*Bb*128], g_T[3*Bb*128], g_E[3*Bb*128];
__device__ float g_RS[3*Bb], g_CS[3*Bb], g_DG[3*Bb];

// ------------- pack weights -------------
__global__ void k_pack(const float* __restrict__ wg1, const float* __restrict__ wg2,
                       const float* __restrict__ a, const float* __restrict__ b,
                       const float* __restrict__ c, const float* __restrict__ d,
                       const float* __restrict__ e, const float* __restrict__ f,
                       float* __restrict__ Wp){
    int i=blockIdx.x*blockDim.x+threadIdx.x; if(i>=256*896) return;
    int row=i/896, col=i%896;
    float v;
    if(col<64) v=wg1[row*64+col];
    else if(col<128) v=wg2[row*64+col-64];
    else{
        int blk=(col-128)>>7, lc=(col-128)&127;
        const float* s;
        switch(blk){case 0:s=a;break;case 1:s=b;break;case 2:s=c;break;
                    case 3:s=d;break;case 4:s=e;break;default:s=f;break;}
        v=s[row*128+lc];
    }
    Wp[i]=v;
}

// ------------- small utils -------------
__global__ void k_zero4(int* a,int* b,int* c,int* d,int n){
    int i=blockIdx.x*blockDim.x+threadIdx.x; if(i<n){a[i]=0;b[i]=0;c[i]=0;d[i]=0;} }
__global__ void k_zero_f2(float* a, float* b, int n){
    int i=blockIdx.x*blockDim.x+threadIdx.x; if(i<n){a[i]=0.f;b[i]=0.f;} }

__global__ void k_count2(const int* __restrict__ ind1, const int* __restrict__ ind2,
                         int* cd1, int* cs1, int* cd2, int* cs2){
    int e=blockIdx.x*blockDim.x+threadIdx.x; if(e>=Ee) return;
    int r1=ind1[e], c1=ind1[Ee+e];
    atomicAdd(&cd1[r1],1); atomicAdd(&cs1[r1],1); atomicAdd(&cs1[c1],1);
    int r2=ind2[e], c2=ind2[Ee+e];
    atomicAdd(&cd2[r2],1); atomicAdd(&cs2[r2],1); atomicAdd(&cs2[c2],1);
}

// 4 independent scans; register-staged, fully unrolled (CHUNK=30)
__global__ void k_scan4(const int* c0,int* r0,int* u0,const int* c1,int* r1,int* u1,
                        const int* c2,int* r2,int* u2,const int* c3,int* r3,int* u3){
    const int* cnt; int* rp; int* cu;
    switch(blockIdx.x){
        case 0: cnt=c0; rp=r0; cu=u0; break;
        case 1: cnt=c1; rp=r1; cu=u1; break;
        case 2: cnt=c2; rp=r2; cu=u2; break;
        default:cnt=c3; rp=r3; cu=u3; break;
    }
    const int CH=30;
    int tid=threadIdx.x;
    int s=tid*CH;
    int vloc[CH];
#pragma unroll
    for(int i=0;i<CH;i++){int idx=s+i; vloc[i]=(idx<Nn)?cnt[idx]:0;}
    int sum=0;
#pragma unroll
    for(int i=0;i<CH;i++) sum+=vloc[i];
    __shared__ int wsum[32];
    int lane=tid&31, wid=tid>>5;
    int v=sum;
#pragma unroll
    for(int o=1;o<32;o<<=1){int t=__shfl_up_sync(0xffffffffu,v,o); if(lane>=o) v+=t;}
    if(lane==31) wsum[wid]=v;
    __syncthreads();
    if(wid==0){
        int w=wsum[lane];
#pragma unroll
        for(int o=1;o<32;o<<=1){int t=__shfl_up_sync(0xffffffffu,w,o); if(lane>=o) w+=t;}
        wsum[lane]=w;
    }
    __syncthreads();
    int excl=v-sum+(wid?wsum[wid-1]:0);
    int run=excl;
#pragma unroll
    for(int i=0;i<CH;i++){
        int idx=s+i;
        if(idx<Nn){ rp[idx]=run; cu[idx]=run; run+=vloc[i]; }
    }
    if(tid==1023) rp[Nn]=run;
}

__global__ void k_scatter_dir(const int* __restrict__ ind, const float* __restrict__ vals,
                              int* cur, int* __restrict__ col, float* __restrict__ val){
    int e=blockIdx.x*blockDim.x+threadIdx.x; if(e>=Ee) return;
    int r=ind[e], c=ind[Ee+e];
    int p=atomicAdd(&cur[r],1);
    col[p]=c; val[p]=vals[e];
}

__global__ void k_scatter_sym(const int* __restrict__ rpd, const int* __restrict__ cold,
                              const float* __restrict__ vald, int* cur,
                              int* __restrict__ cols, float* __restrict__ vals){
    int r=blockIdx.x*blockDim.x+threadIdx.x; if(r>=Nn) return;
    for(int i=rpd[r];i<rpd[r+1];i++){
        int c=cold[i]; float v=vald[i];
        int p=atomicAdd(&cur[r],1); cols[p]=c; vals[p]=v;
        int q=atomicAdd(&cur[c],1); cols[q]=r; vals[q]=v;
    }
}

// ------------- inner-product macro (8x8, f32x2) -------------
#define MMA_KK(sak, sWk) do{ \
    float4 aA=*(const float4*)(sak); \
    float4 aB=*(const float4*)((sak)+4); \
    const ulonglong2* bw=(const ulonglong2*)(sWk); \
    ulonglong2 bA=bw[0], bB=bw[1]; \
    u64 s0=pk2(aA.x,aA.x), s1=pk2(aA.y,aA.y); \
    u64 s2=pk2(aA.z,aA.z), s3=pk2(aA.w,aA.w); \
    u64 s4=pk2(aB.x,aB.x), s5=pk2(aB.y,aB.y); \
    u64 s6=pk2(aB.z,aB.z), s7=pk2(aB.w,aB.w); \
    fma2(acc[0][0],s0,bA.x); fma2(acc[0][1],s0,bA.y); fma2(acc[0][2],s0,bB.x); fma2(acc[0][3],s0,bB.y); \
    fma2(acc[1][0],s1,bA.x); fma2(acc[1][1],s1,bA.y); fma2(acc[1][2],s1,bB.x); fma2(acc[1][3],s1,bB.y); \
    fma2(acc[2][0],s2,bA.x); fma2(acc[2][1],s2,bA.y); fma2(acc[2][2],s2,bB.x); fma2(acc[2][3],s2,bB.y); \
    fma2(acc[3][0],s3,bA.x); fma2(acc[3][1],s3,bA.y); fma2(acc[3][2],s3,bB.x); fma2(acc[3][3],s3,bB.y); \
    fma2(acc[4][0],s4,bA.x); fma2(acc[4][1],s4,bA.y); fma2(acc[4][2],s4,bB.x); fma2(acc[4][3],s4,bB.y); \
    fma2(acc[5][0],s5,bA.x); fma2(acc[5][1],s5,bA.y); fma2(acc[5][2],s5,bB.x); fma2(acc[5][3],s5,bB.y); \
    fma2(acc[6][0],s6,bA.x); fma2(acc[6][1],s6,bA.y); fma2(acc[6][2],s6,bB.x); fma2(acc[6][3],s6,bB.y); \
    fma2(acc[7][0],s7,bA.x); fma2(acc[7][1],s7,bA.y); fma2(acc[7][2],s7,bB.x); fma2(acc[7][3],s7,bB.y); \
}while(0)

// ------------- packed GEMM slice: feat[30000x256] @ Wp[:,128*bx:128*(bx+1)] -------------
__global__ __launch_bounds__(256,2) void k_gemmP(
        const float* __restrict__ A, const float* __restrict__ Wp, int bxoff,
        float* __restrict__ e1, float* __restrict__ e2,
        float* __restrict__ x0, float* __restrict__ x1, float* __restrict__ x2,
        float* __restrict__ x3, float* __restrict__ x4, float* __restrict__ x5){
    __shared__ __align__(16) float sA[32*APAD];
    __shared__ __align__(16) float sW[32*128];
    int tid=threadIdx.x, tx=tid&15, ty=tid>>4;
    int bx=blockIdx.x+bxoff;
    int br=blockIdx.y*128;
    u64 acc[8][4];
#pragma unroll
    for(int i=0;i<8;i++){acc[i][0]=0;acc[i][1]=0;acc[i][2]=0;acc[i][3]=0;}
    int ra=tid>>3, fa=(tid&7)<<2;
    int cw=(tid&31)<<2, kw=tid>>5;

    for(int k0=0;k0<256;k0+=32){
#pragma unroll
        for(int h=0;h<4;h++){
            int r=ra+h*32, gr=br+r;
            float4 v=make_float4(0.f,0.f,0.f,0.f);
            if(gr<Nn) v=*(const float4*)(A+(long)gr*256+k0+fa);
            sA[(fa+0)*APAD+r]=v.x; sA[(fa+1)*APAD+r]=v.y;
            sA[(fa+2)*APAD+r]=v.z; sA[(fa+3)*APAD+r]=v.w;
        }
#pragma unroll
        for(int h=0;h<4;h++){
            int kk=kw+h*8;
            float4 v=*(const float4*)(Wp+(long)(k0+kk)*896+bx*128+cw);
            *(float4*)&sW[kk*128+cw]=v;
        }
        __syncthreads();
#pragma unroll
        for(int kk=0;kk<32;kk++){
            MMA_KK(&sA[kk*APAD+ty*8], &sW[kk*128+tx*8]);
        }
        __syncthreads();
    }
    float* dst; int w; int c0;
    if(bx==0){
        if(tx<8){ dst=e1; w=64; c0=tx*8; } else { dst=e2; w=64; c0=(tx-8)*8; }
    } else {
        switch(bx-1){case 0:dst=x0;break;case 1:dst=x1;break;case 2:dst=x2;break;
                     case 3:dst=x3;break;case 4:dst=x4;break;default:dst=x5;break;}
        w=128; c0=tx*8;
    }
#pragma unroll
    for(int i=0;i<8;i++){
        int gr=br+ty*8+i; if(gr>=Nn) continue;
        float vv[8];
#pragma unroll
        for(int p=0;p<4;p++){float2 t=up2(acc[i][p]); vv[2*p]=t.x; vv[2*p+1]=t.y;}
        float* cp=dst+(long)gr*w+c0;
        *(float4*)cp=make_float4(vv[0],vv[1],vv[2],vv[3]);
        *(float4*)(cp+4)=make_float4(vv[4],vv[5],vv[6],vv[7]);
    }
}

// ------------- generic GEMM: C[n,128]=A[n,K]@W[K,128] (+bias, act) -------------
__global__ __launch_bounds__(256,2) void k_gemm128(
        const float* __restrict__ A, const float* __restrict__ W,
        const float* __restrict__ bias, float* __restrict__ C,
        int n, int K, int act){
    __shared__ __align__(16) float sA[32*APAD];
    __shared__ __align__(16) float sW[32*128];
    int tid=threadIdx.x, tx=tid&15, ty=tid>>4;
    int br=blockIdx.y*128;
    u64 acc[8][4];
#pragma unroll
    for(int i=0;i<8;i++){acc[i][0]=0;acc[i][1]=0;acc[i][2]=0;acc[i][3]=0;}
    int ra=tid>>3, fa=(tid&7)<<2;
    int cw=(tid&31)<<2, kw=tid>>5;

    for(int k0=0;k0<K;k0+=32){
#pragma unroll
        for(int h=0;h<4;h++){
            int r=ra+h*32, gr=br+r;
            float4 v=make_float4(0.f,0.f,0.f,0.f);
            if(gr<n) v=*(const float4*)(A+(long)gr*K+k0+fa);
            sA[(fa+0)*APAD+r]=v.x; sA[(fa+1)*APAD+r]=v.y;
            sA[(fa+2)*APAD+r]=v.z; sA[(fa+3)*APAD+r]=v.w;
        }
#pragma unroll
        for(int h=0;h<4;h++){
            int kk=kw+h*8;
            float4 v=*(const float4*)(W+(long)(k0+kk)*128+cw);
            *(float4*)&sW[kk*128+cw]=v;
        }
        __syncthreads();
#pragma unroll
        for(int kk=0;kk<32;kk++){
            MMA_KK(&sA[kk*APAD+ty*8], &sW[kk*128+tx*8]);
        }
        __syncthreads();
    }
    float bb[8];
#pragma unroll
    for(int q=0;q<8;q++) bb[q]=bias?bias[tx*8+q]:0.f;
#pragma unroll
    for(int i=0;i<8;i++){
        int gr=br+ty*8+i; if(gr>=n) continue;
        float vv[8];
#pragma unroll
        for(int p=0;p<4;p++){float2 t=up2(acc[i][p]); vv[2*p]=t.x; vv[2*p+1]=t.y;}
#pragma unroll
        for(int q=0;q<8;q++){
            float v=vv[q]+bb[q];
            if(act==1) v=(v>0.f)?v:expm1f(v);
            vv[q]=v;
        }
        float* cp=C+(long)gr*128+tx*8;
        *(float4*)cp=make_float4(vv[0],vv[1],vv[2],vv[3]);
        *(float4*)(cp+4)=make_float4(vv[4],vv[5],vv[6],vv[7]);
    }
}

// ------------- GEMM M=16 (W2 in smem) -------------
__global__ void k_gemm16(const float* __restrict__ H, const float* __restrict__ W2,
                         float* __restrict__ C, int n){
    __shared__ float sW[128*16];
    int tid=threadIdx.y*16+threadIdx.x;
#pragma unroll
    for(int q=0;q<2;q++) ((float4*)sW)[tid*2+q]=((const float4*)W2)[tid*2+q];
    __syncthreads();
    int r=blockIdx.x*16+threadIdx.y, j=threadIdx.x;
    if(r>=n) return;
    const float4* H4=(const float4*)(H+(long)r*128);
    float acc=0.f;
#pragma unroll
    for(int k4=0;k4<32;k4++){
        float4 h=H4[k4];
        acc+=h.x*sW[(k4*4+0)*16+j];
        acc+=h.y*sW[(k4*4+1)*16+j];
        acc+=h.z*sW[(k4*4+2)*16+j];
        acc+=h.w*sW[(k4*4+3)*16+j];
    }
    C[(long)r*16+j]=acc;
}

// ------------- SpMM (warp per row, 2-way unrolled) -------------
__device__ __forceinline__ float4 spmm_row128(const int* __restrict__ rp,
        const int* __restrict__ col, const float* __restrict__ val,
        const float4* __restrict__ X4, int w, int lane){
    int s=rp[w], e=rp[w+1];
    float4 A=make_float4(0.f,0.f,0.f,0.f), B=A;
    int i=s;
    for(; i+1<e; i+=2){
        int c0=col[i], c1=col[i+1];
        float v0=val[i], v1=val[i+1];
        float4 x0=X4[(long)c0*32+lane];
        float4 x1=X4[(long)c1*32+lane];
        A.x+=v0*x0.x; A.y+=v0*x0.y; A.z+=v0*x0.z; A.w+=v0*x0.w;
        B.x+=v1*x1.x; B.y+=v1*x1.y; B.z+=v1*x1.z; B.w+=v1*x1.w;
    }
    if(i<e){
        int c=col[i]; float v=val[i];
        float4 x=X4[(long)c*32+lane];
        A.x+=v*x.x; A.y+=v*x.y; A.z+=v*x.z; A.w+=v*x.w;
    }
    A.x+=B.x; A.y+=B.y; A.z+=B.z; A.w+=B.w;
    return A;
}

__global__ void k_spmm128(const int* __restrict__ rp, const int* __restrict__ col,
                          const float* __restrict__ val, const float* __restrict__ X,
                          float* __restrict__ Y){
    int w=(blockIdx.x*blockDim.x+threadIdx.x)>>5; if(w>=Nn) return;
    int lane=threadIdx.x&31;
    float4 a=spmm_row128(rp,col,val,(const float4*)X,w,lane);
    a.x=fmaxf(a.x,0.f); a.y=fmaxf(a.y,0.f); a.z=fmaxf(a.z,0.f); a.w=fmaxf(a.w,0.f);
    ((float4*)Y)[(long)w*32+lane]=a;
}

__global__ void k_spmm128f(const int* __restrict__ rp1, const int* __restrict__ col1,
                           const float* __restrict__ val1,
                           const int* __restrict__ rp2, const int* __restrict__ col2,
                           const float* __restrict__ val2,
                           const float* __restrict__ b1, const float* __restrict__ b2,
                           const float* __restrict__ X, float* __restrict__ Y){
    int w=(blockIdx.x*blockDim.x+threadIdx.x)>>5; if(w>=Nn) return;
    int lane=threadIdx.x&31;
    float4 a1=spmm_row128(rp1,col1,val1,(const float4*)X,w,lane);
    float4 a2=spmm_row128(rp2,col2,val2,(const float4*)X,w,lane);
    float f1=b1[w], f2=b2[w];
    float4 r;
    r.x=fmaxf(f1*a1.x+f2*a2.x,0.f); r.y=fmaxf(f1*a1.y+f2*a2.y,0.f);
    r.z=fmaxf(f1*a1.z+f2*a2.z,0.f); r.w=fmaxf(f1*a1.w+f2*a2.w,0.f);
    ((float4*)Y)[(long)w*32+lane]=r;
}

__global__ void k_spmm128g(const int* __restrict__ bidx,
                           const int* __restrict__ rp, const int* __restrict__ col,
                           const float* __restrict__ val, const float* __restrict__ X,
                           float* __restrict__ Z){
    int w=(blockIdx.x*blockDim.x+threadIdx.x)>>5; if(w>=Bb) return;
    int lane=threadIdx.x&31;
    int row=bidx[w];
    float4 a=spmm_row128(rp,col,val,(const float4*)X,row,lane);
    a.x=fmaxf(a.x,0.f); a.y=fmaxf(a.y,0.f); a.z=fmaxf(a.z,0.f); a.w=fmaxf(a.w,0.f);
    ((float4*)Z)[(long)w*32+lane]=a;
}

__global__ void k_spmm128fg(const int* __restrict__ bidx,
                            const int* __restrict__ rp1, const int* __restrict__ col1,
                            const float* __restrict__ val1,
                            const int* __restrict__ rp2, const int* __restrict__ col2,
                            const float* __restrict__ val2,
                            const float* __restrict__ b1, const float* __restrict__ b2,
                            const float* __restrict__ X, float* __restrict__ Z){
    int w=(blockIdx.x*blockDim.x+threadIdx.x)>>5; if(w>=Bb) return;
    int lane=threadIdx.x&31;
    int row=bidx[w];
    float4 a1=spmm_row128(rp1,col1,val1,(const float4*)X,row,lane);
    float4 a2=spmm_row128(rp2,col2,val2,(const float4*)X,row,lane);
    float f1=b1[row], f2=b2[row];
    float4 r;
    r.x=fmaxf(f1*a1.x+f2*a2.x,0.f); r.y=fmaxf(f1*a1.y+f2*a2.y,0.f);
    r.z=fmaxf(f1*a1.z+f2*a2.z,0.f); r.w=fmaxf(f1*a1.w+f2*a2.w,0.f);
    ((float4*)Z)[(long)w*32+lane]=r;
}

__global__ void k_spmm64(const int* __restrict__ rp, const int* __restrict__ col,
                         const float* __restrict__ val, const float* __restrict__ X,
                         float* __restrict__ Y){
    int w=(blockIdx.x*blockDim.x+threadIdx.x)>>5; if(w>=Nn) return;
    int lane=threadIdx.x&31;
    const float2* X2=(const float2*)X;
    int s=rp[w], e=rp[w+1];
    float2 A=make_float2(0.f,0.f), B=A;
    int i=s;
    for(; i+1<e; i+=2){
        int c0=col[i], c1=col[i+1];
        float v0=val[i], v1=val[i+1];
        float2 x0=X2[(long)c0*32+lane];
        float2 x1=X2[(long)c1*32+lane];
        A.x+=v0*x0.x; A.y+=v0*x0.y;
        B.x+=v1*x1.x; B.y+=v1*x1.y;
    }
    if(i<e){
        int c=col[i]; float v=val[i];
        float2 x=X2[(long)c*32+lane];
        A.x+=v*x.x; A.y+=v*x.y;
    }
    A.x=fmaxf(A.x+B.x,0.f); A.y=fmaxf(A.y+B.y,0.f);
    ((float2*)Y)[(long)w*32+lane]=A;
}

__global__ void k_spmm16(const int* __restrict__ rp, const int* __restrict__ col,
                         const float* __restrict__ val, const float* __restrict__ X,
                         float* __restrict__ Y){
    int row=blockIdx.x*16+threadIdx.y; int j=threadIdx.x;
    if(row>=Nn) return;
    float acc=0.f;
    for(int i=rp[row];i<rp[row+1];i++) acc+=val[i]*X[(long)col[i]*16+j];
    Y[(long)row*16+j]=acc;
}

__global__ void k_spmm16f(const int* __restrict__ rp1, const int* __restrict__ col1,
                          const float* __restrict__ val1,
                          const int* __restrict__ rp2, const int* __restrict__ col2,
                          const float* __restrict__ val2,
                          const float* __restrict__ b1, const float* __restrict__ b2,
                          const float* __restrict__ X, float* __restrict__ Y){
    int row=blockIdx.x*16+threadIdx.y; int j=threadIdx.x;
    if(row>=Nn) return;
    float a1=0.f, a2=0.f;
    for(int i=rp1[row];i<rp1[row+1];i++) a1+=val1[i]*X[(long)col1[i]*16+j];
    for(int i=rp2[row];i<rp2[row+1];i++) a2+=val2[i]*X[(long)col2[i]*16+j];
    Y[(long)row*16+j]=b1[row]*a1+b2[row]*a2;
}

// ------------- gen_view helpers -------------
__global__ void k_nodedot(const float* __restrict__ emb, const float* __restrict__ Wm,
                          float* __restrict__ dr, float* __restrict__ dc){
    int node=(blockIdx.x*blockDim.x+threadIdx.x)>>5; if(node>=Nn) return;
    int lane=threadIdx.x&31;
    float2 e=((const float2*)(emb+(long)node*64))[lane];
    float2 wr=((const float2*)Wm)[lane];
    float2 wc=((const float2*)Wm)[lane+32];
    float a=e.x*wr.x+e.y*wr.y;
    float b=e.x*wc.x+e.y*wc.y;
#pragma unroll
    for(int o=16;o;o>>=1){
        a+=__shfl_xor_sync(0xffffffffu,a,o);
        b+=__shfl_xor_sync(0xffffffffu,b,o);
    }
    if(lane==0){dr[node]=a; dc[node]=b;}
}

__global__ void k_gensoftmax(const int* __restrict__ rp, const int* __restrict__ col,
                             float* __restrict__ val, const float* __restrict__ dr,
                             const float* __restrict__ dc, const float* __restrict__ bm,
                             float com){
    int row=(blockIdx.x*blockDim.x+threadIdx.x)>>5; if(row>=Nn) return;
    int lane=threadIdx.x&31;
    int s=rp[row], e=rp[row+1];
    if(s==e) return;
    float base=dr[row]+bm[0];
    float m=-3.4e38f;
    for(int i=s+lane;i<e;i+=32) m=fmaxf(m, base+dc[col[i]]);
#pragma unroll
    for(int o=16;o;o>>=1) m=fmaxf(m,__shfl_xor_sync(0xffffffffu,m,o));
    float ss=0.f;
    for(int i=s+lane;i<e;i+=32) ss+=__expf(base+dc[col[i]]-m);
#pragma unroll
    for(int o=16;o;o>>=1) ss+=__shfl_xor_sync(0xffffffffu,ss,o);
    float inv=com/ss;
    for(int i=s+lane;i<e;i+=32) val[i]+=__expf(base+dc[col[i]]-m)*inv;
}

// ------------- 16-class softmax + logits + top2 weight -------------
__global__ void k_softmax_w(const float* __restrict__ C, float* __restrict__ lg,
                            float* __restrict__ w){
    int node=blockIdx.x*blockDim.x+threadIdx.x; if(node>=Nn) return;
    float x[16];
    const float4* p=(const float4*)(C+(long)node*16);
#pragma unroll
    for(int q=0;q<4;q++){float4 t=p[q]; x[4*q]=t.x; x[4*q+1]=t.y; x[4*q+2]=t.z; x[4*q+3]=t.w;}
    float m=x[0];
#pragma unroll
    for(int j=1;j<16;j++) m=fmaxf(m,x[j]);
    float s=0.f;
#pragma unroll
    for(int j=0;j<16;j++){x[j]=__expf(x[j]-m); s+=x[j];}
    float inv=1.f/s;
    float fir=0.f, sec=0.f;
#pragma unroll
    for(int j=0;j<16;j++){
        float pr=x[j]*inv;
        lg[(long)node*16+j]=logf(pr+EPSF);
        if(pr>fir){sec=fir; fir=pr;} else if(pr>sec) sec=pr;
    }
    if(w) w[node]=sqrtf((fir+EPSF)*(fir-sec+EPSF));
}

__global__ void k_bal(const float* __restrict__ w1, const float* __restrict__ w2,
                      float* __restrict__ b1, float* __restrict__ b2){
    int i=blockIdx.x*blockDim.x+threadIdx.x; if(i>=Nn) return;
    float a=w1[i], b=w2[i], inv=1.f/(a+b);
    b1[i]=a*inv; b2[i]=b*inv;
}

__global__ void k_normrows(float* __restrict__ E, int nrows){
    int row=(blockIdx.x*blockDim.x+threadIdx.x)>>5; if(row>=nrows) return;
    int lane=threadIdx.x&31;
    float4* p=(float4*)(E+(long)row*128);
    float4 v=p[lane];
    float s=v.x*v.x+v.y*v.y+v.z*v.z+v.w*v.w;
#pragma unroll
    for(int o=16;o;o>>=1) s+=__shfl_xor_sync(0xffffffffu,s,o);
    float inv=rsqrtf(s);
    v.x*=inv; v.y*=inv; v.z*=inv; v.w*=inv;
    p[lane]=v;
}

// ------------- contrast pair: exp(2*z1.z2) row/col sums + diag -------------
__global__ __launch_bounds__(256,2) void k_contrast(
        const float* __restrict__ z1, const float* __restrict__ z2,
        float* __restrict__ rs, float* __restrict__ cs, float* __restrict__ dg){
    __shared__ __align__(16) float sA[32*APAD];
    __shared__ __align__(16) float sW[32*128];
    __shared__ float sRS[128], sCS[128];
    int tid=threadIdx.x, tx=tid&15, ty=tid>>4;
    int br=blockIdx.y*128, bc=blockIdx.x*128;
    u64 acc[8][4];
#pragma unroll
    for(int i=0;i<8;i++){acc[i][0]=0;acc[i][1]=0;acc[i][2]=0;acc[i][3]=0;}
    int ra=tid>>3, fa=(tid&7)<<2;

    for(int k0=0;k0<128;k0+=32){
#pragma unroll
        for(int h=0;h<4;h++){
            int r=ra+h*32;
            float4 v=*(const float4*)(z1+(long)(br+r)*128+k0+fa);
            sA[(fa+0)*APAD+r]=v.x; sA[(fa+1)*APAD+r]=v.y;
            sA[(fa+2)*APAD+r]=v.z; sA[(fa+3)*APAD+r]=v.w;
        }
#pragma unroll
        for(int h=0;h<4;h++){
            int c=ra+h*32;
            float4 v=*(const float4*)(z2+(long)(bc+c)*128+k0+fa);
            sW[(fa+0)*128+c]=v.x; sW[(fa+1)*128+c]=v.y;
            sW[(fa+2)*128+c]=v.z; sW[(fa+3)*128+c]=v.w;
        }
        __syncthreads();
#pragma unroll
        for(int kk=0;kk<32;kk++){
            MMA_KK(&sA[kk*APAD+ty*8], &sW[kk*128+tx*8]);
        }
        __syncthreads();
    }
    if(tid<128){sRS[tid]=0.f; sCS[tid]=0.f;}
    __syncthreads();
    float rsum[8]={0,0,0,0,0,0,0,0}, csum[8]={0,0,0,0,0,0,0,0};
#pragma unroll
    for(int i=0;i<8;i++){
        float vv[8];
#pragma unroll
        for(int p=0;p<4;p++){float2 t=up2(acc[i][p]); vv[2*p]=t.x; vv[2*p+1]=t.y;}
        int gr=br+ty*8+i;
#pragma unroll
        for(int j=0;j<8;j++){
            float e=__expf(2.0f*vv[j]);
            rsum[i]+=e; csum[j]+=e;
            if(gr==bc+tx*8+j) dg[gr]=e;
        }
    }
#pragma unroll
    for(int i=0;i<8;i++) atomicAdd(&sRS[ty*8+i], rsum[i]);
#pragma unroll
    for(int j=0;j<8;j++) atomicAdd(&sCS[tx*8+j], csum[j]);
    __syncthreads();
    if(tid<128){atomicAdd(&rs[br+tid], sRS[tid]); atomicAdd(&cs[bc+tid], sCS[tid]);}
}

__global__ void k_creduce3(const float* __restrict__ RS, const float* __restrict__ CS,
                           const float* __restrict__ DG, float* out){
    __shared__ float sh[1024];
    int pair=blockIdx.x;
    const float* rs=RS+(long)pair*Bb;
    const float* cs=CS+(long)pair*Bb;
    const float* dg=DG+(long)pair*Bb;
    int tid=threadIdx.x;
    float a=0.f;
    for(int i=tid;i<Bb;i+=1024){
        a+=-logf(dg[i]/(rs[i]+EPSF)+EPSF);
        a+=-logf(dg[i]/(cs[i]+EPSF)+EPSF);
    }
    sh[tid]=a; __syncthreads();
    for(int d=512;d;d>>=1){ if(tid<d) sh[tid]+=sh[tid+d]; __syncthreads(); }
    if(tid==0) out[pair]=0.5f*sh[0]/(float)Bb;
}

// ------------- host -------------
#define GSA(var) ([]{ void* _p; cudaGetSymbolAddress(&_p, var); return _p; }())

extern "C" void kernel_launch(void* const* d_in, const int* in_sizes, int n_in,
                              void* d_out, int out_size){
    const float* feat  =(const float*)d_in[0];
    const int*   i1    =(const int*)  d_in[1];
    const float* v1    =(const float*)d_in[2];
    const int*   i2    =(const int*)  d_in[3];
    const float* v2    =(const float*)d_in[4];
    const int*   bidx  =(const int*)  d_in[5];
    const float* Wgen1 =(const float*)d_in[6];
    const float* Wm1   =(const float*)d_in[7];
    const float* bm1   =(const float*)d_in[8];
    const float* Wgen2 =(const float*)d_in[9];
    const float* Wm2   =(const float*)d_in[10];
    const float* bm2   =(const float*)d_in[11];
    const float* W1v1  =(const float*)d_in[12];
    const float* W2v1  =(const float*)d_in[13];
    const float* W1v2  =(const float*)d_in[14];
    const float* W2v2  =(const float*)d_in[15];
    const float* W1v   =(const float*)d_in[16];
    const float* W2v   =(const float*)d_in[17];
    const float* Wg    =(const float*)d_in[18];
    const float* Wg1   =(const float*)d_in[19];
    const float* Wg2   =(const float*)d_in[20];
    const float* Wp1   =(const float*)d_in[21];
    const float* bp1   =(const float*)d_in[22];
    const float* Wp2   =(const float*)d_in[23];
    const float* bp2   =(const float*)d_in[24];
    float* out=(float*)d_out;

    float* Wp=(float*)GSA(g_Wp);
    float* X64a=(float*)GSA(g_X64a); float* X64b=(float*)GSA(g_X64b);
    float* XC1=(float*)GSA(g_XC1); float* XC2=(float*)GSA(g_XC2); float* XCf=(float*)GSA(g_XCf);
    float* XG=(float*)GSA(g_XG); float* XG1=(float*)GSA(g_XG1); float* XG2=(float*)GSA(g_XG2);
    float* Ha=(float*)GSA(g_Ha); float* Hb=(float*)GSA(g_Hb);
    float* emba=(float*)GSA(g_emba); float* embb=(float*)GSA(g_embb);
    float* S16a=(float*)GSA(g_S16a); float* S16b=(float*)GSA(g_S16b);
    float* C16a=(float*)GSA(g_C16a); float* C16b=(float*)GSA(g_C16b);
    float* dra=(float*)GSA(g_dra), *dca=(float*)GSA(g_dca);
    float* drb=(float*)GSA(g_drb), *dcb=(float*)GSA(g_dcb);
    float* w1=(float*)GSA(g_w1), *w2=(float*)GSA(g_w2);
    float* b1=(float*)GSA(g_b1), *b2=(float*)GSA(g_b2);
    int* cnt1=(int*)GSA(g_cnt1), *cnt1b=(int*)GSA(g_cnt1b);
    int* cnt2=(int*)GSA(g_cnt2), *cnt2b=(int*)GSA(g_cnt2b);
    int* cur1d=(int*)GSA(g_cur1d), *cur2d=(int*)GSA(g_cur2d);
    int* cur1s=(int*)GSA(g_cur1s), *cur2s=(int*)GSA(g_cur2s);
    int* rp1d=(int*)GSA(g_rp1d), *rp2d=(int*)GSA(g_rp2d);
    int* rp1s=(int*)GSA(g_rp1s), *rp2s=(int*)GSA(g_rp2s);
    int* col1d=(int*)GSA(g_col1d);   float* val1d=(float*)GSA(g_val1d);
    int* col2d=(int*)GSA(g_col2d);   float* val2d=(float*)GSA(g_val2d);
    int* col1s=(int*)GSA(g_col1s);   float* val1s=(float*)GSA(g_val1s);
    int* col2s=(int*)GSA(g_col2s);   float* val2s=(float*)GSA(g_val2s);
    float* Z=(float*)GSA(g_Z), *T=(float*)GSA(g_T), *E=(float*)GSA(g_E);
    float* RS=(float*)GSA(g_RS), *CS=(float*)GSA(g_CS), *DG=(float*)GSA(g_DG);

    float* E0=E;
    float* E1=E+(long)Bb*128;
    float* E2=E+(long)2*Bb*128;

    const int TB=256;
    int gN  =(Nn+TB-1)/TB;
    int gE  =(Ee+TB-1)/TB;
    int gW  =(Nn*32+TB-1)/TB;
    int gWB =(Bb*32+TB-1)/TB;
    dim3 b16(16,16); int g16=(Nn+15)/16;
    dim3 cg(32,32);

    static cudaStream_t s1=0, s2=0, s3=0;
    static cudaEvent_t eRoot=0,eScan=0,eA=0,eB=0,eC=0,eD=0,eSym2=0,eW1=0,eW2=0,
                       eZ1=0,eZ2=0,eFg=0,eEV=0,eE12=0,eCa=0,eCb=0,eF2=0;
    if(!s1){
        cudaStreamCreateWithFlags(&s1, cudaStreamNonBlocking);
        cudaStreamCreateWithFlags(&s2, cudaStreamNonBlocking);
        cudaStreamCreateWithFlags(&s3, cudaStreamNonBlocking);
        cudaEventCreateWithFlags(&eRoot,cudaEventDisableTiming);
        cudaEventCreateWithFlags(&eScan,cudaEventDisableTiming);
        cudaEventCreateWithFlags(&eA, cudaEventDisableTiming);
        cudaEventCreateWithFlags(&eB, cudaEventDisableTiming);
        cudaEventCreateWithFlags(&eC, cudaEventDisableTiming);
        cudaEventCreateWithFlags(&eD, cudaEventDisableTiming);
        cudaEventCreateWithFlags(&eSym2,cudaEventDisableTiming);
        cudaEventCreateWithFlags(&eW1,cudaEventDisableTiming);
        cudaEventCreateWithFlags(&eW2,cudaEventDisableTiming);
        cudaEventCreateWithFlags(&eZ1,cudaEventDisableTiming);
        cudaEventCreateWithFlags(&eZ2,cudaEventDisableTiming);
        cudaEventCreateWithFlags(&eFg,cudaEventDisableTiming);
        cudaEventCreateWithFlags(&eEV,cudaEventDisableTiming);
        cudaEventCreateWithFlags(&eE12,cudaEventDisableTiming);
        cudaEventCreateWithFlags(&eCa,cudaEventDisableTiming);
        cudaEventCreateWithFlags(&eCb,cudaEventDisableTiming);
        cudaEventCreateWithFlags(&eF2,cudaEventDisableTiming);
    }

    cudaEventRecord(eRoot, 0);
    cudaStreamWaitEvent(s1, eRoot, 0);
    cudaStreamWaitEvent(s2, eRoot, 0);
    cudaStreamWaitEvent(s3, eRoot, 0);

    int gyP=(Nn+127)/128;
    // ---- stream 0: pack + sliced big GEMM, reordered by consumer need ----
    // bx map: 0=X64ab, 1=XC1, 2=XC2, 3=XCf, 4=XG, 5=XG1, 6=XG2
    k_pack<<<(256*896+TB-1)/TB,TB>>>(Wgen1,Wgen2,W1v1,W1v2,W1v,Wg,Wg1,Wg2,Wp);
    k_zero_f2<<<(3*Bb+TB-1)/TB,TB>>>(RS,CS,3*Bb);
    k_gemmP<<<dim3(1,gyP),256>>>(feat,Wp,0,X64a,X64b,XC1,XC2,XCf,XG,XG1,XG2);
    cudaEventRecord(eA, 0);   // X64a, X64b
    k_gemmP<<<dim3(2,gyP),256>>>(feat,Wp,1,X64a,X64b,XC1,XC2,XCf,XG,XG1,XG2);
    cudaEventRecord(eB, 0);   // XC1, XC2
    k_gemmP<<<dim3(2,gyP),256>>>(feat,Wp,3,X64a,X64b,XC1,XC2,XCf,XG,XG1,XG2);
    cudaEventRecord(eD, 0);   // XCf, XG
    k_gemmP<<<dim3(2,gyP),256>>>(feat,Wp,5,X64a,X64b,XC1,XC2,XCf,XG,XG1,XG2);
    cudaEventRecord(eC, 0);   // XG1, XG2

    // ---- s1: CSR build + view1 pipeline ----
    k_zero4<<<gN,TB,0,s1>>>(cnt1,cnt1b,cnt2,cnt2b,Nn);
    k_count2<<<gE,TB,0,s1>>>(i1,i2,cnt1,cnt1b,cnt2,cnt2b);
    k_scan4<<<4,1024,0,s1>>>(cnt1,rp1d,cur1d,cnt1b,rp1s,cur1s,cnt2,rp2d,cur2d,cnt2b,rp2s,cur2s);
    cudaEventRecord(eScan, s1);
    k_scatter_dir<<<gE,TB,0,s1>>>(i1,v1,cur1d,col1d,val1d);
    cudaStreamWaitEvent(s1, eA, 0);
    k_spmm64<<<gW,TB,0,s1>>>(rp1d,col1d,val1d,X64a,emba);
    k_nodedot<<<gW,TB,0,s1>>>(emba,Wm1,dra,dca);
    k_gensoftmax<<<gW,TB,0,s1>>>(rp1d,col1d,val1d,dra,dca,bm1,0.5f);
    k_scatter_sym<<<gN,TB,0,s1>>>(rp1d,col1d,val1d,cur1s,col1s,val1s);
    cudaStreamWaitEvent(s1, eB, 0);
    k_spmm128<<<gW,TB,0,s1>>>(rp1s,col1s,val1s,XC1,Ha);
    k_gemm16<<<g16,b16,0,s1>>>(Ha,W2v1,S16a,Nn);
    k_spmm16<<<g16,b16,0,s1>>>(rp1s,col1s,val1s,S16a,C16a);
    k_softmax_w<<<gN,TB,0,s1>>>(C16a,out+(long)16*Nn,w1);
    cudaEventRecord(eW1, s1);
    cudaStreamWaitEvent(s1, eC, 0);
    k_spmm128g<<<gWB,TB,0,s1>>>(bidx,rp1s,col1s,val1s,XG1,E1);
    cudaEventRecord(eZ1, s1);

    // ---- s2: view2 pipeline, then fused classifier chain ----
    cudaStreamWaitEvent(s2, eScan, 0);
    k_scatter_dir<<<gE,TB,0,s2>>>(i2,v2,cur2d,col2d,val2d);
    cudaStreamWaitEvent(s2, eA, 0);
    k_spmm64<<<gW,TB,0,s2>>>(rp2d,col2d,val2d,X64b,embb);
    k_nodedot<<<gW,TB,0,s2>>>(embb,Wm2,drb,dcb);
    k_gensoftmax<<<gW,TB,0,s2>>>(rp2d,col2d,val2d,drb,dcb,bm2,0.5f);
    k_scatter_sym<<<gN,TB,0,s2>>>(rp2d,col2d,val2d,cur2s,col2s,val2s);
    cudaEventRecord(eSym2, s2);
    cudaStreamWaitEvent(s2, eB, 0);
    k_spmm128<<<gW,TB,0,s2>>>(rp2s,col2s,val2s,XC2,Hb);
    k_gemm16<<<g16,b16,0,s2>>>(Hb,W2v2,S16b,Nn);
    k_spmm16<<<g16,b16,0,s2>>>(rp2s,col2s,val2s,S16b,C16b);
    k_softmax_w<<<gN,TB,0,s2>>>(C16b,out+(long)32*Nn,w2);
    cudaEventRecord(eW2, s2);
    // fused classifier chain (needs w1 from s1, XCf/XG from eD)
    cudaStreamWaitEvent(s2, eW1, 0);
    cudaStreamWaitEvent(s2, eD, 0);
    k_bal<<<gN,TB,0,s2>>>(w1,w2,b1,b2);
    k_spmm128fg<<<gWB,TB,0,s2>>>(bidx,rp1s,col1s,val1s,rp2s,col2s,val2s,b1,b2,XG,Z);
    cudaEventRecord(eFg, s2);
    k_spmm128f<<<gW,TB,0,s2>>>(rp1s,col1s,val1s,rp2s,col2s,val2s,b1,b2,XCf,Ha);
    k_gemm16<<<g16,b16,0,s2>>>(Ha,W2v,S16a,Nn);
    k_spmm16f<<<g16,b16,0,s2>>>(rp1s,col1s,val1s,rp2s,col2s,val2s,b1,b2,S16a,C16a);
    k_softmax_w<<<gN,TB,0,s2>>>(C16a,out,nullptr);
    cudaEventRecord(eF2, s2);

    // ---- s3: XG2 gather, E1/E2 projection + contrast(E1,E2) ----
    cudaStreamWaitEvent(s3, eC, 0);
    cudaStreamWaitEvent(s3, eSym2, 0);
    k_spmm128g<<<gWB,TB,0,s3>>>(bidx,rp2s,col2s,val2s,XG2,E2);
    cudaEventRecord(eZ2, s3);
    cudaStreamWaitEvent(s3, eZ1, 0);
    k_gemm128<<<dim3(1,(2*Bb+127)/128),256,0,s3>>>(E1,Wp1,bp1,T+(long)Bb*128,2*Bb,128,1);
    k_gemm128<<<dim3(1,(2*Bb+127)/128),256,0,s3>>>(T+(long)Bb*128,Wp2,bp2,E1,2*Bb,128,0);
    k_normrows<<<(2*Bb*32+TB-1)/TB,TB,0,s3>>>(E1,2*Bb);
    cudaEventRecord(eE12, s3);
    k_contrast<<<cg,256,0,s3>>>(E1,E2,RS+2*Bb,CS+2*Bb,DG+2*Bb);   // pair v1v2

    // ---- s1: EV projection + contrast(EV,E1) ----
    cudaStreamWaitEvent(s1, eFg, 0);
    k_gemm128<<<dim3(1,(Bb+127)/128),256,0,s1>>>(Z,Wp1,bp1,T,Bb,128,1);
    k_gemm128<<<dim3(1,(Bb+127)/128),256,0,s1>>>(T,Wp2,bp2,E0,Bb,128,0);
    k_normrows<<<(Bb*32+TB-1)/TB,TB,0,s1>>>(E0,Bb);
    cudaEventRecord(eEV, s1);
    cudaStreamWaitEvent(s1, eE12, 0);
    k_contrast<<<cg,256,0,s1>>>(E0,E1,RS,CS,DG);                   // pair vv1
    cudaEventRecord(eCa, s1);

    // ---- s3: contrast(EV,E2) ----
    cudaStreamWaitEvent(s3, eEV, 0);
    k_contrast<<<cg,256,0,s3>>>(E0,E2,RS+Bb,CS+Bb,DG+Bb);          // pair vv2
    cudaEventRecord(eCb, s3);

    // ---- stream 0: join all streams + final reduce ----
    cudaStreamWaitEvent(0, eCa, 0);
    cudaStreamWaitEvent(0, eCb, 0);
    cudaStreamWaitEvent(0, eF2, 0);
    k_creduce3<<<3,1024>>>(RS,CS,DG,out+(long)48*Nn);
}

// round 13
// speedup vs baseline: 1.6318x; 1.6150x over previous
#include <cuda_runtime.h>
#include <math.h>

#define Nn 30000
#define Ee 480000
#define Bb 4096
#define EPSF 1e-8f

typedef unsigned long long u64;
typedef unsigned int u32;
__device__ __forceinline__ u64 pk2(float x,float y){u64 r;asm("mov.b64 %0,{%1,%2};":"=l"(r):"f"(x),"f"(y));return r;}
__device__ __forceinline__ float2 up2(u64 v){float2 r;asm("mov.b64 {%0,%1},%2;":"=f"(r.x),"=f"(r.y):"l"(v));return r;}
__device__ __forceinline__ void fma2(u64&d,u64 a,u64 b){asm("fma.rn.f32x2 %0,%1,%2,%0;":"+l"(d):"l"(a),"l"(b));}
__device__ __forceinline__ u32 f2tf(float f){u32 u;asm("cvt.rna.tf32.f32 %0,%1;":"=r"(u):"f"(f));return u;}
__device__ __forceinline__ void mma_tf32(float* c,u32 a0,u32 a1,u32 a2,u32 a3,u32 b0,u32 b1){
    asm volatile("mma.sync.aligned.m16n8k8.row.col.f32.tf32.tf32.f32 "
        "{%0,%1,%2,%3},{%4,%5,%6,%7},{%8,%9},{%0,%1,%2,%3};"
        : "+f"(c[0]),"+f"(c[1]),"+f"(c[2]),"+f"(c[3])
        : "r"(a0),"r"(a1),"r"(a2),"r"(a3),"r"(b0),"r"(b1));
}

#define APAD 132
#define SAP 36     // A smem row stride (floats): bank-exact (36%32==4)
#define SBP 136    // B smem row stride: bank-exact (136%32==8)

// ------------- device scratch -------------
__device__ float g_Wp[256*896];
__device__ float g_X64a[Nn*64], g_X64b[Nn*64];
__device__ float g_XC1[Nn*128], g_XC2[Nn*128], g_XCf[Nn*128];
__device__ float g_XG[Nn*128], g_XG1[Nn*128], g_XG2[Nn*128];
__device__ float g_Ha[Nn*128], g_Hb[Nn*128];
__device__ float g_emba[Nn*64], g_embb[Nn*64];
__device__ float g_S16a[Nn*16], g_S16b[Nn*16];
__device__ float g_C16a[Nn*16], g_C16b[Nn*16];
__device__ float g_dra[Nn], g_dca[Nn], g_drb[Nn], g_dcb[Nn];
__device__ float g_w1[Nn], g_w2[Nn], g_b1[Nn], g_b2[Nn];
__device__ int   g_cnt1[Nn], g_cnt1b[Nn], g_cnt2[Nn], g_cnt2b[Nn];
__device__ int   g_cur1d[Nn], g_cur2d[Nn], g_cur1s[Nn], g_cur2s[Nn];
__device__ int   g_rp1d[Nn+1], g_rp2d[Nn+1], g_rp1s[Nn+1], g_rp2s[Nn+1];
__device__ int   g_col1d[Ee];   __device__ float g_val1d[Ee];
__device__ int   g_col2d[Ee];   __device__ float g_val2d[Ee];
__device__ int   g_col1s[2*Ee]; __device__ float g_val1s[2*Ee];
__device__ int   g_col2s[2*Ee]; __device__ float g_val2s[2*Ee];
__device__ float g_Z[3*Bb*128], g_T[3*Bb*128], g_E[3*Bb*128];
__device__ float g_RS[3*Bb], g_CS[3*Bb], g_DG[3*Bb];

// ------------- pack weights -------------
__global__ void k_pack(const float* __restrict__ wg1, const float* __restrict__ wg2,
                       const float* __restrict__ a, const float* __restrict__ b,
                       const float* __restrict__ c, const float* __restrict__ d,
                       const float* __restrict__ e, const float* __restrict__ f,
                       float* __restrict__ Wp){
    int i=blockIdx.x*blockDim.x+threadIdx.x; if(i>=256*896) return;
    int row=i/896, col=i%896;
    float v;
    if(col<64) v=wg1[row*64+col];
    else if(col<128) v=wg2[row*64+col-64];
    else{
        int blk=(col-128)>>7, lc=(col-128)&127;
        const float* s;
        switch(blk){case 0:s=a;break;case 1:s=b;break;case 2:s=c;break;
                    case 3:s=d;break;case 4:s=e;break;default:s=f;break;}
        v=s[row*128+lc];
    }
    Wp[i]=v;
}

// ------------- small utils -------------
__global__ void k_zero4(int* a,int* b,int* c,int* d,int n){
    int i=blockIdx.x*blockDim.x+threadIdx.x; if(i<n){a[i]=0;b[i]=0;c[i]=0;d[i]=0;} }
__global__ void k_zero_f2(float* a, float* b, int n){
    int i=blockIdx.x*blockDim.x+threadIdx.x; if(i<n){a[i]=0.f;b[i]=0.f;} }

__global__ void k_count2(const int* __restrict__ ind1, const int* __restrict__ ind2,
                         int* cd1, int* cs1, int* cd2, int* cs2){
    int e=blockIdx.x*blockDim.x+threadIdx.x; if(e>=Ee) return;
    int r1=ind1[e], c1=ind1[Ee+e];
    atomicAdd(&cd1[r1],1); atomicAdd(&cs1[r1],1); atomicAdd(&cs1[c1],1);
    int r2=ind2[e], c2=ind2[Ee+e];
    atomicAdd(&cd2[r2],1); atomicAdd(&cs2[r2],1); atomicAdd(&cs2[c2],1);
}

// 4 independent scans; register-staged, fully unrolled (CHUNK=30)
__global__ void k_scan4(const int* c0,int* r0,int* u0,const int* c1,int* r1,int* u1,
                        const int* c2,int* r2,int* u2,const int* c3,int* r3,int* u3){
    const int* cnt; int* rp; int* cu;
    switch(blockIdx.x){
        case 0: cnt=c0; rp=r0; cu=u0; break;
        case 1: cnt=c1; rp=r1; cu=u1; break;
        case 2: cnt=c2; rp=r2; cu=u2; break;
        default:cnt=c3; rp=r3; cu=u3; break;
    }
    const int CH=30;
    int tid=threadIdx.x;
    int s=tid*CH;
    int vloc[CH];
#pragma unroll
    for(int i=0;i<CH;i++){int idx=s+i; vloc[i]=(idx<Nn)?cnt[idx]:0;}
    int sum=0;
#pragma unroll
    for(int i=0;i<CH;i++) sum+=vloc[i];
    __shared__ int wsum[32];
    int lane=tid&31, wid=tid>>5;
    int v=sum;
#pragma unroll
    for(int o=1;o<32;o<<=1){int t=__shfl_up_sync(0xffffffffu,v,o); if(lane>=o) v+=t;}
    if(lane==31) wsum[wid]=v;
    __syncthreads();
    if(wid==0){
        int w=wsum[lane];
#pragma unroll
        for(int o=1;o<32;o<<=1){int t=__shfl_up_sync(0xffffffffu,w,o); if(lane>=o) w+=t;}
        wsum[lane]=w;
    }
    __syncthreads();
    int excl=v-sum+(wid?wsum[wid-1]:0);
    int run=excl;
#pragma unroll
    for(int i=0;i<CH;i++){
        int idx=s+i;
        if(idx<Nn){ rp[idx]=run; cu[idx]=run; run+=vloc[i]; }
    }
    if(tid==1023) rp[Nn]=run;
}

__global__ void k_scatter_dir(const int* __restrict__ ind, const float* __restrict__ vals,
                              int* cur, int* __restrict__ col, float* __restrict__ val){
    int e=blockIdx.x*blockDim.x+threadIdx.x; if(e>=Ee) return;
    int r=ind[e], c=ind[Ee+e];
    int p=atomicAdd(&cur[r],1);
    col[p]=c; val[p]=vals[e];
}

__global__ void k_scatter_sym(const int* __restrict__ rpd, const int* __restrict__ cold,
                              const float* __restrict__ vald, int* cur,
                              int* __restrict__ cols, float* __restrict__ vals){
    int r=blockIdx.x*blockDim.x+threadIdx.x; if(r>=Nn) return;
    for(int i=rpd[r];i<rpd[r+1];i++){
        int c=cold[i]; float v=vald[i];
        int p=atomicAdd(&cur[r],1); cols[p]=c; vals[p]=v;
        int q=atomicAdd(&cur[c],1); cols[q]=r; vals[q]=v;
    }
}

// ======== tf32 MMA block: 128x128 tile, 8 warps (2x4), warp tile 64x32 ========
// A smem: [128 rows][SAP] tf32 bits (row-major k). B smem: [32 k][SBP] tf32 bits.
// compute loop body: per k8 load B frags (8), per mf load A frags (4), 16 mma.
#define TF32_COMPUTE_CHUNK() do{ \
    _Pragma("unroll") \
    for(int k8=0;k8<4;k8++){ \
        int kb=k8*8; \
        u32 bf[4][2]; \
        _Pragma("unroll") \
        for(int nf=0;nf<4;nf++){ \
            int nb=wc*32+nf*8+(lane>>2); \
            bf[nf][0]=sB[(kb+(lane&3))*SBP+nb]; \
            bf[nf][1]=sB[(kb+(lane&3)+4)*SBP+nb]; \
        } \
        _Pragma("unroll") \
        for(int mf=0;mf<4;mf++){ \
            int rb=wr*64+mf*16+(lane>>2); \
            u32 a0=sA[rb*SAP+kb+(lane&3)]; \
            u32 a1=sA[(rb+8)*SAP+kb+(lane&3)]; \
            u32 a2=sA[rb*SAP+kb+(lane&3)+4]; \
            u32 a3=sA[(rb+8)*SAP+kb+(lane&3)+4]; \
            _Pragma("unroll") \
            for(int nf=0;nf<4;nf++) mma_tf32(acc[mf][nf],a0,a1,a2,a3,bf[nf][0],bf[nf][1]); \
        } \
    } \
}while(0)

// ------------- packed GEMM slice (tf32): feat[30000x256] @ Wp[:,128*bx..] -------------
__global__ __launch_bounds__(256,2) void k_gemmP(
        const float* __restrict__ A, const float* __restrict__ Wp, int bxoff,
        float* __restrict__ e1, float* __restrict__ e2,
        float* __restrict__ x0, float* __restrict__ x1, float* __restrict__ x2,
        float* __restrict__ x3, float* __restrict__ x4, float* __restrict__ x5){
    __shared__ __align__(16) u32 sA[128*SAP];
    __shared__ __align__(16) u32 sB[32*SBP];
    int tid=threadIdx.x, lane=tid&31, ww=tid>>5, wr=ww>>2, wc=ww&3;
    int bx=blockIdx.x+bxoff;
    int br=blockIdx.y*128;
    float acc[4][4][4];
#pragma unroll
    for(int i=0;i<4;i++)
#pragma unroll
    for(int j=0;j<4;j++)
#pragma unroll
    for(int q=0;q<4;q++) acc[i][j][q]=0.f;
    int ra=tid>>3, fa=(tid&7)<<2;        // A loader
    int kwB=tid>>5, cw=(tid&31)<<2;      // B loader

    for(int k0=0;k0<256;k0+=32){
#pragma unroll
        for(int h=0;h<4;h++){
            int r=ra+h*32, gr=br+r;
            float4 v=make_float4(0.f,0.f,0.f,0.f);
            if(gr<Nn) v=*(const float4*)(A+(long)gr*256+k0+fa);
            uint4 t=make_uint4(f2tf(v.x),f2tf(v.y),f2tf(v.z),f2tf(v.w));
            *(uint4*)&sA[r*SAP+fa]=t;
        }
#pragma unroll
        for(int h=0;h<4;h++){
            int kk=kwB+h*8;
            float4 v=*(const float4*)(Wp+(long)(k0+kk)*896+bx*128+cw);
            uint4 t=make_uint4(f2tf(v.x),f2tf(v.y),f2tf(v.z),f2tf(v.w));
            *(uint4*)&sB[kk*SBP+cw]=t;
        }
        __syncthreads();
        TF32_COMPUTE_CHUNK();
        __syncthreads();
    }
    // epilogue: warp covers rows [br+wr*64,+64), cols [wc*32,+32)
    float* dst; int w; int cb;
    if(bx==0){
        if(wc<2){ dst=e1; w=64; cb=wc*32; } else { dst=e2; w=64; cb=(wc-2)*32; }
    } else {
        switch(bx-1){case 0:dst=x0;break;case 1:dst=x1;break;case 2:dst=x2;break;
                     case 3:dst=x3;break;case 4:dst=x4;break;default:dst=x5;break;}
        w=128; cb=wc*32;
    }
#pragma unroll
    for(int mf=0;mf<4;mf++){
        int r0=br+wr*64+mf*16+(lane>>2);
        int r1=r0+8;
#pragma unroll
        for(int nf=0;nf<4;nf++){
            int c=cb+nf*8+(lane&3)*2;
            if(r0<Nn) *(float2*)&dst[(long)r0*w+c]=make_float2(acc[mf][nf][0],acc[mf][nf][1]);
            if(r1<Nn) *(float2*)&dst[(long)r1*w+c]=make_float2(acc[mf][nf][2],acc[mf][nf][3]);
        }
    }
}

// ------------- inner-product macro (8x8, f32x2) for fp32 gemm128 -------------
#define MMA_KK(sak, sWk) do{ \
    float4 aA=*(const float4*)(sak); \
    float4 aB=*(const float4*)((sak)+4); \
    const ulonglong2* bw=(const ulonglong2*)(sWk); \
    ulonglong2 bA=bw[0], bB=bw[1]; \
    u64 s0=pk2(aA.x,aA.x), s1=pk2(aA.y,aA.y); \
    u64 s2=pk2(aA.z,aA.z), s3=pk2(aA.w,aA.w); \
    u64 s4=pk2(aB.x,aB.x), s5=pk2(aB.y,aB.y); \
    u64 s6=pk2(aB.z,aB.z), s7=pk2(aB.w,aB.w); \
    fma2(acc[0][0],s0,bA.x); fma2(acc[0][1],s0,bA.y); fma2(acc[0][2],s0,bB.x); fma2(acc[0][3],s0,bB.y); \
    fma2(acc[1][0],s1,bA.x); fma2(acc[1][1],s1,bA.y); fma2(acc[1][2],s1,bB.x); fma2(acc[1][3],s1,bB.y); \
    fma2(acc[2][0],s2,bA.x); fma2(acc[2][1],s2,bA.y); fma2(acc[2][2],s2,bB.x); fma2(acc[2][3],s2,bB.y); \
    fma2(acc[3][0],s3,bA.x); fma2(acc[3][1],s3,bA.y); fma2(acc[3][2],s3,bB.x); fma2(acc[3][3],s3,bB.y); \
    fma2(acc[4][0],s4,bA.x); fma2(acc[4][1],s4,bA.y); fma2(acc[4][2],s4,bB.x); fma2(acc[4][3],s4,bB.y); \
    fma2(acc[5][0],s5,bA.x); fma2(acc[5][1],s5,bA.y); fma2(acc[5][2],s5,bB.x); fma2(acc[5][3],s5,bB.y); \
    fma2(acc[6][0],s6,bA.x); fma2(acc[6][1],s6,bA.y); fma2(acc[6][2],s6,bB.x); fma2(acc[6][3],s6,bB.y); \
    fma2(acc[7][0],s7,bA.x); fma2(acc[7][1],s7,bA.y); fma2(acc[7][2],s7,bB.x); fma2(acc[7][3],s7,bB.y); \
}while(0)

// ------------- generic GEMM (fp32): C[n,128]=A[n,K]@W[K,128] (+bias, act) -------------
__global__ __launch_bounds__(256,2) void k_gemm128(
        const float* __restrict__ A, const float* __restrict__ W,
        const float* __restrict__ bias, float* __restrict__ C,
        int n, int K, int act){
    __shared__ __align__(16) float sA[32*APAD];
    __shared__ __align__(16) float sW[32*128];
    int tid=threadIdx.x, tx=tid&15, ty=tid>>4;
    int br=blockIdx.y*128;
    u64 acc[8][4];
#pragma unroll
    for(int i=0;i<8;i++){acc[i][0]=0;acc[i][1]=0;acc[i][2]=0;acc[i][3]=0;}
    int ra=tid>>3, fa=(tid&7)<<2;
    int cw=(tid&31)<<2, kw=tid>>5;

    for(int k0=0;k0<K;k0+=32){
#pragma unroll
        for(int h=0;h<4;h++){
            int r=ra+h*32, gr=br+r;
            float4 v=make_float4(0.f,0.f,0.f,0.f);
            if(gr<n) v=*(const float4*)(A+(long)gr*K+k0+fa);
            sA[(fa+0)*APAD+r]=v.x; sA[(fa+1)*APAD+r]=v.y;
            sA[(fa+2)*APAD+r]=v.z; sA[(fa+3)*APAD+r]=v.w;
        }
#pragma unroll
        for(int h=0;h<4;h++){
            int kk=kw+h*8;
            float4 v=*(const float4*)(W+(long)(k0+kk)*128+cw);
            *(float4*)&sW[kk*128+cw]=v;
        }
        __syncthreads();
#pragma unroll
        for(int kk=0;kk<32;kk++){
            MMA_KK(&sA[kk*APAD+ty*8], &sW[kk*128+tx*8]);
        }
        __syncthreads();
    }
    float bb[8];
#pragma unroll
    for(int q=0;q<8;q++) bb[q]=bias?bias[tx*8+q]:0.f;
#pragma unroll
    for(int i=0;i<8;i++){
        int gr=br+ty*8+i; if(gr>=n) continue;
        float vv[8];
#pragma unroll
        for(int p=0;p<4;p++){float2 t=up2(acc[i][p]); vv[2*p]=t.x; vv[2*p+1]=t.y;}
#pragma unroll
        for(int q=0;q<8;q++){
            float v=vv[q]+bb[q];
            if(act==1) v=(v>0.f)?v:expm1f(v);
            vv[q]=v;
        }
        float* cp=C+(long)gr*128+tx*8;
        *(float4*)cp=make_float4(vv[0],vv[1],vv[2],vv[3]);
        *(float4*)(cp+4)=make_float4(vv[4],vv[5],vv[6],vv[7]);
    }
}

// ------------- GEMM M=16 (W2 in smem) -------------
__global__ void k_gemm16(const float* __restrict__ H, const float* __restrict__ W2,
                         float* __restrict__ C, int n){
    __shared__ float sW[128*16];
    int tid=threadIdx.y*16+threadIdx.x;
#pragma unroll
    for(int q=0;q<2;q++) ((float4*)sW)[tid*2+q]=((const float4*)W2)[tid*2+q];
    __syncthreads();
    int r=blockIdx.x*16+threadIdx.y, j=threadIdx.x;
    if(r>=n) return;
    const float4* H4=(const float4*)(H+(long)r*128);
    float acc=0.f;
#pragma unroll
    for(int k4=0;k4<32;k4++){
        float4 h=H4[k4];
        acc+=h.x*sW[(k4*4+0)*16+j];
        acc+=h.y*sW[(k4*4+1)*16+j];
        acc+=h.z*sW[(k4*4+2)*16+j];
        acc+=h.w*sW[(k4*4+3)*16+j];
    }
    C[(long)r*16+j]=acc;
}

// ------------- SpMM (warp per row, 2-way unrolled) -------------
__device__ __forceinline__ float4 spmm_row128(const int* __restrict__ rp,
        const int* __restrict__ col, const float* __restrict__ val,
        const float4* __restrict__ X4, int w, int lane){
    int s=rp[w], e=rp[w+1];
    float4 A=make_float4(0.f,0.f,0.f,0.f), B=A;
    int i=s;
    for(; i+1<e; i+=2){
        int c0=col[i], c1=col[i+1];
        float v0=val[i], v1=val[i+1];
        float4 x0=X4[(long)c0*32+lane];
        float4 x1=X4[(long)c1*32+lane];
        A.x+=v0*x0.x; A.y+=v0*x0.y; A.z+=v0*x0.z; A.w+=v0*x0.w;
        B.x+=v1*x1.x; B.y+=v1*x1.y; B.z+=v1*x1.z; B.w+=v1*x1.w;
    }
    if(i<e){
        int c=col[i]; float v=val[i];
        float4 x=X4[(long)c*32+lane];
        A.x+=v*x.x; A.y+=v*x.y; A.z+=v*x.z; A.w+=v*x.w;
    }
    A.x+=B.x; A.y+=B.y; A.z+=B.z; A.w+=B.w;
    return A;
}

__global__ void k_spmm128(const int* __restrict__ rp, const int* __restrict__ col,
                          const float* __restrict__ val, const float* __restrict__ X,
                          float* __restrict__ Y){
    int w=(blockIdx.x*blockDim.x+threadIdx.x)>>5; if(w>=Nn) return;
    int lane=threadIdx.x&31;
    float4 a=spmm_row128(rp,col,val,(const float4*)X,w,lane);
    a.x=fmaxf(a.x,0.f); a.y=fmaxf(a.y,0.f); a.z=fmaxf(a.z,0.f); a.w=fmaxf(a.w,0.f);
    ((float4*)Y)[(long)w*32+lane]=a;
}

__global__ void k_spmm128f(const int* __restrict__ rp1, const int* __restrict__ col1,
                           const float* __restrict__ val1,
                           const int* __restrict__ rp2, const int* __restrict__ col2,
                           const float* __restrict__ val2,
                           const float* __restrict__ b1, const float* __restrict__ b2,
                           const float* __restrict__ X, float* __restrict__ Y){
    int w=(blockIdx.x*blockDim.x+threadIdx.x)>>5; if(w>=Nn) return;
    int lane=threadIdx.x&31;
    float4 a1=spmm_row128(rp1,col1,val1,(const float4*)X,w,lane);
    float4 a2=spmm_row128(rp2,col2,val2,(const float4*)X,w,lane);
    float f1=b1[w], f2=b2[w];
    float4 r;
    r.x=fmaxf(f1*a1.x+f2*a2.x,0.f); r.y=fmaxf(f1*a1.y+f2*a2.y,0.f);
    r.z=fmaxf(f1*a1.z+f2*a2.z,0.f); r.w=fmaxf(f1*a1.w+f2*a2.w,0.f);
    ((float4*)Y)[(long)w*32+lane]=r;
}

__global__ void k_spmm128g(const int* __restrict__ bidx,
                           const int* __restrict__ rp, const int* __restrict__ col,
                           const float* __restrict__ val, const float* __restrict__ X,
                           float* __restrict__ Z){
    int w=(blockIdx.x*blockDim.x+threadIdx.x)>>5; if(w>=Bb) return;
    int lane=threadIdx.x&31;
    int row=bidx[w];
    float4 a=spmm_row128(rp,col,val,(const float4*)X,row,lane);
    a.x=fmaxf(a.x,0.f); a.y=fmaxf(a.y,0.f); a.z=fmaxf(a.z,0.f); a.w=fmaxf(a.w,0.f);
    ((float4*)Z)[(long)w*32+lane]=a;
}

__global__ void k_spmm128fg(const int* __restrict__ bidx,
                            const int* __restrict__ rp1, const int* __restrict__ col1,
                            const float* __restrict__ val1,
                            const int* __restrict__ rp2, const int* __restrict__ col2,
                            const float* __restrict__ val2,
                            const float* __restrict__ b1, const float* __restrict__ b2,
                            const float* __restrict__ X, float* __restrict__ Z){
    int w=(blockIdx.x*blockDim.x+threadIdx.x)>>5; if(w>=Bb) return;
    int lane=threadIdx.x&31;
    int row=bidx[w];
    float4 a1=spmm_row128(rp1,col1,val1,(const float4*)X,row,lane);
    float4 a2=spmm_row128(rp2,col2,val2,(const float4*)X,row,lane);
    float f1=b1[row], f2=b2[row];
    float4 r;
    r.x=fmaxf(f1*a1.x+f2*a2.x,0.f); r.y=fmaxf(f1*a1.y+f2*a2.y,0.f);
    r.z=fmaxf(f1*a1.z+f2*a2.z,0.f); r.w=fmaxf(f1*a1.w+f2*a2.w,0.f);
    ((float4*)Z)[(long)w*32+lane]=r;
}

__global__ void k_spmm64(const int* __restrict__ rp, const int* __restrict__ col,
                         const float* __restrict__ val, const float* __restrict__ X,
                         float* __restrict__ Y){
    int w=(blockIdx.x*blockDim.x+threadIdx.x)>>5; if(w>=Nn) return;
    int lane=threadIdx.x&31;
    const float2* X2=(const float2*)X;
    int s=rp[w], e=rp[w+1];
    float2 A=make_float2(0.f,0.f), B=A;
    int i=s;
    for(; i+1<e; i+=2){
        int c0=col[i], c1=col[i+1];
        float v0=val[i], v1=val[i+1];
        float2 x0=X2[(long)c0*32+lane];
        float2 x1=X2[(long)c1*32+lane];
        A.x+=v0*x0.x; A.y+=v0*x0.y;
        B.x+=v1*x1.x; B.y+=v1*x1.y;
    }
    if(i<e){
        int c=col[i]; float v=val[i];
        float2 x=X2[(long)c*32+lane];
        A.x+=v*x.x; A.y+=v*x.y;
    }
    A.x=fmaxf(A.x+B.x,0.f); A.y=fmaxf(A.y+B.y,0.f);
    ((float2*)Y)[(long)w*32+lane]=A;
}

__global__ void k_spmm16(const int* __restrict__ rp, const int* __restrict__ col,
                         const float* __restrict__ val, const float* __restrict__ X,
                         float* __restrict__ Y){
    int row=blockIdx.x*16+threadIdx.y; int j=threadIdx.x;
    if(row>=Nn) return;
    float acc=0.f;
    for(int i=rp[row];i<rp[row+1];i++) acc+=val[i]*X[(long)col[i]*16+j];
    Y[(long)row*16+j]=acc;
}

__global__ void k_spmm16f(const int* __restrict__ rp1, const int* __restrict__ col1,
                          const float* __restrict__ val1,
                          const int* __restrict__ rp2, const int* __restrict__ col2,
                          const float* __restrict__ val2,
                          const float* __restrict__ b1, const float* __restrict__ b2,
                          const float* __restrict__ X, float* __restrict__ Y){
    int row=blockIdx.x*16+threadIdx.y; int j=threadIdx.x;
    if(row>=Nn) return;
    float a1=0.f, a2=0.f;
    for(int i=rp1[row];i<rp1[row+1];i++) a1+=val1[i]*X[(long)col1[i]*16+j];
    for(int i=rp2[row];i<rp2[row+1];i++) a2+=val2[i]*X[(long)col2[i]*16+j];
    Y[(long)row*16+j]=b1[row]*a1+b2[row]*a2;
}

// ------------- gen_view helpers -------------
__global__ void k_nodedot(const float* __restrict__ emb, const float* __restrict__ Wm,
                          float* __restrict__ dr, float* __restrict__ dc){
    int node=(blockIdx.x*blockDim.x+threadIdx.x)>>5; if(node>=Nn) return;
    int lane=threadIdx.x&31;
    float2 e=((const float2*)(emb+(long)node*64))[lane];
    float2 wr=((const float2*)Wm)[lane];
    float2 wc=((const float2*)Wm)[lane+32];
    float a=e.x*wr.x+e.y*wr.y;
    float b=e.x*wc.x+e.y*wc.y;
#pragma unroll
    for(int o=16;o;o>>=1){
        a+=__shfl_xor_sync(0xffffffffu,a,o);
        b+=__shfl_xor_sync(0xffffffffu,b,o);
    }
    if(lane==0){dr[node]=a; dc[node]=b;}
}

__global__ void k_gensoftmax(const int* __restrict__ rp, const int* __restrict__ col,
                             float* __restrict__ val, const float* __restrict__ dr,
                             const float* __restrict__ dc, const float* __restrict__ bm,
                             float com){
    int row=(blockIdx.x*blockDim.x+threadIdx.x)>>5; if(row>=Nn) return;
    int lane=threadIdx.x&31;
    int s=rp[row], e=rp[row+1];
    if(s==e) return;
    float base=dr[row]+bm[0];
    float m=-3.4e38f;
    for(int i=s+lane;i<e;i+=32) m=fmaxf(m, base+dc[col[i]]);
#pragma unroll
    for(int o=16;o;o>>=1) m=fmaxf(m,__shfl_xor_sync(0xffffffffu,m,o));
    float ss=0.f;
    for(int i=s+lane;i<e;i+=32) ss+=__expf(base+dc[col[i]]-m);
#pragma unroll
    for(int o=16;o;o>>=1) ss+=__shfl_xor_sync(0xffffffffu,ss,o);
    float inv=com/ss;
    for(int i=s+lane;i<e;i+=32) val[i]+=__expf(base+dc[col[i]]-m)*inv;
}

// ------------- 16-class softmax + logits + top2 weight -------------
__global__ void k_softmax_w(const float* __restrict__ C, float* __restrict__ lg,
                            float* __restrict__ w){
    int node=blockIdx.x*blockDim.x+threadIdx.x; if(node>=Nn) return;
    float x[16];
    const float4* p=(const float4*)(C+(long)node*16);
#pragma unroll
    for(int q=0;q<4;q++){float4 t=p[q]; x[4*q]=t.x; x[4*q+1]=t.y; x[4*q+2]=t.z; x[4*q+3]=t.w;}
    float m=x[0];
#pragma unroll
    for(int j=1;j<16;j++) m=fmaxf(m,x[j]);
    float s=0.f;
#pragma unroll
    for(int j=0;j<16;j++){x[j]=__expf(x[j]-m); s+=x[j];}
    float inv=1.f/s;
    float fir=0.f, sec=0.f;
#pragma unroll
    for(int j=0;j<16;j++){
        float pr=x[j]*inv;
        lg[(long)node*16+j]=logf(pr+EPSF);
        if(pr>fir){sec=fir; fir=pr;} else if(pr>sec) sec=pr;
    }
    if(w) w[node]=sqrtf((fir+EPSF)*(fir-sec+EPSF));
}

__global__ void k_bal(const float* __restrict__ w1, const float* __restrict__ w2,
                      float* __restrict__ b1, float* __restrict__ b2){
    int i=blockIdx.x*blockDim.x+threadIdx.x; if(i>=Nn) return;
    float a=w1[i], b=w2[i], inv=1.f/(a+b);
    b1[i]=a*inv; b2[i]=b*inv;
}

__global__ void k_normrows(float* __restrict__ E, int nrows){
    int row=(blockIdx.x*blockDim.x+threadIdx.x)>>5; if(row>=nrows) return;
    int lane=threadIdx.x&31;
    float4* p=(float4*)(E+(long)row*128);
    float4 v=p[lane];
    float s=v.x*v.x+v.y*v.y+v.z*v.z+v.w*v.w;
#pragma unroll
    for(int o=16;o;o>>=1) s+=__shfl_xor_sync(0xffffffffu,s,o);
    float inv=rsqrtf(s);
    v.x*=inv; v.y*=inv; v.z*=inv; v.w*=inv;
    p[lane]=v;
}

// ------------- contrast pair (tf32): exp(2*z1.z2) row/col sums + diag -------------
__global__ __launch_bounds__(256,2) void k_contrast(
        const float* __restrict__ z1, const float* __restrict__ z2,
        float* __restrict__ rs, float* __restrict__ cs, float* __restrict__ dg){
    __shared__ __align__(16) u32 sA[128*SAP];
    __shared__ __align__(16) u32 sB[32*SBP];
    __shared__ float sRS[128], sCS[128];
    int tid=threadIdx.x, lane=tid&31, ww=tid>>5, wr=ww>>2, wc=ww&3;
    int br=blockIdx.y*128, bc=blockIdx.x*128;
    float acc[4][4][4];
#pragma unroll
    for(int i=0;i<4;i++)
#pragma unroll
    for(int j=0;j<4;j++)
#pragma unroll
    for(int q=0;q<4;q++) acc[i][j][q]=0.f;
    int ra=tid>>3, fa=(tid&7)<<2;

    for(int k0=0;k0<128;k0+=32){
        // A rows: z1 tile [128][32]
#pragma unroll
        for(int h=0;h<4;h++){
            int r=ra+h*32;
            float4 v=*(const float4*)(z1+(long)(br+r)*128+k0+fa);
            uint4 t=make_uint4(f2tf(v.x),f2tf(v.y),f2tf(v.z),f2tf(v.w));
            *(uint4*)&sA[r*SAP+fa]=t;
        }
        // B: sB[k][n] = z2[bc+n][k0+k]  (transposed scatter)
#pragma unroll
        for(int h=0;h<4;h++){
            int c=ra+h*32;
            float4 v=*(const float4*)(z2+(long)(bc+c)*128+k0+fa);
            sB[(fa+0)*SBP+c]=f2tf(v.x); sB[(fa+1)*SBP+c]=f2tf(v.y);
            sB[(fa+2)*SBP+c]=f2tf(v.z); sB[(fa+3)*SBP+c]=f2tf(v.w);
        }
        __syncthreads();
        TF32_COMPUTE_CHUNK();
        __syncthreads();
    }
    if(tid<128){sRS[tid]=0.f; sCS[tid]=0.f;}
    __syncthreads();
    float cs0[4]={0,0,0,0}, cs1[4]={0,0,0,0};
#pragma unroll
    for(int mf=0;mf<4;mf++){
        float r0sum=0.f, r1sum=0.f;
        int r0g=br+wr*64+mf*16+(lane>>2);
        int r1g=r0g+8;
#pragma unroll
        for(int nf=0;nf<4;nf++){
            float e0=__expf(2.f*acc[mf][nf][0]);
            float e1=__expf(2.f*acc[mf][nf][1]);
            float e2=__expf(2.f*acc[mf][nf][2]);
            float e3=__expf(2.f*acc[mf][nf][3]);
            int cg_=bc+wc*32+nf*8+(lane&3)*2;
            if(r0g==cg_)   dg[r0g]=e0;
            if(r0g==cg_+1) dg[r0g]=e1;
            if(r1g==cg_)   dg[r1g]=e2;
            if(r1g==cg_+1) dg[r1g]=e3;
            r0sum+=e0+e1; r1sum+=e2+e3;
            cs0[nf]+=e0+e2; cs1[nf]+=e1+e3;
        }
        r0sum+=__shfl_xor_sync(0xffffffffu,r0sum,1);
        r0sum+=__shfl_xor_sync(0xffffffffu,r0sum,2);
        r1sum+=__shfl_xor_sync(0xffffffffu,r1sum,1);
        r1sum+=__shfl_xor_sync(0xffffffffu,r1sum,2);
        if((lane&3)==0){
            atomicAdd(&sRS[wr*64+mf*16+(lane>>2)], r0sum);
            atomicAdd(&sRS[wr*64+mf*16+(lane>>2)+8], r1sum);
        }
    }
#pragma unroll
    for(int nf=0;nf<4;nf++){
#pragma unroll
        for(int o=4;o<32;o<<=1){
            cs0[nf]+=__shfl_xor_sync(0xffffffffu,cs0[nf],o);
            cs1[nf]+=__shfl_xor_sync(0xffffffffu,cs1[nf],o);
        }
        if(lane<4){
            atomicAdd(&sCS[wc*32+nf*8+lane*2],   cs0[nf]);
            atomicAdd(&sCS[wc*32+nf*8+lane*2+1], cs1[nf]);
        }
    }
    __syncthreads();
    if(tid<128){atomicAdd(&rs[br+tid], sRS[tid]); atomicAdd(&cs[bc+tid], sCS[tid]);}
}

__global__ void k_creduce3(const float* __restrict__ RS, const float* __restrict__ CS,
                           const float* __restrict__ DG, float* out){
    __shared__ float sh[1024];
    int pair=blockIdx.x;
    const float* rs=RS+(long)pair*Bb;
    const float* cs=CS+(long)pair*Bb;
    const float* dg=DG+(long)pair*Bb;
    int tid=threadIdx.x;
    float a=0.f;
    for(int i=tid;i<Bb;i+=1024){
        a+=-logf(dg[i]/(rs[i]+EPSF)+EPSF);
        a+=-logf(dg[i]/(cs[i]+EPSF)+EPSF);
    }
    sh[tid]=a; __syncthreads();
    for(int d=512;d;d>>=1){ if(tid<d) sh[tid]+=sh[tid+d]; __syncthreads(); }
    if(tid==0) out[pair]=0.5f*sh[0]/(float)Bb;
}

// ------------- host -------------
#define GSA(var) ([]{ void* _p; cudaGetSymbolAddress(&_p, var); return _p; }())

extern "C" void kernel_launch(void* const* d_in, const int* in_sizes, int n_in,
                              void* d_out, int out_size){
    const float* feat  =(const float*)d_in[0];
    const int*   i1    =(const int*)  d_in[1];
    const float* v1    =(const float*)d_in[2];
    const int*   i2    =(const int*)  d_in[3];
    const float* v2    =(const float*)d_in[4];
    const int*   bidx  =(const int*)  d_in[5];
    const float* Wgen1 =(const float*)d_in[6];
    const float* Wm1   =(const float*)d_in[7];
    const float* bm1   =(const float*)d_in[8];
    const float* Wgen2 =(const float*)d_in[9];
    const float* Wm2   =(const float*)d_in[10];
    const float* bm2   =(const float*)d_in[11];
    const float* W1v1  =(const float*)d_in[12];
    const float* W2v1  =(const float*)d_in[13];
    const float* W1v2  =(const float*)d_in[14];
    const float* W2v2  =(const float*)d_in[15];
    const float* W1v   =(const float*)d_in[16];
    const float* W2v   =(const float*)d_in[17];
    const float* Wg    =(const float*)d_in[18];
    const float* Wg1   =(const float*)d_in[19];
    const float* Wg2   =(const float*)d_in[20];
    const float* Wp1   =(const float*)d_in[21];
    const float* bp1   =(const float*)d_in[22];
    const float* Wp2   =(const float*)d_in[23];
    const float* bp2   =(const float*)d_in[24];
    float* out=(float*)d_out;

    float* Wp=(float*)GSA(g_Wp);
    float* X64a=(float*)GSA(g_X64a); float* X64b=(float*)GSA(g_X64b);
    float* XC1=(float*)GSA(g_XC1); float* XC2=(float*)GSA(g_XC2); float* XCf=(float*)GSA(g_XCf);
    float* XG=(float*)GSA(g_XG); float* XG1=(float*)GSA(g_XG1); float* XG2=(float*)GSA(g_XG2);
    float* Ha=(float*)GSA(g_Ha); float* Hb=(float*)GSA(g_Hb);
    float* emba=(float*)GSA(g_emba); float* embb=(float*)GSA(g_embb);
    float* S16a=(float*)GSA(g_S16a); float* S16b=(float*)GSA(g_S16b);
    float* C16a=(float*)GSA(g_C16a); float* C16b=(float*)GSA(g_C16b);
    float* dra=(float*)GSA(g_dra), *dca=(float*)GSA(g_dca);
    float* drb=(float*)GSA(g_drb), *dcb=(float*)GSA(g_dcb);
    float* w1=(float*)GSA(g_w1), *w2=(float*)GSA(g_w2);
    float* b1=(float*)GSA(g_b1), *b2=(float*)GSA(g_b2);
    int* cnt1=(int*)GSA(g_cnt1), *cnt1b=(int*)GSA(g_cnt1b);
    int* cnt2=(int*)GSA(g_cnt2), *cnt2b=(int*)GSA(g_cnt2b);
    int* cur1d=(int*)GSA(g_cur1d), *cur2d=(int*)GSA(g_cur2d);
    int* cur1s=(int*)GSA(g_cur1s), *cur2s=(int*)GSA(g_cur2s);
    int* rp1d=(int*)GSA(g_rp1d), *rp2d=(int*)GSA(g_rp2d);
    int* rp1s=(int*)GSA(g_rp1s), *rp2s=(int*)GSA(g_rp2s);
    int* col1d=(int*)GSA(g_col1d);   float* val1d=(float*)GSA(g_val1d);
    int* col2d=(int*)GSA(g_col2d);   float* val2d=(float*)GSA(g_val2d);
    int* col1s=(int*)GSA(g_col1s);   float* val1s=(float*)GSA(g_val1s);
    int* col2s=(int*)GSA(g_col2s);   float* val2s=(float*)GSA(g_val2s);
    float* Z=(float*)GSA(g_Z), *T=(float*)GSA(g_T), *E=(float*)GSA(g_E);
    float* RS=(float*)GSA(g_RS), *CS=(float*)GSA(g_CS), *DG=(float*)GSA(g_DG);

    float* E0=E;
    float* E1=E+(long)Bb*128;
    float* E2=E+(long)2*Bb*128;

    const int TB=256;
    int gN  =(Nn+TB-1)/TB;
    int gE  =(Ee+TB-1)/TB;
    int gW  =(Nn*32+TB-1)/TB;
    int gWB =(Bb*32+TB-1)/TB;
    dim3 b16(16,16); int g16=(Nn+15)/16;
    dim3 cg(32,32);

    static cudaStream_t s1=0, s2=0, s3=0;
    static cudaEvent_t eRoot=0,eScan=0,eA=0,eB=0,eC=0,eD=0,eSym2=0,eW1=0,eW2=0,
                       eZ1=0,eZ2=0,eFg=0,eEV=0,eE12=0,eCa=0,eCb=0,eF2=0;
    if(!s1){
        cudaStreamCreateWithFlags(&s1, cudaStreamNonBlocking);
        cudaStreamCreateWithFlags(&s2, cudaStreamNonBlocking);
        cudaStreamCreateWithFlags(&s3, cudaStreamNonBlocking);
        cudaEventCreateWithFlags(&eRoot,cudaEventDisableTiming);
        cudaEventCreateWithFlags(&eScan,cudaEventDisableTiming);
        cudaEventCreateWithFlags(&eA, cudaEventDisableTiming);
        cudaEventCreateWithFlags(&eB, cudaEventDisableTiming);
        cudaEventCreateWithFlags(&eC, cudaEventDisableTiming);
        cudaEventCreateWithFlags(&eD, cudaEventDisableTiming);
        cudaEventCreateWithFlags(&eSym2,cudaEventDisableTiming);
        cudaEventCreateWithFlags(&eW1,cudaEventDisableTiming);
        cudaEventCreateWithFlags(&eW2,cudaEventDisableTiming);
        cudaEventCreateWithFlags(&eZ1,cudaEventDisableTiming);
        cudaEventCreateWithFlags(&eZ2,cudaEventDisableTiming);
        cudaEventCreateWithFlags(&eFg,cudaEventDisableTiming);
        cudaEventCreateWithFlags(&eEV,cudaEventDisableTiming);
        cudaEventCreateWithFlags(&eE12,cudaEventDisableTiming);
        cudaEventCreateWithFlags(&eCa,cudaEventDisableTiming);
        cudaEventCreateWithFlags(&eCb,cudaEventDisableTiming);
        cudaEventCreateWithFlags(&eF2,cudaEventDisableTiming);
    }

    cudaEventRecord(eRoot, 0);
    cudaStreamWaitEvent(s1, eRoot, 0);
    cudaStreamWaitEvent(s2, eRoot, 0);
    cudaStreamWaitEvent(s3, eRoot, 0);

    int gyP=(Nn+127)/128;
    // ---- stream 0: pack + sliced big GEMM, ordered by consumer need ----
    // bx map: 0=X64ab, 1=XC1, 2=XC2, 3=XCf, 4=XG, 5=XG1, 6=XG2
    k_pack<<<(256*896+TB-1)/TB,TB>>>(Wgen1,Wgen2,W1v1,W1v2,W1v,Wg,Wg1,Wg2,Wp);
    k_zero_f2<<<(3*Bb+TB-1)/TB,TB>>>(RS,CS,3*Bb);
    k_gemmP<<<dim3(1,gyP),256>>>(feat,Wp,0,X64a,X64b,XC1,XC2,XCf,XG,XG1,XG2);
    cudaEventRecord(eA, 0);   // X64a, X64b
    k_gemmP<<<dim3(2,gyP),256>>>(feat,Wp,1,X64a,X64b,XC1,XC2,XCf,XG,XG1,XG2);
    cudaEventRecord(eB, 0);   // XC1, XC2
    k_gemmP<<<dim3(2,gyP),256>>>(feat,Wp,3,X64a,X64b,XC1,XC2,XCf,XG,XG1,XG2);
    cudaEventRecord(eD, 0);   // XCf, XG
    k_gemmP<<<dim3(2,gyP),256>>>(feat,Wp,5,X64a,X64b,XC1,XC2,XCf,XG,XG1,XG2);
    cudaEventRecord(eC, 0);   // XG1, XG2

    // ---- s1: CSR build + view1 pipeline ----
    k_zero4<<<gN,TB,0,s1>>>(cnt1,cnt1b,cnt2,cnt2b,Nn);
    k_count2<<<gE,TB,0,s1>>>(i1,i2,cnt1,cnt1b,cnt2,cnt2b);
    k_scan4<<<4,1024,0,s1>>>(cnt1,rp1d,cur1d,cnt1b,rp1s,cur1s,cnt2,rp2d,cur2d,cnt2b,rp2s,cur2s);
    cudaEventRecord(eScan, s1);
    k_scatter_dir<<<gE,TB,0,s1>>>(i1,v1,cur1d,col1d,val1d);
    cudaStreamWaitEvent(s1, eA, 0);
    k_spmm64<<<gW,TB,0,s1>>>(rp1d,col1d,val1d,X64a,emba);
    k_nodedot<<<gW,TB,0,s1>>>(emba,Wm1,dra,dca);
    k_gensoftmax<<<gW,TB,0,s1>>>(rp1d,col1d,val1d,dra,dca,bm1,0.5f);
    k_scatter_sym<<<gN,TB,0,s1>>>(rp1d,col1d,val1d,cur1s,col1s,val1s);
    cudaStreamWaitEvent(s1, eB, 0);
    k_spmm128<<<gW,TB,0,s1>>>(rp1s,col1s,val1s,XC1,Ha);
    k_gemm16<<<g16,b16,0,s1>>>(Ha,W2v1,S16a,Nn);
    k_spmm16<<<g16,b16,0,s1>>>(rp1s,col1s,val1s,S16a,C16a);
    k_softmax_w<<<gN,TB,0,s1>>>(C16a,out+(long)16*Nn,w1);
    cudaEventRecord(eW1, s1);
    cudaStreamWaitEvent(s1, eC, 0);
    k_spmm128g<<<gWB,TB,0,s1>>>(bidx,rp1s,col1s,val1s,XG1,E1);
    cudaEventRecord(eZ1, s1);

    // ---- s2: view2 pipeline, then fused classifier chain ----
    cudaStreamWaitEvent(s2, eScan, 0);
    k_scatter_dir<<<gE,TB,0,s2>>>(i2,v2,cur2d,col2d,val2d);
    cudaStreamWaitEvent(s2, eA, 0);
    k_spmm64<<<gW,TB,0,s2>>>(rp2d,col2d,val2d,X64b,embb);
    k_nodedot<<<gW,TB,0,s2>>>(embb,Wm2,drb,dcb);
    k_gensoftmax<<<gW,TB,0,s2>>>(rp2d,col2d,val2d,drb,dcb,bm2,0.5f);
    k_scatter_sym<<<gN,TB,0,s2>>>(rp2d,col2d,val2d,cur2s,col2s,val2s);
    cudaEventRecord(eSym2, s2);
    cudaStreamWaitEvent(s2, eB, 0);
    k_spmm128<<<gW,TB,0,s2>>>(rp2s,col2s,val2s,XC2,Hb);
    k_gemm16<<<g16,b16,0,s2>>>(Hb,W2v2,S16b,Nn);
    k_spmm16<<<g16,b16,0,s2>>>(rp2s,col2s,val2s,S16b,C16b);
    k_softmax_w<<<gN,TB,0,s2>>>(C16b,out+(long)32*Nn,w2);
    cudaEventRecord(eW2, s2);
    cudaStreamWaitEvent(s2, eW1, 0);
    cudaStreamWaitEvent(s2, eD, 0);
    k_bal<<<gN,TB,0,s2>>>(w1,w2,b1,b2);
    k_spmm128fg<<<gWB,TB,0,s2>>>(bidx,rp1s,col1s,val1s,rp2s,col2s,val2s,b1,b2,XG,Z);
    cudaEventRecord(eFg, s2);
    k_spmm128f<<<gW,TB,0,s2>>>(rp1s,col1s,val1s,rp2s,col2s,val2s,b1,b2,XCf,Ha);
    k_gemm16<<<g16,b16,0,s2>>>(Ha,W2v,S16a,Nn);
    k_spmm16f<<<g16,b16,0,s2>>>(rp1s,col1s,val1s,rp2s,col2s,val2s,b1,b2,S16a,C16a);
    k_softmax_w<<<gN,TB,0,s2>>>(C16a,out,nullptr);
    cudaEventRecord(eF2, s2);

    // ---- s3: XG2 gather, E1/E2 projection + contrast(E1,E2) ----
    cudaStreamWaitEvent(s3, eC, 0);
    cudaStreamWaitEvent(s3, eSym2, 0);
    k_spmm128g<<<gWB,TB,0,s3>>>(bidx,rp2s,col2s,val2s,XG2,E2);
    cudaEventRecord(eZ2, s3);
    cudaStreamWaitEvent(s3, eZ1, 0);
    k_gemm128<<<dim3(1,(2*Bb+127)/128),256,0,s3>>>(E1,Wp1,bp1,T+(long)Bb*128,2*Bb,128,1);
    k_gemm128<<<dim3(1,(2*Bb+127)/128),256,0,s3>>>(T+(long)Bb*128,Wp2,bp2,E1,2*Bb,128,0);
    k_normrows<<<(2*Bb*32+TB-1)/TB,TB,0,s3>>>(E1,2*Bb);
    cudaEventRecord(eE12, s3);
    k_contrast<<<cg,256,0,s3>>>(E1,E2,RS+2*Bb,CS+2*Bb,DG+2*Bb);   // pair v1v2

    // ---- s1: EV projection + contrast(EV,E1) ----
    cudaStreamWaitEvent(s1, eFg, 0);
    k_gemm128<<<dim3(1,(Bb+127)/128),256,0,s1>>>(Z,Wp1,bp1,T,Bb,128,1);
    k_gemm128<<<dim3(1,(Bb+127)/128),256,0,s1>>>(T,Wp2,bp2,E0,Bb,128,0);
    k_normrows<<<(Bb*32+TB-1)/TB,TB,0,s1>>>(E0,Bb);
    cudaEventRecord(eEV, s1);
    cudaStreamWaitEvent(s1, eE12, 0);
    k_contrast<<<cg,256,0,s1>>>(E0,E1,RS,CS,DG);                   // pair vv1
    cudaEventRecord(eCa, s1);

    // ---- s3: contrast(EV,E2) ----
    cudaStreamWaitEvent(s3, eEV, 0);
    k_contrast<<<cg,256,0,s3>>>(E0,E2,RS+Bb,CS+Bb,DG+Bb);          // pair vv2
    cudaEventRecord(eCb, s3);

    // ---- stream 0: join all streams + final reduce ----
    cudaStreamWaitEvent(0, eCa, 0);
    cudaStreamWaitEvent(0, eCb, 0);
    cudaStreamWaitEvent(0, eF2, 0);
    k_creduce3<<<3,1024>>>(RS,CS,DG,out+(long)48*Nn);
}

// round 14
// speedup vs baseline: 1.7070x; 1.0461x over previous
#include <cuda_runtime.h>
#include <math.h>

#define Nn 30000
#define Ee 480000
#define Bb 4096
#define EPSF 1e-8f

typedef unsigned long long u64;
typedef unsigned int u32;
__device__ __forceinline__ u32 f2tf(float f){u32 u;asm("cvt.rna.tf32.f32 %0,%1;":"=r"(u):"f"(f));return u;}
__device__ __forceinline__ void mma_tf32(float* c,u32 a0,u32 a1,u32 a2,u32 a3,u32 b0,u32 b1){
    asm volatile("mma.sync.aligned.m16n8k8.row.col.f32.tf32.tf32.f32 "
        "{%0,%1,%2,%3},{%4,%5,%6,%7},{%8,%9},{%0,%1,%2,%3};"
        : "+f"(c[0]),"+f"(c[1]),"+f"(c[2]),"+f"(c[3])
        : "r"(a0),"r"(a1),"r"(a2),"r"(a3),"r"(b0),"r"(b1));
}

#define SAP 36     // A smem row stride: bank-exact
#define SBP 136    // B smem row stride: bank-exact

// ------------- device scratch -------------
__device__ float g_Wp[256*896];
__device__ float g_X64a[Nn*64], g_X64b[Nn*64];
__device__ float g_XC1[Nn*128], g_XC2[Nn*128], g_XCf[Nn*128];
__device__ float g_XG[Nn*128], g_XG1[Nn*128], g_XG2[Nn*128];
__device__ float g_Ha[Nn*128], g_Hb[Nn*128];
__device__ float g_emba[Nn*64], g_embb[Nn*64];
__device__ float g_S16a[Nn*16], g_S16b[Nn*16];
__device__ float g_C16a[Nn*16], g_C16b[Nn*16];
__device__ float g_dra[Nn], g_dca[Nn], g_drb[Nn], g_dcb[Nn];
__device__ float g_w1[Nn], g_w2[Nn], g_b1[Nn], g_b2[Nn];
__device__ int   g_cnt1[Nn], g_cnt1b[Nn], g_cnt2[Nn], g_cnt2b[Nn];
__device__ int   g_cur1d[Nn], g_cur2d[Nn], g_cur1s[Nn], g_cur2s[Nn];
__device__ int   g_rp1d[Nn+1], g_rp2d[Nn+1], g_rp1s[Nn+1], g_rp2s[Nn+1];
__device__ int   g_col1d[Ee];   __device__ float g_val1d[Ee];   __device__ int g_row1d[Ee];
__device__ int   g_col2d[Ee];   __device__ float g_val2d[Ee];   __device__ int g_row2d[Ee];
__device__ int   g_col1s[2*Ee]; __device__ float g_val1s[2*Ee];
__device__ int   g_col2s[2*Ee]; __device__ float g_val2s[2*Ee];
__device__ float g_Z[3*Bb*128], g_T[3*Bb*128], g_E[3*Bb*128];
__device__ float g_RS[3*Bb], g_CS[3*Bb], g_DG[3*Bb];

// ------------- pack weights -------------
__global__ void k_pack(const float* __restrict__ wg1, const float* __restrict__ wg2,
                       const float* __restrict__ a, const float* __restrict__ b,
                       const float* __restrict__ c, const float* __restrict__ d,
                       const float* __restrict__ e, const float* __restrict__ f,
                       float* __restrict__ Wp){
    int i=blockIdx.x*blockDim.x+threadIdx.x; if(i>=256*896) return;
    int row=i/896, col=i%896;
    float v;
    if(col<64) v=wg1[row*64+col];
    else if(col<128) v=wg2[row*64+col-64];
    else{
        int blk=(col-128)>>7, lc=(col-128)&127;
        const float* s;
        switch(blk){case 0:s=a;break;case 1:s=b;break;case 2:s=c;break;
                    case 3:s=d;break;case 4:s=e;break;default:s=f;break;}
        v=s[row*128+lc];
    }
    Wp[i]=v;
}

// ------------- small utils -------------
__global__ void k_zero4(int* a,int* b,int* c,int* d,int n){
    int i=blockIdx.x*blockDim.x+threadIdx.x; if(i<n){a[i]=0;b[i]=0;c[i]=0;d[i]=0;} }
__global__ void k_zero_f2(float* a, float* b, int n){
    int i=blockIdx.x*blockDim.x+threadIdx.x; if(i<n){a[i]=0.f;b[i]=0.f;} }

__global__ void k_count2(const int* __restrict__ ind1, const int* __restrict__ ind2,
                         int* cd1, int* cs1, int* cd2, int* cs2){
    int e=blockIdx.x*blockDim.x+threadIdx.x; if(e>=Ee) return;
    int r1=ind1[e], c1=ind1[Ee+e];
    atomicAdd(&cd1[r1],1); atomicAdd(&cs1[r1],1); atomicAdd(&cs1[c1],1);
    int r2=ind2[e], c2=ind2[Ee+e];
    atomicAdd(&cd2[r2],1); atomicAdd(&cs2[r2],1); atomicAdd(&cs2[c2],1);
}

// 4 independent scans; register-staged, fully unrolled (CHUNK=30)
__global__ void k_scan4(const int* c0,int* r0,int* u0,const int* c1,int* r1,int* u1,
                        const int* c2,int* r2,int* u2,const int* c3,int* r3,int* u3){
    const int* cnt; int* rp; int* cu;
    switch(blockIdx.x){
        case 0: cnt=c0; rp=r0; cu=u0; break;
        case 1: cnt=c1; rp=r1; cu=u1; break;
        case 2: cnt=c2; rp=r2; cu=u2; break;
        default:cnt=c3; rp=r3; cu=u3; break;
    }
    const int CH=30;
    int tid=threadIdx.x;
    int s=tid*CH;
    int vloc[CH];
#pragma unroll
    for(int i=0;i<CH;i++){int idx=s+i; vloc[i]=(idx<Nn)?cnt[idx]:0;}
    int sum=0;
#pragma unroll
    for(int i=0;i<CH;i++) sum+=vloc[i];
    __shared__ int wsum[32];
    int lane=tid&31, wid=tid>>5;
    int v=sum;
#pragma unroll
    for(int o=1;o<32;o<<=1){int t=__shfl_up_sync(0xffffffffu,v,o); if(lane>=o) v+=t;}
    if(lane==31) wsum[wid]=v;
    __syncthreads();
    if(wid==0){
        int w=wsum[lane];
#pragma unroll
        for(int o=1;o<32;o<<=1){int t=__shfl_up_sync(0xffffffffu,w,o); if(lane>=o) w+=t;}
        wsum[lane]=w;
    }
    __syncthreads();
    int excl=v-sum+(wid?wsum[wid-1]:0);
    int run=excl;
#pragma unroll
    for(int i=0;i<CH;i++){
        int idx=s+i;
        if(idx<Nn){ rp[idx]=run; cu[idx]=run; run+=vloc[i]; }
    }
    if(tid==1023) rp[Nn]=run;
}

__global__ void k_scatter_dir(const int* __restrict__ ind, const float* __restrict__ vals,
                              int* cur, int* __restrict__ col, float* __restrict__ val,
                              int* __restrict__ rowid){
    int e=blockIdx.x*blockDim.x+threadIdx.x; if(e>=Ee) return;
    int r=ind[e], c=ind[Ee+e];
    int p=atomicAdd(&cur[r],1);
    col[p]=c; val[p]=vals[e]; rowid[p]=r;
}

// edge-parallel symmetrize: each directed slot emits both directions
__global__ void k_scatter_sym_e(const int* __restrict__ rowid, const int* __restrict__ cold,
                                const float* __restrict__ vald, int* cur,
                                int* __restrict__ cols, float* __restrict__ vals){
    int e=blockIdx.x*blockDim.x+threadIdx.x; if(e>=Ee) return;
    int r=rowid[e], c=cold[e]; float v=vald[e];
    int p=atomicAdd(&cur[r],1); cols[p]=c; vals[p]=v;
    int q=atomicAdd(&cur[c],1); cols[q]=r; vals[q]=v;
}

// ======== tf32 MMA block: 128x128 tile, 8 warps (2x4), warp tile 64x32 ========
#define TF32_COMPUTE_CHUNK() do{ \
    _Pragma("unroll") \
    for(int k8=0;k8<4;k8++){ \
        int kb=k8*8; \
        u32 bf[4][2]; \
        _Pragma("unroll") \
        for(int nf=0;nf<4;nf++){ \
            int nb=wc*32+nf*8+(lane>>2); \
            bf[nf][0]=sB[(kb+(lane&3))*SBP+nb]; \
            bf[nf][1]=sB[(kb+(lane&3)+4)*SBP+nb]; \
        } \
        _Pragma("unroll") \
        for(int mf=0;mf<4;mf++){ \
            int rb=wr*64+mf*16+(lane>>2); \
            u32 a0=sA[rb*SAP+kb+(lane&3)]; \
            u32 a1=sA[(rb+8)*SAP+kb+(lane&3)]; \
            u32 a2=sA[rb*SAP+kb+(lane&3)+4]; \
            u32 a3=sA[(rb+8)*SAP+kb+(lane&3)+4]; \
            _Pragma("unroll") \
            for(int nf=0;nf<4;nf++) mma_tf32(acc[mf][nf],a0,a1,a2,a3,bf[nf][0],bf[nf][1]); \
        } \
    } \
}while(0)

// ------------- packed GEMM slice (tf32): feat[30000x256] @ Wp[:,128*bx..] -------------
__global__ __launch_bounds__(256,2) void k_gemmP(
        const float* __restrict__ A, const float* __restrict__ Wp, int bxoff,
        float* __restrict__ e1, float* __restrict__ e2,
        float* __restrict__ x0, float* __restrict__ x1, float* __restrict__ x2,
        float* __restrict__ x3, float* __restrict__ x4, float* __restrict__ x5){
    __shared__ __align__(16) u32 sA[128*SAP];
    __shared__ __align__(16) u32 sB[32*SBP];
    int tid=threadIdx.x, lane=tid&31, ww=tid>>5, wr=ww>>2, wc=ww&3;
    int bx=blockIdx.x+bxoff;
    int br=blockIdx.y*128;
    float acc[4][4][4];
#pragma unroll
    for(int i=0;i<4;i++)
#pragma unroll
    for(int j=0;j<4;j++)
#pragma unroll
    for(int q=0;q<4;q++) acc[i][j][q]=0.f;
    int ra=tid>>3, fa=(tid&7)<<2;
    int kwB=tid>>5, cw=(tid&31)<<2;

    for(int k0=0;k0<256;k0+=32){
#pragma unroll
        for(int h=0;h<4;h++){
            int r=ra+h*32, gr=br+r;
            float4 v=make_float4(0.f,0.f,0.f,0.f);
            if(gr<Nn) v=*(const float4*)(A+(long)gr*256+k0+fa);
            uint4 t=make_uint4(f2tf(v.x),f2tf(v.y),f2tf(v.z),f2tf(v.w));
            *(uint4*)&sA[r*SAP+fa]=t;
        }
#pragma unroll
        for(int h=0;h<4;h++){
            int kk=kwB+h*8;
            float4 v=*(const float4*)(Wp+(long)(k0+kk)*896+bx*128+cw);
            uint4 t=make_uint4(f2tf(v.x),f2tf(v.y),f2tf(v.z),f2tf(v.w));
            *(uint4*)&sB[kk*SBP+cw]=t;
        }
        __syncthreads();
        TF32_COMPUTE_CHUNK();
        __syncthreads();
    }
    float* dst; int w; int cb;
    if(bx==0){
        if(wc<2){ dst=e1; w=64; cb=wc*32; } else { dst=e2; w=64; cb=(wc-2)*32; }
    } else {
        switch(bx-1){case 0:dst=x0;break;case 1:dst=x1;break;case 2:dst=x2;break;
                     case 3:dst=x3;break;case 4:dst=x4;break;default:dst=x5;break;}
        w=128; cb=wc*32;
    }
#pragma unroll
    for(int mf=0;mf<4;mf++){
        int r0=br+wr*64+mf*16+(lane>>2);
        int r1=r0+8;
#pragma unroll
        for(int nf=0;nf<4;nf++){
            int c=cb+nf*8+(lane&3)*2;
            if(r0<Nn) *(float2*)&dst[(long)r0*w+c]=make_float2(acc[mf][nf][0],acc[mf][nf][1]);
            if(r1<Nn) *(float2*)&dst[(long)r1*w+c]=make_float2(acc[mf][nf][2],acc[mf][nf][3]);
        }
    }
}

// ------------- projection GEMM (tf32): C[n,128]=A[n,128]@W[128,128] (+bias, act) -------
// n must be a multiple of 128 (it is: Bb, 2Bb, 3Bb).
__global__ __launch_bounds__(256,2) void k_gemm128(
        const float* __restrict__ A, const float* __restrict__ W,
        const float* __restrict__ bias, float* __restrict__ C,
        int n, int act){
    __shared__ __align__(16) u32 sA[128*SAP];
    __shared__ __align__(16) u32 sB[32*SBP];
    int tid=threadIdx.x, lane=tid&31, ww=tid>>5, wr=ww>>2, wc=ww&3;
    int br=blockIdx.y*128;
    float acc[4][4][4];
#pragma unroll
    for(int i=0;i<4;i++)
#pragma unroll
    for(int j=0;j<4;j++)
#pragma unroll
    for(int q=0;q<4;q++) acc[i][j][q]=0.f;
    int ra=tid>>3, fa=(tid&7)<<2;
    int kwB=tid>>5, cw=(tid&31)<<2;

    for(int k0=0;k0<128;k0+=32){
#pragma unroll
        for(int h=0;h<4;h++){
            int r=ra+h*32;
            float4 v=*(const float4*)(A+(long)(br+r)*128+k0+fa);
            uint4 t=make_uint4(f2tf(v.x),f2tf(v.y),f2tf(v.z),f2tf(v.w));
            *(uint4*)&sA[r*SAP+fa]=t;
        }
#pragma unroll
        for(int h=0;h<4;h++){
            int kk=kwB+h*8;
            float4 v=*(const float4*)(W+(long)(k0+kk)*128+cw);
            uint4 t=make_uint4(f2tf(v.x),f2tf(v.y),f2tf(v.z),f2tf(v.w));
            *(uint4*)&sB[kk*SBP+cw]=t;
        }
        __syncthreads();
        TF32_COMPUTE_CHUNK();
        __syncthreads();
    }
#pragma unroll
    for(int mf=0;mf<4;mf++){
        int r0=br+wr*64+mf*16+(lane>>2);
        int r1=r0+8;
#pragma unroll
        for(int nf=0;nf<4;nf++){
            int c=wc*32+nf*8+(lane&3)*2;
            float b0=bias?bias[c]:0.f, b1=bias?bias[c+1]:0.f;
            float v0=acc[mf][nf][0]+b0, v1=acc[mf][nf][1]+b1;
            float v2=acc[mf][nf][2]+b0, v3=acc[mf][nf][3]+b1;
            if(act==1){
                v0=(v0>0.f)?v0:expm1f(v0); v1=(v1>0.f)?v1:expm1f(v1);
                v2=(v2>0.f)?v2:expm1f(v2); v3=(v3>0.f)?v3:expm1f(v3);
            }
            *(float2*)&C[(long)r0*128+c]=make_float2(v0,v1);
            *(float2*)&C[(long)r1*128+c]=make_float2(v2,v3);
        }
    }
}

// ------------- GEMM M=16 (W2 in smem) -------------
__global__ void k_gemm16(const float* __restrict__ H, const float* __restrict__ W2,
                         float* __restrict__ C, int n){
    __shared__ float sW[128*16];
    int tid=threadIdx.y*16+threadIdx.x;
#pragma unroll
    for(int q=0;q<2;q++) ((float4*)sW)[tid*2+q]=((const float4*)W2)[tid*2+q];
    __syncthreads();
    int r=blockIdx.x*16+threadIdx.y, j=threadIdx.x;
    if(r>=n) return;
    const float4* H4=(const float4*)(H+(long)r*128);
    float acc=0.f;
#pragma unroll
    for(int k4=0;k4<32;k4++){
        float4 h=H4[k4];
        acc+=h.x*sW[(k4*4+0)*16+j];
        acc+=h.y*sW[(k4*4+1)*16+j];
        acc+=h.z*sW[(k4*4+2)*16+j];
        acc+=h.w*sW[(k4*4+3)*16+j];
    }
    C[(long)r*16+j]=acc;
}

// ------------- SpMM (warp per row, 2-way unrolled) -------------
__device__ __forceinline__ float4 spmm_row128(const int* __restrict__ rp,
        const int* __restrict__ col, const float* __restrict__ val,
        const float4* __restrict__ X4, int w, int lane){
    int s=rp[w], e=rp[w+1];
    float4 A=make_float4(0.f,0.f,0.f,0.f), B=A;
    int i=s;
    for(; i+1<e; i+=2){
        int c0=col[i], c1=col[i+1];
        float v0=val[i], v1=val[i+1];
        float4 x0=X4[(long)c0*32+lane];
        float4 x1=X4[(long)c1*32+lane];
        A.x+=v0*x0.x; A.y+=v0*x0.y; A.z+=v0*x0.z; A.w+=v0*x0.w;
        B.x+=v1*x1.x; B.y+=v1*x1.y; B.z+=v1*x1.z; B.w+=v1*x1.w;
    }
    if(i<e){
        int c=col[i]; float v=val[i];
        float4 x=X4[(long)c*32+lane];
        A.x+=v*x.x; A.y+=v*x.y; A.z+=v*x.z; A.w+=v*x.w;
    }
    A.x+=B.x; A.y+=B.y; A.z+=B.z; A.w+=B.w;
    return A;
}

__global__ void k_spmm128(const int* __restrict__ rp, const int* __restrict__ col,
                          const float* __restrict__ val, const float* __restrict__ X,
                          float* __restrict__ Y){
    int w=(blockIdx.x*blockDim.x+threadIdx.x)>>5; if(w>=Nn) return;
    int lane=threadIdx.x&31;
    float4 a=spmm_row128(rp,col,val,(const float4*)X,w,lane);
    a.x=fmaxf(a.x,0.f); a.y=fmaxf(a.y,0.f); a.z=fmaxf(a.z,0.f); a.w=fmaxf(a.w,0.f);
    ((float4*)Y)[(long)w*32+lane]=a;
}

__global__ void k_spmm128f(const int* __restrict__ rp1, const int* __restrict__ col1,
                           const float* __restrict__ val1,
                           const int* __restrict__ rp2, const int* __restrict__ col2,
                           const float* __restrict__ val2,
                           const float* __restrict__ b1, const float* __restrict__ b2,
                           const float* __restrict__ X, float* __restrict__ Y){
    int w=(blockIdx.x*blockDim.x+threadIdx.x)>>5; if(w>=Nn) return;
    int lane=threadIdx.x&31;
    float4 a1=spmm_row128(rp1,col1,val1,(const float4*)X,w,lane);
    float4 a2=spmm_row128(rp2,col2,val2,(const float4*)X,w,lane);
    float f1=b1[w], f2=b2[w];
    float4 r;
    r.x=fmaxf(f1*a1.x+f2*a2.x,0.f); r.y=fmaxf(f1*a1.y+f2*a2.y,0.f);
    r.z=fmaxf(f1*a1.z+f2*a2.z,0.f); r.w=fmaxf(f1*a1.w+f2*a2.w,0.f);
    ((float4*)Y)[(long)w*32+lane]=r;
}

__global__ void k_spmm128g(const int* __restrict__ bidx,
                           const int* __restrict__ rp, const int* __restrict__ col,
                           const float* __restrict__ val, const float* __restrict__ X,
                           float* __restrict__ Z){
    int w=(blockIdx.x*blockDim.x+threadIdx.x)>>5; if(w>=Bb) return;
    int lane=threadIdx.x&31;
    int row=bidx[w];
    float4 a=spmm_row128(rp,col,val,(const float4*)X,row,lane);
    a.x=fmaxf(a.x,0.f); a.y=fmaxf(a.y,0.f); a.z=fmaxf(a.z,0.f); a.w=fmaxf(a.w,0.f);
    ((float4*)Z)[(long)w*32+lane]=a;
}

__global__ void k_spmm128fg(const int* __restrict__ bidx,
                            const int* __restrict__ rp1, const int* __restrict__ col1,
                            const float* __restrict__ val1,
                            const int* __restrict__ rp2, const int* __restrict__ col2,
                            const float* __restrict__ val2,
                            const float* __restrict__ b1, const float* __restrict__ b2,
                            const float* __restrict__ X, float* __restrict__ Z){
    int w=(blockIdx.x*blockDim.x+threadIdx.x)>>5; if(w>=Bb) return;
    int lane=threadIdx.x&31;
    int row=bidx[w];
    float4 a1=spmm_row128(rp1,col1,val1,(const float4*)X,row,lane);
    float4 a2=spmm_row128(rp2,col2,val2,(const float4*)X,row,lane);
    float f1=b1[row], f2=b2[row];
    float4 r;
    r.x=fmaxf(f1*a1.x+f2*a2.x,0.f); r.y=fmaxf(f1*a1.y+f2*a2.y,0.f);
    r.z=fmaxf(f1*a1.z+f2*a2.z,0.f); r.w=fmaxf(f1*a1.w+f2*a2.w,0.f);
    ((float4*)Z)[(long)w*32+lane]=r;
}

__global__ void k_spmm64(const int* __restrict__ rp, const int* __restrict__ col,
                         const float* __restrict__ val, const float* __restrict__ X,
                         float* __restrict__ Y){
    int w=(blockIdx.x*blockDim.x+threadIdx.x)>>5; if(w>=Nn) return;
    int lane=threadIdx.x&31;
    const float2* X2=(const float2*)X;
    int s=rp[w], e=rp[w+1];
    float2 A=make_float2(0.f,0.f), B=A;
    int i=s;
    for(; i+1<e; i+=2){
        int c0=col[i], c1=col[i+1];
        float v0=val[i], v1=val[i+1];
        float2 x0=X2[(long)c0*32+lane];
        float2 x1=X2[(long)c1*32+lane];
        A.x+=v0*x0.x; A.y+=v0*x0.y;
        B.x+=v1*x1.x; B.y+=v1*x1.y;
    }
    if(i<e){
        int c=col[i]; float v=val[i];
        float2 x=X2[(long)c*32+lane];
        A.x+=v*x.x; A.y+=v*x.y;
    }
    A.x=fmaxf(A.x+B.x,0.f); A.y=fmaxf(A.y+B.y,0.f);
    ((float2*)Y)[(long)w*32+lane]=A;
}

__global__ void k_spmm16(const int* __restrict__ rp, const int* __restrict__ col,
                         const float* __restrict__ val, const float* __restrict__ X,
                         float* __restrict__ Y){
    int row=blockIdx.x*16+threadIdx.y; int j=threadIdx.x;
    if(row>=Nn) return;
    float acc=0.f;
    for(int i=rp[row];i<rp[row+1];i++) acc+=val[i]*X[(long)col[i]*16+j];
    Y[(long)row*16+j]=acc;
}

__global__ void k_spmm16f(const int* __restrict__ rp1, const int* __restrict__ col1,
                          const float* __restrict__ val1,
                          const int* __restrict__ rp2, const int* __restrict__ col2,
                          const float* __restrict__ val2,
                          const float* __restrict__ b1, const float* __restrict__ b2,
                          const float* __restrict__ X, float* __restrict__ Y){
    int row=blockIdx.x*16+threadIdx.y; int j=threadIdx.x;
    if(row>=Nn) return;
    float a1=0.f, a2=0.f;
    for(int i=rp1[row];i<rp1[row+1];i++) a1+=val1[i]*X[(long)col1[i]*16+j];
    for(int i=rp2[row];i<rp2[row+1];i++) a2+=val2[i]*X[(long)col2[i]*16+j];
    Y[(long)row*16+j]=b1[row]*a1+b2[row]*a2;
}

// ------------- gen_view helpers -------------
__global__ void k_nodedot(const float* __restrict__ emb, const float* __restrict__ Wm,
                          float* __restrict__ dr, float* __restrict__ dc){
    int node=(blockIdx.x*blockDim.x+threadIdx.x)>>5; if(node>=Nn) return;
    int lane=threadIdx.x&31;
    float2 e=((const float2*)(emb+(long)node*64))[lane];
    float2 wr=((const float2*)Wm)[lane];
    float2 wc=((const float2*)Wm)[lane+32];
    float a=e.x*wr.x+e.y*wr.y;
    float b=e.x*wc.x+e.y*wc.y;
#pragma unroll
    for(int o=16;o;o>>=1){
        a+=__shfl_xor_sync(0xffffffffu,a,o);
        b+=__shfl_xor_sync(0xffffffffu,b,o);
    }
    if(lane==0){dr[node]=a; dc[node]=b;}
}

__global__ void k_gensoftmax(const int* __restrict__ rp, const int* __restrict__ col,
                             float* __restrict__ val, const float* __restrict__ dr,
                             const float* __restrict__ dc, const float* __restrict__ bm,
                             float com){
    int row=(blockIdx.x*blockDim.x+threadIdx.x)>>5; if(row>=Nn) return;
    int lane=threadIdx.x&31;
    int s=rp[row], e=rp[row+1];
    if(s==e) return;
    float base=dr[row]+bm[0];
    float m=-3.4e38f;
    for(int i=s+lane;i<e;i+=32) m=fmaxf(m, base+dc[col[i]]);
#pragma unroll
    for(int o=16;o;o>>=1) m=fmaxf(m,__shfl_xor_sync(0xffffffffu,m,o));
    float ss=0.f;
    for(int i=s+lane;i<e;i+=32) ss+=__expf(base+dc[col[i]]-m);
#pragma unroll
    for(int o=16;o;o>>=1) ss+=__shfl_xor_sync(0xffffffffu,ss,o);
    float inv=com/ss;
    for(int i=s+lane;i<e;i+=32) val[i]+=__expf(base+dc[col[i]]-m)*inv;
}

// ------------- 16-class softmax + logits + top2 weight -------------
__global__ void k_softmax_w(const float* __restrict__ C, float* __restrict__ lg,
                            float* __restrict__ w){
    int node=blockIdx.x*blockDim.x+threadIdx.x; if(node>=Nn) return;
    float x[16];
    const float4* p=(const float4*)(C+(long)node*16);
#pragma unroll
    for(int q=0;q<4;q++){float4 t=p[q]; x[4*q]=t.x; x[4*q+1]=t.y; x[4*q+2]=t.z; x[4*q+3]=t.w;}
    float m=x[0];
#pragma unroll
    for(int j=1;j<16;j++) m=fmaxf(m,x[j]);
    float s=0.f;
#pragma unroll
    for(int j=0;j<16;j++){x[j]=__expf(x[j]-m); s+=x[j];}
    float inv=1.f/s;
    float fir=0.f, sec=0.f;
#pragma unroll
    for(int j=0;j<16;j++){
        float pr=x[j]*inv;
        lg[(long)node*16+j]=logf(pr+EPSF);
        if(pr>fir){sec=fir; fir=pr;} else if(pr>sec) sec=pr;
    }
    if(w) w[node]=sqrtf((fir+EPSF)*(fir-sec+EPSF));
}

__global__ void k_bal(const float* __restrict__ w1, const float* __restrict__ w2,
                      float* __restrict__ b1, float* __restrict__ b2){
    int i=blockIdx.x*blockDim.x+threadIdx.x; if(i>=Nn) return;
    float a=w1[i], b=w2[i], inv=1.f/(a+b);
    b1[i]=a*inv; b2[i]=b*inv;
}

__global__ void k_normrows(float* __restrict__ E, int nrows){
    int row=(blockIdx.x*blockDim.x+threadIdx.x)>>5; if(row>=nrows) return;
    int lane=threadIdx.x&31;
    float4* p=(float4*)(E+(long)row*128);
    float4 v=p[lane];
    float s=v.x*v.x+v.y*v.y+v.z*v.z+v.w*v.w;
#pragma unroll
    for(int o=16;o;o>>=1) s+=__shfl_xor_sync(0xffffffffu,s,o);
    float inv=rsqrtf(s);
    v.x*=inv; v.y*=inv; v.z*=inv; v.w*=inv;
    p[lane]=v;
}

// ------------- contrast pair (tf32): exp(2*z1.z2) row/col sums + diag -------------
__global__ __launch_bounds__(256,2) void k_contrast(
        const float* __restrict__ z1, const float* __restrict__ z2,
        float* __restrict__ rs, float* __restrict__ cs, float* __restrict__ dg){
    __shared__ __align__(16) u32 sA[128*SAP];
    __shared__ __align__(16) u32 sB[32*SBP];
    __shared__ float sRS[128], sCS[128];
    int tid=threadIdx.x, lane=tid&31, ww=tid>>5, wr=ww>>2, wc=ww&3;
    int br=blockIdx.y*128, bc=blockIdx.x*128;
    float acc[4][4][4];
#pragma unroll
    for(int i=0;i<4;i++)
#pragma unroll
    for(int j=0;j<4;j++)
#pragma unroll
    for(int q=0;q<4;q++) acc[i][j][q]=0.f;
    int ra=tid>>3, fa=(tid&7)<<2;

    for(int k0=0;k0<128;k0+=32){
#pragma unroll
        for(int h=0;h<4;h++){
            int r=ra+h*32;
            float4 v=*(const float4*)(z1+(long)(br+r)*128+k0+fa);
            uint4 t=make_uint4(f2tf(v.x),f2tf(v.y),f2tf(v.z),f2tf(v.w));
            *(uint4*)&sA[r*SAP+fa]=t;
        }
#pragma unroll
        for(int h=0;h<4;h++){
            int c=ra+h*32;
            float4 v=*(const float4*)(z2+(long)(bc+c)*128+k0+fa);
            sB[(fa+0)*SBP+c]=f2tf(v.x); sB[(fa+1)*SBP+c]=f2tf(v.y);
            sB[(fa+2)*SBP+c]=f2tf(v.z); sB[(fa+3)*SBP+c]=f2tf(v.w);
        }
        __syncthreads();
        TF32_COMPUTE_CHUNK();
        __syncthreads();
    }
    if(tid<128){sRS[tid]=0.f; sCS[tid]=0.f;}
    __syncthreads();
    float cs0[4]={0,0,0,0}, cs1[4]={0,0,0,0};
#pragma unroll
    for(int mf=0;mf<4;mf++){
        float r0sum=0.f, r1sum=0.f;
        int r0g=br+wr*64+mf*16+(lane>>2);
        int r1g=r0g+8;
#pragma unroll
        for(int nf=0;nf<4;nf++){
            float e0=__expf(2.f*acc[mf][nf][0]);
            float e1=__expf(2.f*acc[mf][nf][1]);
            float e2=__expf(2.f*acc[mf][nf][2]);
            float e3=__expf(2.f*acc[mf][nf][3]);
            int cg_=bc+wc*32+nf*8+(lane&3)*2;
            if(r0g==cg_)   dg[r0g]=e0;
            if(r0g==cg_+1) dg[r0g]=e1;
            if(r1g==cg_)   dg[r1g]=e2;
            if(r1g==cg_+1) dg[r1g]=e3;
            r0sum+=e0+e1; r1sum+=e2+e3;
            cs0[nf]+=e0+e2; cs1[nf]+=e1+e3;
        }
        r0sum+=__shfl_xor_sync(0xffffffffu,r0sum,1);
        r0sum+=__shfl_xor_sync(0xffffffffu,r0sum,2);
        r1sum+=__shfl_xor_sync(0xffffffffu,r1sum,1);
        r1sum+=__shfl_xor_sync(0xffffffffu,r1sum,2);
        if((lane&3)==0){
            atomicAdd(&sRS[wr*64+mf*16+(lane>>2)], r0sum);
            atomicAdd(&sRS[wr*64+mf*16+(lane>>2)+8], r1sum);
        }
    }
#pragma unroll
    for(int nf=0;nf<4;nf++){
#pragma unroll
        for(int o=4;o<32;o<<=1){
            cs0[nf]+=__shfl_xor_sync(0xffffffffu,cs0[nf],o);
            cs1[nf]+=__shfl_xor_sync(0xffffffffu,cs1[nf],o);
        }
        if(lane<4){
            atomicAdd(&sCS[wc*32+nf*8+lane*2],   cs0[nf]);
            atomicAdd(&sCS[wc*32+nf*8+lane*2+1], cs1[nf]);
        }
    }
    __syncthreads();
    if(tid<128){atomicAdd(&rs[br+tid], sRS[tid]); atomicAdd(&cs[bc+tid], sCS[tid]);}
}

__global__ void k_creduce3(const float* __restrict__ RS, const float* __restrict__ CS,
                           const float* __restrict__ DG, float* out){
    __shared__ float sh[1024];
    int pair=blockIdx.x;
    const float* rs=RS+(long)pair*Bb;
    const float* cs=CS+(long)pair*Bb;
    const float* dg=DG+(long)pair*Bb;
    int tid=threadIdx.x;
    float a=0.f;
    for(int i=tid;i<Bb;i+=1024){
        a+=-logf(dg[i]/(rs[i]+EPSF)+EPSF);
        a+=-logf(dg[i]/(cs[i]+EPSF)+EPSF);
    }
    sh[tid]=a; __syncthreads();
    for(int d=512;d;d>>=1){ if(tid<d) sh[tid]+=sh[tid+d]; __syncthreads(); }
    if(tid==0) out[pair]=0.5f*sh[0]/(float)Bb;
}

// ------------- host -------------
#define GSA(var) ([]{ void* _p; cudaGetSymbolAddress(&_p, var); return _p; }())

extern "C" void kernel_launch(void* const* d_in, const int* in_sizes, int n_in,
                              void* d_out, int out_size){
    const float* feat  =(const float*)d_in[0];
    const int*   i1    =(const int*)  d_in[1];
    const float* v1    =(const float*)d_in[2];
    const int*   i2    =(const int*)  d_in[3];
    const float* v2    =(const float*)d_in[4];
    const int*   bidx  =(const int*)  d_in[5];
    const float* Wgen1 =(const float*)d_in[6];
    const float* Wm1   =(const float*)d_in[7];
    const float* bm1   =(const float*)d_in[8];
    const float* Wgen2 =(const float*)d_in[9];
    const float* Wm2   =(const float*)d_in[10];
    const float* bm2   =(const float*)d_in[11];
    const float* W1v1  =(const float*)d_in[12];
    const float* W2v1  =(const float*)d_in[13];
    const float* W1v2  =(const float*)d_in[14];
    const float* W2v2  =(const float*)d_in[15];
    const float* W1v   =(const float*)d_in[16];
    const float* W2v   =(const float*)d_in[17];
    const float* Wg    =(const float*)d_in[18];
    const float* Wg1   =(const float*)d_in[19];
    const float* Wg2   =(const float*)d_in[20];
    const float* Wp1   =(const float*)d_in[21];
    const float* bp1   =(const float*)d_in[22];
    const float* Wp2   =(const float*)d_in[23];
    const float* bp2   =(const float*)d_in[24];
    float* out=(float*)d_out;

    float* Wp=(float*)GSA(g_Wp);
    float* X64a=(float*)GSA(g_X64a); float* X64b=(float*)GSA(g_X64b);
    float* XC1=(float*)GSA(g_XC1); float* XC2=(float*)GSA(g_XC2); float* XCf=(float*)GSA(g_XCf);
    float* XG=(float*)GSA(g_XG); float* XG1=(float*)GSA(g_XG1); float* XG2=(float*)GSA(g_XG2);
    float* Ha=(float*)GSA(g_Ha); float* Hb=(float*)GSA(g_Hb);
    float* emba=(float*)GSA(g_emba); float* embb=(float*)GSA(g_embb);
    float* S16a=(float*)GSA(g_S16a); float* S16b=(float*)GSA(g_S16b);
    float* C16a=(float*)GSA(g_C16a); float* C16b=(float*)GSA(g_C16b);
    float* dra=(float*)GSA(g_dra), *dca=(float*)GSA(g_dca);
    float* drb=(float*)GSA(g_drb), *dcb=(float*)GSA(g_dcb);
    float* w1=(float*)GSA(g_w1), *w2=(float*)GSA(g_w2);
    float* b1=(float*)GSA(g_b1), *b2=(float*)GSA(g_b2);
    int* cnt1=(int*)GSA(g_cnt1), *cnt1b=(int*)GSA(g_cnt1b);
    int* cnt2=(int*)GSA(g_cnt2), *cnt2b=(int*)GSA(g_cnt2b);
    int* cur1d=(int*)GSA(g_cur1d), *cur2d=(int*)GSA(g_cur2d);
    int* cur1s=(int*)GSA(g_cur1s), *cur2s=(int*)GSA(g_cur2s);
    int* rp1d=(int*)GSA(g_rp1d), *rp2d=(int*)GSA(g_rp2d);
    int* rp1s=(int*)GSA(g_rp1s), *rp2s=(int*)GSA(g_rp2s);
    int* col1d=(int*)GSA(g_col1d);   float* val1d=(float*)GSA(g_val1d);
    int* col2d=(int*)GSA(g_col2d);   float* val2d=(float*)GSA(g_val2d);
    int* row1d=(int*)GSA(g_row1d);   int* row2d=(int*)GSA(g_row2d);
    int* col1s=(int*)GSA(g_col1s);   float* val1s=(float*)GSA(g_val1s);
    int* col2s=(int*)GSA(g_col2s);   float* val2s=(float*)GSA(g_val2s);
    float* Z=(float*)GSA(g_Z), *T=(float*)GSA(g_T), *E=(float*)GSA(g_E);
    float* RS=(float*)GSA(g_RS), *CS=(float*)GSA(g_CS), *DG=(float*)GSA(g_DG);

    float* E0=E;
    float* E1=E+(long)Bb*128;
    float* E2=E+(long)2*Bb*128;

    const int TB=256;
    int gN  =(Nn+TB-1)/TB;
    int gE  =(Ee+TB-1)/TB;
    int gW  =(Nn*32+TB-1)/TB;
    int gWB =(Bb*32+TB-1)/TB;
    dim3 b16(16,16); int g16=(Nn+15)/16;
    dim3 cg(32,32);

    static cudaStream_t s1=0, s2=0, s3=0;
    static cudaEvent_t eRoot=0,eScan=0,eA=0,eB=0,eC=0,eD=0,eSym2=0,eW1=0,eW2=0,
                       eZ1=0,eZ2=0,eFg=0,eEV=0,eE12=0,eCa=0,eCb=0,eF2=0;
    if(!s1){
        cudaStreamCreateWithFlags(&s1, cudaStreamNonBlocking);
        cudaStreamCreateWithFlags(&s2, cudaStreamNonBlocking);
        cudaStreamCreateWithFlags(&s3, cudaStreamNonBlocking);
        cudaEventCreateWithFlags(&eRoot,cudaEventDisableTiming);
        cudaEventCreateWithFlags(&eScan,cudaEventDisableTiming);
        cudaEventCreateWithFlags(&eA, cudaEventDisableTiming);
        cudaEventCreateWithFlags(&eB, cudaEventDisableTiming);
        cudaEventCreateWithFlags(&eC, cudaEventDisableTiming);
        cudaEventCreateWithFlags(&eD, cudaEventDisableTiming);
        cudaEventCreateWithFlags(&eSym2,cudaEventDisableTiming);
        cudaEventCreateWithFlags(&eW1,cudaEventDisableTiming);
        cudaEventCreateWithFlags(&eW2,cudaEventDisableTiming);
        cudaEventCreateWithFlags(&eZ1,cudaEventDisableTiming);
        cudaEventCreateWithFlags(&eZ2,cudaEventDisableTiming);
        cudaEventCreateWithFlags(&eFg,cudaEventDisableTiming);
        cudaEventCreateWithFlags(&eEV,cudaEventDisableTiming);
        cudaEventCreateWithFlags(&eE12,cudaEventDisableTiming);
        cudaEventCreateWithFlags(&eCa,cudaEventDisableTiming);
        cudaEventCreateWithFlags(&eCb,cudaEventDisableTiming);
        cudaEventCreateWithFlags(&eF2,cudaEventDisableTiming);
    }

    cudaEventRecord(eRoot, 0);
    cudaStreamWaitEvent(s1, eRoot, 0);
    cudaStreamWaitEvent(s2, eRoot, 0);
    cudaStreamWaitEvent(s3, eRoot, 0);

    int gyP=(Nn+127)/128;
    // ---- stream 0: pack + sliced big GEMM, ordered by consumer need ----
    k_pack<<<(256*896+TB-1)/TB,TB>>>(Wgen1,Wgen2,W1v1,W1v2,W1v,Wg,Wg1,Wg2,Wp);
    k_zero_f2<<<(3*Bb+TB-1)/TB,TB>>>(RS,CS,3*Bb);
    k_gemmP<<<dim3(1,gyP),256>>>(feat,Wp,0,X64a,X64b,XC1,XC2,XCf,XG,XG1,XG2);
    cudaEventRecord(eA, 0);   // X64a, X64b
    k_gemmP<<<dim3(2,gyP),256>>>(feat,Wp,1,X64a,X64b,XC1,XC2,XCf,XG,XG1,XG2);
    cudaEventRecord(eB, 0);   // XC1, XC2
    k_gemmP<<<dim3(2,gyP),256>>>(feat,Wp,3,X64a,X64b,XC1,XC2,XCf,XG,XG1,XG2);
    cudaEventRecord(eD, 0);   // XCf, XG
    k_gemmP<<<dim3(2,gyP),256>>>(feat,Wp,5,X64a,X64b,XC1,XC2,XCf,XG,XG1,XG2);
    cudaEventRecord(eC, 0);   // XG1, XG2

    // ---- s1: CSR build + view1 pipeline ----
    k_zero4<<<gN,TB,0,s1>>>(cnt1,cnt1b,cnt2,cnt2b,Nn);
    k_count2<<<gE,TB,0,s1>>>(i1,i2,cnt1,cnt1b,cnt2,cnt2b);
    k_scan4<<<4,1024,0,s1>>>(cnt1,rp1d,cur1d,cnt1b,rp1s,cur1s,cnt2,rp2d,cur2d,cnt2b,rp2s,cur2s);
    cudaEventRecord(eScan, s1);
    k_scatter_dir<<<gE,TB,0,s1>>>(i1,v1,cur1d,col1d,val1d,row1d);
    cudaStreamWaitEvent(s1, eA, 0);
    k_spmm64<<<gW,TB,0,s1>>>(rp1d,col1d,val1d,X64a,emba);
    k_nodedot<<<gW,TB,0,s1>>>(emba,Wm1,dra,dca);
    k_gensoftmax<<<gW,TB,0,s1>>>(rp1d,col1d,val1d,dra,dca,bm1,0.5f);
    k_scatter_sym_e<<<gE,TB,0,s1>>>(row1d,col1d,val1d,cur1s,col1s,val1s);
    cudaStreamWaitEvent(s1, eB, 0);
    k_spmm128<<<gW,TB,0,s1>>>(rp1s,col1s,val1s,XC1,Ha);
    k_gemm16<<<g16,b16,0,s1>>>(Ha,W2v1,S16a,Nn);
    k_spmm16<<<g16,b16,0,s1>>>(rp1s,col1s,val1s,S16a,C16a);
    k_softmax_w<<<gN,TB,0,s1>>>(C16a,out+(long)16*Nn,w1);
    cudaEventRecord(eW1, s1);
    cudaStreamWaitEvent(s1, eC, 0);
    k_spmm128g<<<gWB,TB,0,s1>>>(bidx,rp1s,col1s,val1s,XG1,E1);
    cudaEventRecord(eZ1, s1);

    // ---- s2: view2 pipeline, then fused classifier chain ----
    cudaStreamWaitEvent(s2, eScan, 0);
    k_scatter_dir<<<gE,TB,0,s2>>>(i2,v2,cur2d,col2d,val2d,row2d);
    cudaStreamWaitEvent(s2, eA, 0);
    k_spmm64<<<gW,TB,0,s2>>>(rp2d,col2d,val2d,X64b,embb);
    k_nodedot<<<gW,TB,0,s2>>>(embb,Wm2,drb,dcb);
    k_gensoftmax<<<gW,TB,0,s2>>>(rp2d,col2d,val2d,drb,dcb,bm2,0.5f);
    k_scatter_sym_e<<<gE,TB,0,s2>>>(row2d,col2d,val2d,cur2s,col2s,val2s);
    cudaEventRecord(eSym2, s2);
    cudaStreamWaitEvent(s2, eB, 0);
    k_spmm128<<<gW,TB,0,s2>>>(rp2s,col2s,val2s,XC2,Hb);
    k_gemm16<<<g16,b16,0,s2>>>(Hb,W2v2,S16b,Nn);
    k_spmm16<<<g16,b16,0,s2>>>(rp2s,col2s,val2s,S16b,C16b);
    k_softmax_w<<<gN,TB,0,s2>>>(C16b,out+(long)32*Nn,w2);
    cudaEventRecord(eW2, s2);
    cudaStreamWaitEvent(s2, eW1, 0);
    cudaStreamWaitEvent(s2, eD, 0);
    k_bal<<<gN,TB,0,s2>>>(w1,w2,b1,b2);
    k_spmm128fg<<<gWB,TB,0,s2>>>(bidx,rp1s,col1s,val1s,rp2s,col2s,val2s,b1,b2,XG,Z);
    cudaEventRecord(eFg, s2);
    k_spmm128f<<<gW,TB,0,s2>>>(rp1s,col1s,val1s,rp2s,col2s,val2s,b1,b2,XCf,Ha);
    k_gemm16<<<g16,b16,0,s2>>>(Ha,W2v,S16a,Nn);
    k_spmm16f<<<g16,b16,0,s2>>>(rp1s,col1s,val1s,rp2s,col2s,val2s,b1,b2,S16a,C16a);
    k_softmax_w<<<gN,TB,0,s2>>>(C16a,out,nullptr);
    cudaEventRecord(eF2, s2);

    // ---- s3: XG2 gather, E1/E2 projection + contrast(E1,E2) ----
    cudaStreamWaitEvent(s3, eC, 0);
    cudaStreamWaitEvent(s3, eSym2, 0);
    k_spmm128g<<<gWB,TB,0,s3>>>(bidx,rp2s,col2s,val2s,XG2,E2);
    cudaEventRecord(eZ2, s3);
    cudaStreamWaitEvent(s3, eZ1, 0);
    k_gemm128<<<dim3(1,(2*Bb)/128),256,0,s3>>>(E1,Wp1,bp1,T+(long)Bb*128,2*Bb,1);
    k_gemm128<<<dim3(1,(2*Bb)/128),256,0,s3>>>(T+(long)Bb*128,Wp2,bp2,E1,2*Bb,0);
    k_normrows<<<(2*Bb*32+TB-1)/TB,TB,0,s3>>>(E1,2*Bb);
    cudaEventRecord(eE12, s3);
    k_contrast<<<cg,256,0,s3>>>(E1,E2,RS+2*Bb,CS+2*Bb,DG+2*Bb);   // pair v1v2

    // ---- s1: EV projection + contrast(EV,E1) ----
    cudaStreamWaitEvent(s1, eFg, 0);
    k_gemm128<<<dim3(1,Bb/128),256,0,s1>>>(Z,Wp1,bp1,T,Bb,1);
    k_gemm128<<<dim3(1,Bb/128),256,0,s1>>>(T,Wp2,bp2,E0,Bb,0);
    k_normrows<<<(Bb*32+TB-1)/TB,TB,0,s1>>>(E0,Bb);
    cudaEventRecord(eEV, s1);
    cudaStreamWaitEvent(s1, eE12, 0);
    k_contrast<<<cg,256,0,s1>>>(E0,E1,RS,CS,DG);                   // pair vv1
    cudaEventRecord(eCa, s1);

    // ---- s3: contrast(EV,E2) ----
    cudaStreamWaitEvent(s3, eEV, 0);
    k_contrast<<<cg,256,0,s3>>>(E0,E2,RS+Bb,CS+Bb,DG+Bb);          // pair vv2
    cudaEventRecord(eCb, s3);

    // ---- stream 0: join all streams + final reduce ----
    cudaStreamWaitEvent(0, eCa, 0);
    cudaStreamWaitEvent(0, eCb, 0);
    cudaStreamWaitEvent(0, eF2, 0);
    k_creduce3<<<3,1024>>>(RS,CS,DG,out+(long)48*Nn);
}

// round 17
// speedup vs baseline: 1.7307x; 1.0139x over previous
#include <cuda_runtime.h>
#include <math.h>

#define Nn 30000
#define Ee 480000
#define Bb 4096
#define EPSF 1e-8f

typedef unsigned long long u64;
typedef unsigned int u32;
__device__ __forceinline__ u32 f2tf(float f){u32 u;asm("cvt.rna.tf32.f32 %0,%1;":"=r"(u):"f"(f));return u;}
__device__ __forceinline__ void mma_tf32(float* c,u32 a0,u32 a1,u32 a2,u32 a3,u32 b0,u32 b1){
    asm volatile("mma.sync.aligned.m16n8k8.row.col.f32.tf32.tf32.f32 "
        "{%0,%1,%2,%3},{%4,%5,%6,%7},{%8,%9},{%0,%1,%2,%3};"
        : "+f"(c[0]),"+f"(c[1]),"+f"(c[2]),"+f"(c[3])
        : "r"(a0),"r"(a1),"r"(a2),"r"(a3),"r"(b0),"r"(b1));
}

#define SAP 36
#define SBP 136

// ------------- device scratch -------------
__device__ float g_Wp[256*896];
__device__ float g_X64a[Nn*64], g_X64b[Nn*64];
__device__ float g_XC1[Nn*128], g_XC2[Nn*128], g_XCf[Nn*128];
__device__ float g_XG[Nn*128], g_XG1[Nn*128], g_XG2[Nn*128];
__device__ float g_Ha[Nn*128], g_Hb[Nn*128];
__device__ float g_Hf1[Nn*128], g_Hf2[Nn*128];
__device__ float g_S16a[Nn*16], g_S16b[Nn*16];
__device__ float g_C16a[Nn*16], g_C16b[Nn*16];
__device__ float g_dra[Nn], g_dca[Nn], g_drb[Nn], g_dcb[Nn];
__device__ float g_w1[Nn], g_w2[Nn];
__device__ int   g_cnt1[Nn], g_cnt1b[Nn], g_cnt2[Nn], g_cnt2b[Nn];
__device__ int   g_cur1d[Nn], g_cur2d[Nn], g_cur1s[Nn], g_cur2s[Nn];
__device__ int   g_rp1d[Nn+1], g_rp2d[Nn+1], g_rp1s[Nn+1], g_rp2s[Nn+1];
__device__ int   g_col1d[Ee];   __device__ float g_val1d[Ee];   __device__ int g_row1d[Ee];
__device__ int   g_col2d[Ee];   __device__ float g_val2d[Ee];   __device__ int g_row2d[Ee];
__device__ int   g_col1s[2*Ee]; __device__ float g_val1s[2*Ee];
__device__ int   g_col2s[2*Ee]; __device__ float g_val2s[2*Ee];
__device__ float g_Z[3*Bb*128], g_T[3*Bb*128], g_E[3*Bb*128];
__device__ float g_RS[3*Bb], g_CS[3*Bb], g_DG[3*Bb];

// ------------- pack weights -------------
__global__ void k_pack(const float* __restrict__ wg1, const float* __restrict__ wg2,
                       const float* __restrict__ a, const float* __restrict__ b,
                       const float* __restrict__ c, const float* __restrict__ d,
                       const float* __restrict__ e, const float* __restrict__ f,
                       float* __restrict__ Wp){
    int i=blockIdx.x*blockDim.x+threadIdx.x; if(i>=256*896) return;
    int row=i/896, col=i%896;
    float v;
    if(col<64) v=wg1[row*64+col];
    else if(col<128) v=wg2[row*64+col-64];
    else{
        int blk=(col-128)>>7, lc=(col-128)&127;
        const float* s;
        switch(blk){case 0:s=a;break;case 1:s=b;break;case 2:s=c;break;
                    case 3:s=d;break;case 4:s=e;break;default:s=f;break;}
        v=s[row*128+lc];
    }
    Wp[i]=v;
}

// ------------- small utils -------------
__global__ void k_zero4(int* a,int* b,int* c,int* d,int n){
    int i=blockIdx.x*blockDim.x+threadIdx.x; if(i<n){a[i]=0;b[i]=0;c[i]=0;d[i]=0;} }
__global__ void k_zero_f2(float* a, float* b, int n){
    int i=blockIdx.x*blockDim.x+threadIdx.x; if(i<n){a[i]=0.f;b[i]=0.f;} }

__global__ void k_count2(const int* __restrict__ ind1, const int* __restrict__ ind2,
                         int* cd1, int* cs1, int* cd2, int* cs2){
    int e=blockIdx.x*blockDim.x+threadIdx.x; if(e>=Ee) return;
    int r1=ind1[e], c1=ind1[Ee+e];
    atomicAdd(&cd1[r1],1); atomicAdd(&cs1[r1],1); atomicAdd(&cs1[c1],1);
    int r2=ind2[e], c2=ind2[Ee+e];
    atomicAdd(&cd2[r2],1); atomicAdd(&cs2[r2],1); atomicAdd(&cs2[c2],1);
}

// 4 independent scans; register-staged, fully unrolled (CHUNK=30)
__global__ void k_scan4(const int* c0,int* r0,int* u0,const int* c1,int* r1,int* u1,
                        const int* c2,int* r2,int* u2,const int* c3,int* r3,int* u3){
    const int* cnt; int* rp; int* cu;
    switch(blockIdx.x){
        case 0: cnt=c0; rp=r0; cu=u0; break;
        case 1: cnt=c1; rp=r1; cu=u1; break;
        case 2: cnt=c2; rp=r2; cu=u2; break;
        default:cnt=c3; rp=r3; cu=u3; break;
    }
    const int CH=30;
    int tid=threadIdx.x;
    int s=tid*CH;
    int vloc[CH];
#pragma unroll
    for(int i=0;i<CH;i++){int idx=s+i; vloc[i]=(idx<Nn)?cnt[idx]:0;}
    int sum=0;
#pragma unroll
    for(int i=0;i<CH;i++) sum+=vloc[i];
    __shared__ int wsum[32];
    int lane=tid&31, wid=tid>>5;
    int v=sum;
#pragma unroll
    for(int o=1;o<32;o<<=1){int t=__shfl_up_sync(0xffffffffu,v,o); if(lane>=o) v+=t;}
    if(lane==31) wsum[wid]=v;
    __syncthreads();
    if(wid==0){
        int w=wsum[lane];
#pragma unroll
        for(int o=1;o<32;o<<=1){int t=__shfl_up_sync(0xffffffffu,w,o); if(lane>=o) w+=t;}
        wsum[lane]=w;
    }
    __syncthreads();
    int excl=v-sum+(wid?wsum[wid-1]:0);
    int run=excl;
#pragma unroll
    for(int i=0;i<CH;i++){
        int idx=s+i;
        if(idx<Nn){ rp[idx]=run; cu[idx]=run; run+=vloc[i]; }
    }
    if(tid==1023) rp[Nn]=run;
}

__global__ void k_scatter_dir(const int* __restrict__ ind, const float* __restrict__ vals,
                              int* cur, int* __restrict__ col, float* __restrict__ val,
                              int* __restrict__ rowid){
    int e=blockIdx.x*blockDim.x+threadIdx.x; if(e>=Ee) return;
    int r=ind[e], c=ind[Ee+e];
    int p=atomicAdd(&cur[r],1);
    col[p]=c; val[p]=vals[e]; rowid[p]=r;
}

// edge-parallel symmetrize
__global__ void k_scatter_sym_e(const int* __restrict__ rowid, const int* __restrict__ cold,
                                const float* __restrict__ vald, int* cur,
                                int* __restrict__ cols, float* __restrict__ vals){
    int e=blockIdx.x*blockDim.x+threadIdx.x; if(e>=Ee) return;
    int r=rowid[e], c=cold[e]; float v=vald[e];
    int p=atomicAdd(&cur[r],1); cols[p]=c; vals[p]=v;
    int q=atomicAdd(&cur[c],1); cols[q]=r; vals[q]=v;
}

// ======== tf32 MMA block ========
#define TF32_COMPUTE_CHUNK() do{ \
    _Pragma("unroll") \
    for(int k8=0;k8<4;k8++){ \
        int kb=k8*8; \
        u32 bf[4][2]; \
        _Pragma("unroll") \
        for(int nf=0;nf<4;nf++){ \
            int nb=wc*32+nf*8+(lane>>2); \
            bf[nf][0]=sB[(kb+(lane&3))*SBP+nb]; \
            bf[nf][1]=sB[(kb+(lane&3)+4)*SBP+nb]; \
        } \
        _Pragma("unroll") \
        for(int mf=0;mf<4;mf++){ \
            int rb=wr*64+mf*16+(lane>>2); \
            u32 a0=sA[rb*SAP+kb+(lane&3)]; \
            u32 a1=sA[(rb+8)*SAP+kb+(lane&3)]; \
            u32 a2=sA[rb*SAP+kb+(lane&3)+4]; \
            u32 a3=sA[(rb+8)*SAP+kb+(lane&3)+4]; \
            _Pragma("unroll") \
            for(int nf=0;nf<4;nf++) mma_tf32(acc[mf][nf],a0,a1,a2,a3,bf[nf][0],bf[nf][1]); \
        } \
    } \
}while(0)

// ------------- packed GEMM slice (tf32) -------------
__global__ __launch_bounds__(256,2) void k_gemmP(
        const float* __restrict__ A, const float* __restrict__ Wp, int bxoff,
        float* __restrict__ e1, float* __restrict__ e2,
        float* __restrict__ x0, float* __restrict__ x1, float* __restrict__ x2,
        float* __restrict__ x3, float* __restrict__ x4, float* __restrict__ x5){
    __shared__ __align__(16) u32 sA[128*SAP];
    __shared__ __align__(16) u32 sB[32*SBP];
    int tid=threadIdx.x, lane=tid&31, ww=tid>>5, wr=ww>>2, wc=ww&3;
    int bx=blockIdx.x+bxoff;
    int br=blockIdx.y*128;
    float acc[4][4][4];
#pragma unroll
    for(int i=0;i<4;i++)
#pragma unroll
    for(int j=0;j<4;j++)
#pragma unroll
    for(int q=0;q<4;q++) acc[i][j][q]=0.f;
    int ra=tid>>3, fa=(tid&7)<<2;
    int kwB=tid>>5, cw=(tid&31)<<2;

    for(int k0=0;k0<256;k0+=32){
#pragma unroll
        for(int h=0;h<4;h++){
            int r=ra+h*32, gr=br+r;
            float4 v=make_float4(0.f,0.f,0.f,0.f);
            if(gr<Nn) v=*(const float4*)(A+(long)gr*256+k0+fa);
            uint4 t=make_uint4(f2tf(v.x),f2tf(v.y),f2tf(v.z),f2tf(v.w));
            *(uint4*)&sA[r*SAP+fa]=t;
        }
#pragma unroll
        for(int h=0;h<4;h++){
            int kk=kwB+h*8;
            float4 v=*(const float4*)(Wp+(long)(k0+kk)*896+bx*128+cw);
            uint4 t=make_uint4(f2tf(v.x),f2tf(v.y),f2tf(v.z),f2tf(v.w));
            *(uint4*)&sB[kk*SBP+cw]=t;
        }
        __syncthreads();
        TF32_COMPUTE_CHUNK();
        __syncthreads();
    }
    float* dst; int w; int cb;
    if(bx==0){
        if(wc<2){ dst=e1; w=64; cb=wc*32; } else { dst=e2; w=64; cb=(wc-2)*32; }
    } else {
        switch(bx-1){case 0:dst=x0;break;case 1:dst=x1;break;case 2:dst=x2;break;
                     case 3:dst=x3;break;case 4:dst=x4;break;default:dst=x5;break;}
        w=128; cb=wc*32;
    }
#pragma unroll
    for(int mf=0;mf<4;mf++){
        int r0=br+wr*64+mf*16+(lane>>2);
        int r1=r0+8;
#pragma unroll
        for(int nf=0;nf<4;nf++){
            int c=cb+nf*8+(lane&3)*2;
            if(r0<Nn) *(float2*)&dst[(long)r0*w+c]=make_float2(acc[mf][nf][0],acc[mf][nf][1]);
            if(r1<Nn) *(float2*)&dst[(long)r1*w+c]=make_float2(acc[mf][nf][2],acc[mf][nf][3]);
        }
    }
}

// ------------- projection GEMM (tf32) -------------
__global__ __launch_bounds__(256,2) void k_gemm128(
        const float* __restrict__ A, const float* __restrict__ W,
        const float* __restrict__ bias, float* __restrict__ C,
        int n, int act){
    __shared__ __align__(16) u32 sA[128*SAP];
    __shared__ __align__(16) u32 sB[32*SBP];
    int tid=threadIdx.x, lane=tid&31, ww=tid>>5, wr=ww>>2, wc=ww&3;
    int br=blockIdx.y*128;
    float acc[4][4][4];
#pragma unroll
    for(int i=0;i<4;i++)
#pragma unroll
    for(int j=0;j<4;j++)
#pragma unroll
    for(int q=0;q<4;q++) acc[i][j][q]=0.f;
    int ra=tid>>3, fa=(tid&7)<<2;
    int kwB=tid>>5, cw=(tid&31)<<2;

    for(int k0=0;k0<128;k0+=32){
#pragma unroll
        for(int h=0;h<4;h++){
            int r=ra+h*32;
            float4 v=*(const float4*)(A+(long)(br+r)*128+k0+fa);
            uint4 t=make_uint4(f2tf(v.x),f2tf(v.y),f2tf(v.z),f2tf(v.w));
            *(uint4*)&sA[r*SAP+fa]=t;
        }
#pragma unroll
        for(int h=0;h<4;h++){
            int kk=kwB+h*8;
            float4 v=*(const float4*)(W+(long)(k0+kk)*128+cw);
            uint4 t=make_uint4(f2tf(v.x),f2tf(v.y),f2tf(v.z),f2tf(v.w));
            *(uint4*)&sB[kk*SBP+cw]=t;
        }
        __syncthreads();
        TF32_COMPUTE_CHUNK();
        __syncthreads();
    }
#pragma unroll
    for(int mf=0;mf<4;mf++){
        int r0=br+wr*64+mf*16+(lane>>2);
        int r1=r0+8;
#pragma unroll
        for(int nf=0;nf<4;nf++){
            int c=wc*32+nf*8+(lane&3)*2;
            float b0=bias?bias[c]:0.f, b1=bias?bias[c+1]:0.f;
            float v0=acc[mf][nf][0]+b0, v1=acc[mf][nf][1]+b1;
            float v2=acc[mf][nf][2]+b0, v3=acc[mf][nf][3]+b1;
            if(act==1){
                v0=(v0>0.f)?v0:expm1f(v0); v1=(v1>0.f)?v1:expm1f(v1);
                v2=(v2>0.f)?v2:expm1f(v2); v3=(v3>0.f)?v3:expm1f(v3);
            }
            *(float2*)&C[(long)r0*128+c]=make_float2(v0,v1);
            *(float2*)&C[(long)r1*128+c]=make_float2(v2,v3);
        }
    }
}

// ------------- GEMM M=16 (W2 in smem) -------------
__global__ void k_gemm16(const float* __restrict__ H, const float* __restrict__ W2,
                         float* __restrict__ C, int n){
    __shared__ float sW[128*16];
    int tid=threadIdx.y*16+threadIdx.x;
#pragma unroll
    for(int q=0;q<2;q++) ((float4*)sW)[tid*2+q]=((const float4*)W2)[tid*2+q];
    __syncthreads();
    int r=blockIdx.x*16+threadIdx.y, j=threadIdx.x;
    if(r>=n) return;
    const float4* H4=(const float4*)(H+(long)r*128);
    float acc=0.f;
#pragma unroll
    for(int k4=0;k4<32;k4++){
        float4 h=H4[k4];
        acc+=h.x*sW[(k4*4+0)*16+j];
        acc+=h.y*sW[(k4*4+1)*16+j];
        acc+=h.z*sW[(k4*4+2)*16+j];
        acc+=h.w*sW[(k4*4+3)*16+j];
    }
    C[(long)r*16+j]=acc;
}

// ------------- SpMM row helper -------------
__device__ __forceinline__ float4 spmm_row128(const int* __restrict__ rp,
        const int* __restrict__ col, const float* __restrict__ val,
        const float4* __restrict__ X4, int w, int lane){
    int s=rp[w], e=rp[w+1];
    float4 A=make_float4(0.f,0.f,0.f,0.f), B=A;
    int i=s;
    for(; i+1<e; i+=2){
        int c0=col[i], c1=col[i+1];
        float v0=val[i], v1=val[i+1];
        float4 x0=X4[(long)c0*32+lane];
        float4 x1=X4[(long)c1*32+lane];
        A.x+=v0*x0.x; A.y+=v0*x0.y; A.z+=v0*x0.z; A.w+=v0*x0.w;
        B.x+=v1*x1.x; B.y+=v1*x1.y; B.z+=v1*x1.z; B.w+=v1*x1.w;
    }
    if(i<e){
        int c=col[i]; float v=val[i];
        float4 x=X4[(long)c*32+lane];
        A.x+=v*x.x; A.y+=v*x.y; A.z+=v*x.z; A.w+=v*x.w;
    }
    A.x+=B.x; A.y+=B.y; A.z+=B.z; A.w+=B.w;
    return A;
}

__global__ void k_spmm128(const int* __restrict__ rp, const int* __restrict__ col,
                          const float* __restrict__ val, const float* __restrict__ X,
                          float* __restrict__ Y){
    int w=(blockIdx.x*blockDim.x+threadIdx.x)>>5; if(w>=Nn) return;
    int lane=threadIdx.x&31;
    float4 a=spmm_row128(rp,col,val,(const float4*)X,w,lane);
    a.x=fmaxf(a.x,0.f); a.y=fmaxf(a.y,0.f); a.z=fmaxf(a.z,0.f); a.w=fmaxf(a.w,0.f);
    ((float4*)Y)[(long)w*32+lane]=a;
}

// dual-CSR SpMM (no relu): rows [0,Nn) -> CSR1->Hf1, rows [Nn,2Nn) -> CSR2->Hf2
__global__ void k_spmm128d(const int* __restrict__ rp1, const int* __restrict__ col1,
                           const float* __restrict__ val1,
                           const int* __restrict__ rp2, const int* __restrict__ col2,
                           const float* __restrict__ val2,
                           const float* __restrict__ X,
                           float* __restrict__ Hf1, float* __restrict__ Hf2){
    int g=(blockIdx.x*blockDim.x+threadIdx.x)>>5; if(g>=2*Nn) return;
    int lane=threadIdx.x&31;
    if(g<Nn){
        float4 a=spmm_row128(rp1,col1,val1,(const float4*)X,g,lane);
        ((float4*)Hf1)[(long)g*32+lane]=a;
    }else{
        int w=g-Nn;
        float4 a=spmm_row128(rp2,col2,val2,(const float4*)X,w,lane);
        ((float4*)Hf2)[(long)w*32+lane]=a;
    }
}

// elementwise combine: Y = relu(f1[row]*Hf1 + f2[row]*Hf2), f = w/(w1+w2)
__global__ void k_combine(const float* __restrict__ Hf1, const float* __restrict__ Hf2,
                          const float* __restrict__ w1, const float* __restrict__ w2,
                          float* __restrict__ Y){
    int i=blockIdx.x*blockDim.x+threadIdx.x; if(i>=Nn*32) return;
    int row=i>>5;
    float aa=w1[row], bb=w2[row], inv=1.f/(aa+bb);
    float f1=aa*inv, f2=bb*inv;
    float4 a=((const float4*)Hf1)[i];
    float4 b=((const float4*)Hf2)[i];
    float4 r;
    r.x=fmaxf(f1*a.x+f2*b.x,0.f); r.y=fmaxf(f1*a.y+f2*b.y,0.f);
    r.z=fmaxf(f1*a.z+f2*b.z,0.f); r.w=fmaxf(f1*a.w+f2*b.w,0.f);
    ((float4*)Y)[i]=r;
}

__global__ void k_spmm128g(const int* __restrict__ bidx,
                           const int* __restrict__ rp, const int* __restrict__ col,
                           const float* __restrict__ val, const float* __restrict__ X,
                           float* __restrict__ Z){
    int w=(blockIdx.x*blockDim.x+threadIdx.x)>>5; if(w>=Bb) return;
    int lane=threadIdx.x&31;
    int row=bidx[w];
    float4 a=spmm_row128(rp,col,val,(const float4*)X,row,lane);
    a.x=fmaxf(a.x,0.f); a.y=fmaxf(a.y,0.f); a.z=fmaxf(a.z,0.f); a.w=fmaxf(a.w,0.f);
    ((float4*)Z)[(long)w*32+lane]=a;
}

__global__ void k_spmm128fg(const int* __restrict__ bidx,
                            const int* __restrict__ rp1, const int* __restrict__ col1,
                            const float* __restrict__ val1,
                            const int* __restrict__ rp2, const int* __restrict__ col2,
                            const float* __restrict__ val2,
                            const float* __restrict__ w1, const float* __restrict__ w2,
                            const float* __restrict__ X, float* __restrict__ Z){
    int w=(blockIdx.x*blockDim.x+threadIdx.x)>>5; if(w>=Bb) return;
    int lane=threadIdx.x&31;
    int row=bidx[w];
    float4 a1=spmm_row128(rp1,col1,val1,(const float4*)X,row,lane);
    float4 a2=spmm_row128(rp2,col2,val2,(const float4*)X,row,lane);
    float aa=w1[row], bb=w2[row], inv=1.f/(aa+bb);
    float f1=aa*inv, f2=bb*inv;
    float4 r;
    r.x=fmaxf(f1*a1.x+f2*a2.x,0.f); r.y=fmaxf(f1*a1.y+f2*a2.y,0.f);
    r.z=fmaxf(f1*a1.z+f2*a2.z,0.f); r.w=fmaxf(f1*a1.w+f2*a2.w,0.f);
    ((float4*)Z)[(long)w*32+lane]=r;
}

// fused: emb = relu(spmm64 row) in regs; dr = emb . Wm[0:64]; dc = emb . Wm[64:128]
__global__ void k_spmm64dot(const int* __restrict__ rp, const int* __restrict__ col,
                            const float* __restrict__ val, const float* __restrict__ X,
                            const float* __restrict__ Wm,
                            float* __restrict__ dr, float* __restrict__ dc){
    int w=(blockIdx.x*blockDim.x+threadIdx.x)>>5; if(w>=Nn) return;
    int lane=threadIdx.x&31;
    const float2* X2=(const float2*)X;
    int s=rp[w], e=rp[w+1];
    float2 A=make_float2(0.f,0.f), B=A;
    int i=s;
    for(; i+1<e; i+=2){
        int c0=col[i], c1=col[i+1];
        float v0=val[i], v1=val[i+1];
        float2 x0=X2[(long)c0*32+lane];
        float2 x1=X2[(long)c1*32+lane];
        A.x+=v0*x0.x; A.y+=v0*x0.y;
        B.x+=v1*x1.x; B.y+=v1*x1.y;
    }
    if(i<e){
        int c=col[i]; float v=val[i];
        float2 x=X2[(long)c*32+lane];
        A.x+=v*x.x; A.y+=v*x.y;
    }
    float ex=fmaxf(A.x+B.x,0.f), ey=fmaxf(A.y+B.y,0.f);
    float2 wrv=((const float2*)Wm)[lane];
    float2 wcv=((const float2*)Wm)[lane+32];
    float a=ex*wrv.x+ey*wrv.y;
    float b=ex*wcv.x+ey*wcv.y;
#pragma unroll
    for(int o=16;o;o>>=1){
        a+=__shfl_xor_sync(0xffffffffu,a,o);
        b+=__shfl_xor_sync(0xffffffffu,b,o);
    }
    if(lane==0){dr[w]=a; dc[w]=b;}
}

__global__ void k_spmm16(const int* __restrict__ rp, const int* __restrict__ col,
                         const float* __restrict__ val, const float* __restrict__ X,
                         float* __restrict__ Y){
    int row=blockIdx.x*16+threadIdx.y; int j=threadIdx.x;
    if(row>=Nn) return;
    float acc=0.f;
    for(int i=rp[row];i<rp[row+1];i++) acc+=val[i]*X[(long)col[i]*16+j];
    Y[(long)row*16+j]=acc;
}

__global__ void k_spmm16f(const int* __restrict__ rp1, const int* __restrict__ col1,
                          const float* __restrict__ val1,
                          const int* __restrict__ rp2, const int* __restrict__ col2,
                          const float* __restrict__ val2,
                          const float* __restrict__ w1, const float* __restrict__ w2,
                          const float* __restrict__ X, float* __restrict__ Y){
    int row=blockIdx.x*16+threadIdx.y; int j=threadIdx.x;
    if(row>=Nn) return;
    float a1=0.f, a2=0.f;
    for(int i=rp1[row];i<rp1[row+1];i++) a1+=val1[i]*X[(long)col1[i]*16+j];
    for(int i=rp2[row];i<rp2[row+1];i++) a2+=val2[i]*X[(long)col2[i]*16+j];
    float aa=w1[row], bb=w2[row], inv=1.f/(aa+bb);
    Y[(long)row*16+j]=aa*inv*a1+bb*inv*a2;
}

// ------------- gen_view softmax update -------------
__global__ void k_gensoftmax(const int* __restrict__ rp, const int* __restrict__ col,
                             float* __restrict__ val, const float* __restrict__ dr,
                             const float* __restrict__ dc, const float* __restrict__ bm,
                             float com){
    int row=(blockIdx.x*blockDim.x+threadIdx.x)>>5; if(row>=Nn) return;
    int lane=threadIdx.x&31;
    int s=rp[row], e=rp[row+1];
    if(s==e) return;
    float base=dr[row]+bm[0];
    float m=-3.4e38f;
    for(int i=s+lane;i<e;i+=32) m=fmaxf(m, base+dc[col[i]]);
#pragma unroll
    for(int o=16;o;o>>=1) m=fmaxf(m,__shfl_xor_sync(0xffffffffu,m,o));
    float ss=0.f;
    for(int i=s+lane;i<e;i+=32) ss+=__expf(base+dc[col[i]]-m);
#pragma unroll
    for(int o=16;o;o>>=1) ss+=__shfl_xor_sync(0xffffffffu,ss,o);
    float inv=com/ss;
    for(int i=s+lane;i<e;i+=32) val[i]+=__expf(base+dc[col[i]]-m)*inv;
}

// ------------- 16-class softmax + logits + top2 weight -------------
__global__ void k_softmax_w(const float* __restrict__ C, float* __restrict__ lg,
                            float* __restrict__ w){
    int node=blockIdx.x*blockDim.x+threadIdx.x; if(node>=Nn) return;
    float x[16];
    const float4* p=(const float4*)(C+(long)node*16);
#pragma unroll
    for(int q=0;q<4;q++){float4 t=p[q]; x[4*q]=t.x; x[4*q+1]=t.y; x[4*q+2]=t.z; x[4*q+3]=t.w;}
    float m=x[0];
#pragma unroll
    for(int j=1;j<16;j++) m=fmaxf(m,x[j]);
    float s=0.f;
#pragma unroll
    for(int j=0;j<16;j++){x[j]=__expf(x[j]-m); s+=x[j];}
    float inv=1.f/s;
    float fir=0.f, sec=0.f;
#pragma unroll
    for(int j=0;j<16;j++){
        float pr=x[j]*inv;
        lg[(long)node*16+j]=logf(pr+EPSF);
        if(pr>fir){sec=fir; fir=pr;} else if(pr>sec) sec=pr;
    }
    if(w) w[node]=sqrtf((fir+EPSF)*(fir-sec+EPSF));
}

__global__ void k_normrows(float* __restrict__ E, int nrows){
    int row=(blockIdx.x*blockDim.x+threadIdx.x)>>5; if(row>=nrows) return;
    int lane=threadIdx.x&31;
    float4* p=(float4*)(E+(long)row*128);
    float4 v=p[lane];
    float s=v.x*v.x+v.y*v.y+v.z*v.z+v.w*v.w;
#pragma unroll
    for(int o=16;o;o>>=1) s+=__shfl_xor_sync(0xffffffffu,s,o);
    float inv=rsqrtf(s);
    v.x*=inv; v.y*=inv; v.z*=inv; v.w*=inv;
    p[lane]=v;
}

// ------------- contrast pair (tf32) -------------
__global__ __launch_bounds__(256,2) void k_contrast(
        const float* __restrict__ z1, const float* __restrict__ z2,
        float* __restrict__ rs, float* __restrict__ cs, float* __restrict__ dg){
    __shared__ __align__(16) u32 sA[128*SAP];
    __shared__ __align__(16) u32 sB[32*SBP];
    __shared__ float sRS[128], sCS[128];
    int tid=threadIdx.x, lane=tid&31, ww=tid>>5, wr=ww>>2, wc=ww&3;
    int br=blockIdx.y*128, bc=blockIdx.x*128;
    float acc[4][4][4];
#pragma unroll
    for(int i=0;i<4;i++)
#pragma unroll
    for(int j=0;j<4;j++)
#pragma unroll
    for(int q=0;q<4;q++) acc[i][j][q]=0.f;
    int ra=tid>>3, fa=(tid&7)<<2;

    for(int k0=0;k0<128;k0+=32){
#pragma unroll
        for(int h=0;h<4;h++){
            int r=ra+h*32;
            float4 v=*(const float4*)(z1+(long)(br+r)*128+k0+fa);
            uint4 t=make_uint4(f2tf(v.x),f2tf(v.y),f2tf(v.z),f2tf(v.w));
            *(uint4*)&sA[r*SAP+fa]=t;
        }
#pragma unroll
        for(int h=0;h<4;h++){
            int c=ra+h*32;
            float4 v=*(const float4*)(z2+(long)(bc+c)*128+k0+fa);
            sB[(fa+0)*SBP+c]=f2tf(v.x); sB[(fa+1)*SBP+c]=f2tf(v.y);
            sB[(fa+2)*SBP+c]=f2tf(v.z); sB[(fa+3)*SBP+c]=f2tf(v.w);
        }
        __syncthreads();
        TF32_COMPUTE_CHUNK();
        __syncthreads();
    }
    if(tid<128){sRS[tid]=0.f; sCS[tid]=0.f;}
    __syncthreads();
    float cs0[4]={0,0,0,0}, cs1[4]={0,0,0,0};
#pragma unroll
    for(int mf=0;mf<4;mf++){
        float r0sum=0.f, r1sum=0.f;
        int r0g=br+wr*64+mf*16+(lane>>2);
        int r1g=r0g+8;
#pragma unroll
        for(int nf=0;nf<4;nf++){
            float e0=__expf(2.f*acc[mf][nf][0]);
            float e1=__expf(2.f*acc[mf][nf][1]);
            float e2=__expf(2.f*acc[mf][nf][2]);
            float e3=__expf(2.f*acc[mf][nf][3]);
            int cg_=bc+wc*32+nf*8+(lane&3)*2;
            if(r0g==cg_)   dg[r0g]=e0;
            if(r0g==cg_+1) dg[r0g]=e1;
            if(r1g==cg_)   dg[r1g]=e2;
            if(r1g==cg_+1) dg[r1g]=e3;
            r0sum+=e0+e1; r1sum+=e2+e3;
            cs0[nf]+=e0+e2; cs1[nf]+=e1+e3;
        }
        r0sum+=__shfl_xor_sync(0xffffffffu,r0sum,1);
        r0sum+=__shfl_xor_sync(0xffffffffu,r0sum,2);
        r1sum+=__shfl_xor_sync(0xffffffffu,r1sum,1);
        r1sum+=__shfl_xor_sync(0xffffffffu,r1sum,2);
        if((lane&3)==0){
            atomicAdd(&sRS[wr*64+mf*16+(lane>>2)], r0sum);
            atomicAdd(&sRS[wr*64+mf*16+(lane>>2)+8], r1sum);
        }
    }
#pragma unroll
    for(int nf=0;nf<4;nf++){
#pragma unroll
        for(int o=4;o<32;o<<=1){
            cs0[nf]+=__shfl_xor_sync(0xffffffffu,cs0[nf],o);
            cs1[nf]+=__shfl_xor_sync(0xffffffffu,cs1[nf],o);
        }
        if(lane<4){
            atomicAdd(&sCS[wc*32+nf*8+lane*2],   cs0[nf]);
            atomicAdd(&sCS[wc*32+nf*8+lane*2+1], cs1[nf]);
        }
    }
    __syncthreads();
    if(tid<128){atomicAdd(&rs[br+tid], sRS[tid]); atomicAdd(&cs[bc+tid], sCS[tid]);}
}

__global__ void k_creduce3(const float* __restrict__ RS, const float* __restrict__ CS,
                           const float* __restrict__ DG, float* out){
    __shared__ float sh[1024];
    int pair=blockIdx.x;
    const float* rs=RS+(long)pair*Bb;
    const float* cs=CS+(long)pair*Bb;
    const float* dg=DG+(long)pair*Bb;
    int tid=threadIdx.x;
    float a=0.f;
    for(int i=tid;i<Bb;i+=1024){
        a+=-logf(dg[i]/(rs[i]+EPSF)+EPSF);
        a+=-logf(dg[i]/(cs[i]+EPSF)+EPSF);
    }
    sh[tid]=a; __syncthreads();
    for(int d=512;d;d>>=1){ if(tid<d) sh[tid]+=sh[tid+d]; __syncthreads(); }
    if(tid==0) out[pair]=0.5f*sh[0]/(float)Bb;
}

// ------------- host -------------
#define GSA(var) ([]{ void* _p; cudaGetSymbolAddress(&_p, var); return _p; }())

extern "C" void kernel_launch(void* const* d_in, const int* in_sizes, int n_in,
                              void* d_out, int out_size){
    const float* feat  =(const float*)d_in[0];
    const int*   i1    =(const int*)  d_in[1];
    const float* v1    =(const float*)d_in[2];
    const int*   i2    =(const int*)  d_in[3];
    const float* v2    =(const float*)d_in[4];
    const int*   bidx  =(const int*)  d_in[5];
    const float* Wgen1 =(const float*)d_in[6];
    const float* Wm1   =(const float*)d_in[7];
    const float* bm1   =(const float*)d_in[8];
    const float* Wgen2 =(const float*)d_in[9];
    const float* Wm2   =(const float*)d_in[10];
    const float* bm2   =(const float*)d_in[11];
    const float* W1v1  =(const float*)d_in[12];
    const float* W2v1  =(const float*)d_in[13];
    const float* W1v2  =(const float*)d_in[14];
    const float* W2v2  =(const float*)d_in[15];
    const float* W1v   =(const float*)d_in[16];
    const float* W2v   =(const float*)d_in[17];
    const float* Wg    =(const float*)d_in[18];
    const float* Wg1   =(const float*)d_in[19];
    const float* Wg2   =(const float*)d_in[20];
    const float* Wp1   =(const float*)d_in[21];
    const float* bp1   =(const float*)d_in[22];
    const float* Wp2   =(const float*)d_in[23];
    const float* bp2   =(const float*)d_in[24];
    float* out=(float*)d_out;

    float* Wp=(float*)GSA(g_Wp);
    float* X64a=(float*)GSA(g_X64a); float* X64b=(float*)GSA(g_X64b);
    float* XC1=(float*)GSA(g_XC1); float* XC2=(float*)GSA(g_XC2); float* XCf=(float*)GSA(g_XCf);
    float* XG=(float*)GSA(g_XG); float* XG1=(float*)GSA(g_XG1); float* XG2=(float*)GSA(g_XG2);
    float* Ha=(float*)GSA(g_Ha); float* Hb=(float*)GSA(g_Hb);
    float* Hf1=(float*)GSA(g_Hf1); float* Hf2=(float*)GSA(g_Hf2);
    float* S16a=(float*)GSA(g_S16a); float* S16b=(float*)GSA(g_S16b);
    float* C16a=(float*)GSA(g_C16a); float* C16b=(float*)GSA(g_C16b);
    float* dra=(float*)GSA(g_dra), *dca=(float*)GSA(g_dca);
    float* drb=(float*)GSA(g_drb), *dcb=(float*)GSA(g_dcb);
    float* w1=(float*)GSA(g_w1), *w2=(float*)GSA(g_w2);
    int* cnt1=(int*)GSA(g_cnt1), *cnt1b=(int*)GSA(g_cnt1b);
    int* cnt2=(int*)GSA(g_cnt2), *cnt2b=(int*)GSA(g_cnt2b);
    int* cur1d=(int*)GSA(g_cur1d), *cur2d=(int*)GSA(g_cur2d);
    int* cur1s=(int*)GSA(g_cur1s), *cur2s=(int*)GSA(g_cur2s);
    int* rp1d=(int*)GSA(g_rp1d), *rp2d=(int*)GSA(g_rp2d);
    int* rp1s=(int*)GSA(g_rp1s), *rp2s=(int*)GSA(g_rp2s);
    int* col1d=(int*)GSA(g_col1d);   float* val1d=(float*)GSA(g_val1d);
    int* col2d=(int*)GSA(g_col2d);   float* val2d=(float*)GSA(g_val2d);
    int* row1d=(int*)GSA(g_row1d);   int* row2d=(int*)GSA(g_row2d);
    int* col1s=(int*)GSA(g_col1s);   float* val1s=(float*)GSA(g_val1s);
    int* col2s=(int*)GSA(g_col2s);   float* val2s=(float*)GSA(g_val2s);
    float* Z=(float*)GSA(g_Z), *T=(float*)GSA(g_T), *E=(float*)GSA(g_E);
    float* RS=(float*)GSA(g_RS), *CS=(float*)GSA(g_CS), *DG=(float*)GSA(g_DG);

    float* E0=E;
    float* E1=E+(long)Bb*128;
    float* E2=E+(long)2*Bb*128;

    const int TB=256;
    int gN  =(Nn+TB-1)/TB;
    int gE  =(Ee+TB-1)/TB;
    int gW  =(Nn*32+TB-1)/TB;
    int gW2 =(2*Nn*32+TB-1)/TB;
    int gWB =(Bb*32+TB-1)/TB;
    int gC  =(Nn*32+TB-1)/TB;
    dim3 b16(16,16); int g16=(Nn+15)/16;
    dim3 cg(32,32);

    static cudaStream_t s1=0, s2=0, s3=0;
    static cudaEvent_t eRoot=0,eScan=0,eA=0,eB=0,eC=0,eD=0,eSym1=0,eSym2=0,eW1=0,eW2=0,
                       eZ1=0,eFg=0,eEV=0,eE12=0,eCa=0,eCb=0,eF2=0,eHf=0;
    if(!s1){
        cudaStreamCreateWithFlags(&s1, cudaStreamNonBlocking);
        cudaStreamCreateWithFlags(&s2, cudaStreamNonBlocking);
        cudaStreamCreateWithFlags(&s3, cudaStreamNonBlocking);
        cudaEventCreateWithFlags(&eRoot,cudaEventDisableTiming);
        cudaEventCreateWithFlags(&eScan,cudaEventDisableTiming);
        cudaEventCreateWithFlags(&eA, cudaEventDisableTiming);
        cudaEventCreateWithFlags(&eB, cudaEventDisableTiming);
        cudaEventCreateWithFlags(&eC, cudaEventDisableTiming);
        cudaEventCreateWithFlags(&eD, cudaEventDisableTiming);
        cudaEventCreateWithFlags(&eSym1,cudaEventDisableTiming);
        cudaEventCreateWithFlags(&eSym2,cudaEventDisableTiming);
        cudaEventCreateWithFlags(&eW1,cudaEventDisableTiming);
        cudaEventCreateWithFlags(&eW2,cudaEventDisableTiming);
        cudaEventCreateWithFlags(&eZ1,cudaEventDisableTiming);
        cudaEventCreateWithFlags(&eFg,cudaEventDisableTiming);
        cudaEventCreateWithFlags(&eEV,cudaEventDisableTiming);
        cudaEventCreateWithFlags(&eE12,cudaEventDisableTiming);
        cudaEventCreateWithFlags(&eCa,cudaEventDisableTiming);
        cudaEventCreateWithFlags(&eCb,cudaEventDisableTiming);
        cudaEventCreateWithFlags(&eF2,cudaEventDisableTiming);
        cudaEventCreateWithFlags(&eHf,cudaEventDisableTiming);
    }

    cudaEventRecord(eRoot, 0);
    cudaStreamWaitEvent(s1, eRoot, 0);
    cudaStreamWaitEvent(s2, eRoot, 0);
    cudaStreamWaitEvent(s3, eRoot, 0);

    int gyP=(Nn+127)/128;
    // ---- stream 0: pack + sliced big GEMM ----
    // bx map: 0=X64ab, 1=XC1, 2=XC2, 3=XCf, 4=XG, 5=XG1, 6=XG2
    k_pack<<<(256*896+TB-1)/TB,TB>>>(Wgen1,Wgen2,W1v1,W1v2,W1v,Wg,Wg1,Wg2,Wp);
    k_zero_f2<<<(3*Bb+TB-1)/TB,TB>>>(RS,CS,3*Bb);
    k_gemmP<<<dim3(1,gyP),256>>>(feat,Wp,0,X64a,X64b,XC1,XC2,XCf,XG,XG1,XG2);
    cudaEventRecord(eA, 0);
    k_gemmP<<<dim3(2,gyP),256>>>(feat,Wp,1,X64a,X64b,XC1,XC2,XCf,XG,XG1,XG2);
    cudaEventRecord(eB, 0);
    k_gemmP<<<dim3(2,gyP),256>>>(feat,Wp,3,X64a,X64b,XC1,XC2,XCf,XG,XG1,XG2);
    cudaEventRecord(eD, 0);
    k_gemmP<<<dim3(2,gyP),256>>>(feat,Wp,5,X64a,X64b,XC1,XC2,XCf,XG,XG1,XG2);
    cudaEventRecord(eC, 0);

    // ---- s1: CSR build + view1 pipeline ----
    k_zero4<<<gN,TB,0,s1>>>(cnt1,cnt1b,cnt2,cnt2b,Nn);
    k_count2<<<gE,TB,0,s1>>>(i1,i2,cnt1,cnt1b,cnt2,cnt2b);
    k_scan4<<<4,1024,0,s1>>>(cnt1,rp1d,cur1d,cnt1b,rp1s,cur1s,cnt2,rp2d,cur2d,cnt2b,rp2s,cur2s);
    cudaEventRecord(eScan, s1);
    k_scatter_dir<<<gE,TB,0,s1>>>(i1,v1,cur1d,col1d,val1d,row1d);
    cudaStreamWaitEvent(s1, eA, 0);
    k_spmm64dot<<<gW,TB,0,s1>>>(rp1d,col1d,val1d,X64a,Wm1,dra,dca);
    k_gensoftmax<<<gW,TB,0,s1>>>(rp1d,col1d,val1d,dra,dca,bm1,0.5f);
    k_scatter_sym_e<<<gE,TB,0,s1>>>(row1d,col1d,val1d,cur1s,col1s,val1s);
    cudaEventRecord(eSym1, s1);
    cudaStreamWaitEvent(s1, eB, 0);
    k_spmm128<<<gW,TB,0,s1>>>(rp1s,col1s,val1s,XC1,Ha);
    k_gemm16<<<g16,b16,0,s1>>>(Ha,W2v1,S16a,Nn);
    k_spmm16<<<g16,b16,0,s1>>>(rp1s,col1s,val1s,S16a,C16a);
    k_softmax_w<<<gN,TB,0,s1>>>(C16a,out+(long)16*Nn,w1);
    cudaEventRecord(eW1, s1);
    cudaStreamWaitEvent(s1, eC, 0);
    k_spmm128g<<<gWB,TB,0,s1>>>(bidx,rp1s,col1s,val1s,XG1,E1);
    cudaEventRecord(eZ1, s1);

    // ---- s2 (part 1): view2 pipeline ----
    cudaStreamWaitEvent(s2, eScan, 0);
    k_scatter_dir<<<gE,TB,0,s2>>>(i2,v2,cur2d,col2d,val2d,row2d);
    cudaStreamWaitEvent(s2, eA, 0);
    k_spmm64dot<<<gW,TB,0,s2>>>(rp2d,col2d,val2d,X64b,Wm2,drb,dcb);
    k_gensoftmax<<<gW,TB,0,s2>>>(rp2d,col2d,val2d,drb,dcb,bm2,0.5f);
    k_scatter_sym_e<<<gE,TB,0,s2>>>(row2d,col2d,val2d,cur2s,col2s,val2s);
    cudaEventRecord(eSym2, s2);
    cudaStreamWaitEvent(s2, eB, 0);
    k_spmm128<<<gW,TB,0,s2>>>(rp2s,col2s,val2s,XC2,Hb);
    k_gemm16<<<g16,b16,0,s2>>>(Hb,W2v2,S16b,Nn);
    k_spmm16<<<g16,b16,0,s2>>>(rp2s,col2s,val2s,S16b,C16b);
    k_softmax_w<<<gN,TB,0,s2>>>(C16b,out+(long)32*Nn,w2);
    cudaEventRecord(eW2, s2);

    // ---- s3 (part 1): hoisted fused-SpMM halves (dual launch; eHf before s2 waits) ----
    cudaStreamWaitEvent(s3, eSym1, 0);
    cudaStreamWaitEvent(s3, eSym2, 0);
    cudaStreamWaitEvent(s3, eD, 0);
    k_spmm128d<<<gW2,TB,0,s3>>>(rp1s,col1s,val1s,rp2s,col2s,val2s,XCf,Hf1,Hf2);
    cudaEventRecord(eHf, s3);

    // ---- s2 (part 2): fused classifier chain ----
    cudaStreamWaitEvent(s2, eW1, 0);
    cudaStreamWaitEvent(s2, eD, 0);
    k_spmm128fg<<<gWB,TB,0,s2>>>(bidx,rp1s,col1s,val1s,rp2s,col2s,val2s,w1,w2,XG,Z);
    cudaEventRecord(eFg, s2);
    cudaStreamWaitEvent(s2, eHf, 0);
    k_combine<<<gC,TB,0,s2>>>(Hf1,Hf2,w1,w2,Ha);
    k_gemm16<<<g16,b16,0,s2>>>(Ha,W2v,S16a,Nn);
    k_spmm16f<<<g16,b16,0,s2>>>(rp1s,col1s,val1s,rp2s,col2s,val2s,w1,w2,S16a,C16a);
    k_softmax_w<<<gN,TB,0,s2>>>(C16a,out,nullptr);
    cudaEventRecord(eF2, s2);

    // ---- s3 (part 2): XG2 gather, E1/E2 projection + contrast(E1,E2) ----
    cudaStreamWaitEvent(s3, eC, 0);
    k_spmm128g<<<gWB,TB,0,s3>>>(bidx,rp2s,col2s,val2s,XG2,E2);
    cudaStreamWaitEvent(s3, eZ1, 0);
    k_gemm128<<<dim3(1,(2*Bb)/128),256,0,s3>>>(E1,Wp1,bp1,T+(long)Bb*128,2*Bb,1);
    k_gemm128<<<dim3(1,(2*Bb)/128),256,0,s3>>>(T+(long)Bb*128,Wp2,bp2,E1,2*Bb,0);
    k_normrows<<<(2*Bb*32+TB-1)/TB,TB,0,s3>>>(E1,2*Bb);
    cudaEventRecord(eE12, s3);
    k_contrast<<<cg,256,0,s3>>>(E1,E2,RS+2*Bb,CS+2*Bb,DG+2*Bb);   // pair v1v2

    // ---- s1: EV projection + contrast(EV,E1) ----
    cudaStreamWaitEvent(s1, eFg, 0);
    k_gemm128<<<dim3(1,Bb/128),256,0,s1>>>(Z,Wp1,bp1,T,Bb,1);
    k_gemm128<<<dim3(1,Bb/128),256,0,s1>>>(T,Wp2,bp2,E0,Bb,0);
    k_normrows<<<(Bb*32+TB-1)/TB,TB,0,s1>>>(E0,Bb);
    cudaEventRecord(eEV, s1);
    cudaStreamWaitEvent(s1, eE12, 0);
    k_contrast<<<cg,256,0,s1>>>(E0,E1,RS,CS,DG);                   // pair vv1
    cudaEventRecord(eCa, s1);

    // ---- s3 (part 3): contrast(EV,E2) ----
    cudaStreamWaitEvent(s3, eEV, 0);
    k_contrast<<<cg,256,0,s3>>>(E0,E2,RS+Bb,CS+Bb,DG+Bb);          // pair vv2
    cudaEventRecord(eCb, s3);

    // ---- stream 0: join + final reduce ----
    cudaStreamWaitEvent(0, eCa, 0);
    cudaStreamWaitEvent(0, eCb, 0);
    cudaStreamWaitEvent(0, eF2, 0);
    k_creduce3<<<3,1024>>>(RS,CS,DG,out+(long)48*Nn);
}